// round 1
// baseline (speedup 1.0000x reference)
#include <cuda_runtime.h>
#include <math.h>

#define N_ATOMS   100000
#define ATOM_FDIM 133
#define HIDDEN    512
#define MAX_NEI   6
#define N_MOLS    4096
#define N_PAIRS   8192
#define FFN1      2048
#define FFN2      1024

// ---------------- scratch (device globals: allocation-free) ----------------
__device__ float g_bufA[N_ATOMS * HIDDEN];   // inp, later atom_hiddens
__device__ float g_bufB[N_ATOMS * HIDDEN];   // gather results, later h1
__device__ float g_bufC[N_ATOMS * HIDDEN];   // msg2, later feature
__device__ float g_h2[N_PAIRS * FFN2];
__device__ float g_sums[N_MOLS * HIDDEN];
__device__ float g_cnt[N_MOLS];

// ---------------- generic fp32 tiled GEMM: C = A[MxK] @ B[KxN] -------------
// flags: bit0 = relu, bit1 = add Cin. bias may be null.
// Requires N % BN == 0 (true for 512/1024/2048). M,K arbitrary.
template <int BM, int BN, int BK, int TM, int TN>
__global__ __launch_bounds__((BM / TM) * (BN / TN))
void sgemm_kernel(int M, int N, int K,
                  const float* __restrict__ A, const float* __restrict__ B,
                  const float* __restrict__ Cin, const float* __restrict__ bias,
                  float* __restrict__ C, int flags)
{
    constexpr int NT = (BM / TM) * (BN / TN);  // 256
    __shared__ float As[BK][BM];
    __shared__ float Bs[BK][BN];

    const int tid  = threadIdx.x;
    const int tcol = tid % (BN / TN);
    const int trow = tid / (BN / TN);
    const int rowBase = blockIdx.y * BM;
    const int colBase = blockIdx.x * BN;

    float acc[TM][TN];
#pragma unroll
    for (int m = 0; m < TM; m++)
#pragma unroll
        for (int n = 0; n < TN; n++) acc[m][n] = 0.f;

    for (int k0 = 0; k0 < K; k0 += BK) {
        // load A tile (BM x BK), transposed into As[k][m]
#pragma unroll
        for (int i = tid; i < BM * BK; i += NT) {
            int r = i / BK, c = i % BK;
            int gr = rowBase + r, gc = k0 + c;
            As[c][r] = (gr < M && gc < K) ? A[(size_t)gr * K + gc] : 0.f;
        }
        // load B tile (BK x BN)
#pragma unroll
        for (int i = tid; i < BK * BN; i += NT) {
            int r = i / BN, c = i % BN;
            int gr = k0 + r;
            Bs[r][c] = (gr < K) ? B[(size_t)gr * N + colBase + c] : 0.f;
        }
        __syncthreads();

#pragma unroll
        for (int k = 0; k < BK; k++) {
            float ra[TM], rb[TN];
#pragma unroll
            for (int m = 0; m < TM; m++) ra[m] = As[k][trow * TM + m];
#pragma unroll
            for (int n = 0; n < TN; n++) rb[n] = Bs[k][tcol * TN + n];
#pragma unroll
            for (int m = 0; m < TM; m++)
#pragma unroll
                for (int n = 0; n < TN; n++)
                    acc[m][n] += ra[m] * rb[n];
        }
        __syncthreads();
    }

    const bool do_relu = flags & 1;
    const bool do_add  = flags & 2;
#pragma unroll
    for (int m = 0; m < TM; m++) {
        int gr = rowBase + trow * TM + m;
        if (gr >= M) continue;
#pragma unroll
        for (int n = 0; n < TN; n++) {
            int gc = colBase + tcol * TN + n;
            float v = acc[m][n];
            if (bias)    v += bias[gc];
            if (do_add)  v += Cin[(size_t)gr * N + gc];
            if (do_relu) v = fmaxf(v, 0.f);
            C[(size_t)gr * N + gc] = v;
        }
    }
}

// ---------------- neighbor gather-sum: dst[i] = sum_j f(src[nei[i][j]]) ----
__global__ void gather_sum_kernel(const float* __restrict__ src,
                                  const int* __restrict__ nei,
                                  float* __restrict__ dst, int relu_src)
{
    int atom = blockIdx.x;
    int c = threadIdx.x;  // 0..127 -> float4 chunk of 512 columns
    const int* nrow = nei + atom * MAX_NEI;
    float4 acc = make_float4(0.f, 0.f, 0.f, 0.f);
#pragma unroll
    for (int j = 0; j < MAX_NEI; j++) {
        int n = __ldg(&nrow[j]);
        float4 v = __ldg((const float4*)(src + (size_t)n * HIDDEN) + c);
        if (relu_src) {
            v.x = fmaxf(v.x, 0.f); v.y = fmaxf(v.y, 0.f);
            v.z = fmaxf(v.z, 0.f); v.w = fmaxf(v.w, 0.f);
        }
        acc.x += v.x; acc.y += v.y; acc.z += v.z; acc.w += v.w;
    }
    ((float4*)(dst + (size_t)atom * HIDDEN))[c] = acc;
}

// ---------------- segment mean pieces --------------------------------------
__global__ void zero_seg_kernel()
{
    int i = blockIdx.x * blockDim.x + threadIdx.x;
    if (i < N_MOLS * HIDDEN) g_sums[i] = 0.f;
    if (i < N_MOLS) g_cnt[i] = 0.f;
}

__global__ void seg_accum_kernel(const float* __restrict__ ah,
                                 const int* __restrict__ mol_ids)
{
    int atom = blockIdx.x;
    int mol  = __ldg(&mol_ids[atom]);
    int c    = threadIdx.x;  // 0..127
    float4 v = __ldg((const float4*)(ah + (size_t)atom * HIDDEN) + c);
    float* s = g_sums + (size_t)mol * HIDDEN + c * 4;
    atomicAdd(s + 0, v.x);
    atomicAdd(s + 1, v.y);
    atomicAdd(s + 2, v.z);
    atomicAdd(s + 3, v.w);
    if (c == 0) atomicAdd(&g_cnt[mol], 1.f);
}

// ---------------- pairwise feature build (fuses segment divide) ------------
__global__ void feature_kernel(const int* __restrict__ edges,
                               float* __restrict__ feat)
{
    int p = blockIdx.x;
    int a = __ldg(&edges[p]);
    int b = __ldg(&edges[N_PAIRS + p]);
    float ia = 1.f / fmaxf(__ldg(&g_cnt[a]), 1.f);
    float ib = 1.f / fmaxf(__ldg(&g_cnt[b]), 1.f);
    int c = threadIdx.x;  // 0..127
    float4 va = __ldg((const float4*)(g_sums + (size_t)a * HIDDEN) + c);
    float4 vb = __ldg((const float4*)(g_sums + (size_t)b * HIDDEN) + c);
    va.x *= ia; va.y *= ia; va.z *= ia; va.w *= ia;
    vb.x *= ib; vb.y *= ib; vb.z *= ib; vb.w *= ib;
    float* frow = feat + (size_t)p * (4 * HIDDEN);
    float4 s = make_float4(va.x + vb.x, va.y + vb.y, va.z + vb.z, va.w + vb.w);
    float4 m = make_float4(va.x * vb.x, va.y * vb.y, va.z * vb.z, va.w * vb.w);
    ((float4*)(frow + 0 * HIDDEN))[c] = s;
    ((float4*)(frow + 1 * HIDDEN))[c] = m;
    ((float4*)(frow + 2 * HIDDEN))[c] = va;
    ((float4*)(frow + 3 * HIDDEN))[c] = vb;
}

// ---------------- final dot + sigmoid --------------------------------------
__global__ void ffn_last_kernel(const float* __restrict__ h2,
                                const float* __restrict__ W,
                                const float* __restrict__ b,
                                float* __restrict__ out)
{
    int p = blockIdx.x;
    float s = 0.f;
    for (int i = threadIdx.x; i < FFN2; i += 128)
        s += h2[(size_t)p * FFN2 + i] * W[i];
#pragma unroll
    for (int off = 16; off; off >>= 1)
        s += __shfl_down_sync(0xffffffffu, s, off);
    __shared__ float red[4];
    if ((threadIdx.x & 31) == 0) red[threadIdx.x >> 5] = s;
    __syncthreads();
    if (threadIdx.x == 0) {
        float t = red[0] + red[1] + red[2] + red[3] + b[0];
        out[p] = 1.f / (1.f + expf(-t));
    }
}

// ---------------- launch ----------------------------------------------------
extern "C" void kernel_launch(void* const* d_in, const int* in_sizes, int n_in,
                              void* d_out, int out_size)
{
    const float* f_atoms = (const float*)d_in[0];
    const int*   a_nei   = (const int*)d_in[1];
    const int*   mol_ids = (const int*)d_in[2];
    const int*   edges   = (const int*)d_in[3];
    const float* W_i     = (const float*)d_in[4];
    const float* W_h     = (const float*)d_in[5];
    const float* W_o     = (const float*)d_in[6];
    const float* b_o     = (const float*)d_in[7];
    const float* W_fi    = (const float*)d_in[8];
    const float* b_fi    = (const float*)d_in[9];
    const float* W_f1    = (const float*)d_in[10];
    const float* b_f1    = (const float*)d_in[11];
    const float* W_f2    = (const float*)d_in[12];
    const float* b_f2    = (const float*)d_in[13];
    float* out = (float*)d_out;

    float *bufA, *bufB, *bufC, *h2p;
    cudaGetSymbolAddress((void**)&bufA, g_bufA);
    cudaGetSymbolAddress((void**)&bufB, g_bufB);
    cudaGetSymbolAddress((void**)&bufC, g_bufC);
    cudaGetSymbolAddress((void**)&h2p,  g_h2);

    auto grid = [](int M, int N) { return dim3(N / 128, (M + 127) / 128); };

    // 1. inp = f_atoms @ W_i                               -> bufA
    sgemm_kernel<128,128,8,8,8><<<grid(N_ATOMS, HIDDEN), 256>>>(
        N_ATOMS, HIDDEN, ATOM_FDIM, f_atoms, W_i, nullptr, nullptr, bufA, 0);

    // 2. bufB = sum_j relu(inp[nei])
    gather_sum_kernel<<<N_ATOMS, 128>>>(bufA, a_nei, bufB, 1);

    // 3. msg2 = relu(inp + bufB @ W_h)                     -> bufC
    sgemm_kernel<128,128,8,8,8><<<grid(N_ATOMS, HIDDEN), 256>>>(
        N_ATOMS, HIDDEN, HIDDEN, bufB, W_h, bufA, nullptr, bufC, 3);

    // 4. bufB = sum_j msg2[nei]
    gather_sum_kernel<<<N_ATOMS, 128>>>(bufC, a_nei, bufB, 0);

    // 5. ah_partial = f_atoms @ W_o[0:133]                 -> bufA
    sgemm_kernel<128,128,8,8,8><<<grid(N_ATOMS, HIDDEN), 256>>>(
        N_ATOMS, HIDDEN, ATOM_FDIM, f_atoms, W_o, nullptr, nullptr, bufA, 0);

    // 6. atom_hiddens = relu(ah_partial + bufB @ W_o[133:645] + b_o)  -> bufA
    sgemm_kernel<128,128,8,8,8><<<grid(N_ATOMS, HIDDEN), 256>>>(
        N_ATOMS, HIDDEN, HIDDEN, bufB, W_o + ATOM_FDIM * HIDDEN, bufA, b_o, bufA, 3);

    // 7-8. segment sums + counts
    zero_seg_kernel<<<(N_MOLS * HIDDEN + 255) / 256, 256>>>();
    seg_accum_kernel<<<N_ATOMS, 128>>>(bufA, mol_ids);

    // 9. pairwise features [P, 4H]                          -> bufC
    feature_kernel<<<N_PAIRS, 128>>>(edges, bufC);

    // 10. h1 = relu(feat @ W_ffn_i + b_ffn_i)               -> bufB
    sgemm_kernel<128,128,8,8,8><<<grid(N_PAIRS, FFN1), 256>>>(
        N_PAIRS, FFN1, 4 * HIDDEN, bufC, W_fi, nullptr, b_fi, bufB, 1);

    // 11. h2 = relu(h1 @ W_ffn_1 + b_ffn_1)                 -> g_h2
    sgemm_kernel<128,128,8,8,8><<<grid(N_PAIRS, FFN2), 256>>>(
        N_PAIRS, FFN2, FFN1, bufB, W_f1, nullptr, b_f1, h2p, 1);

    // 12. out = sigmoid(h2 . W_ffn_2 + b_ffn_2)
    ffn_last_kernel<<<N_PAIRS, 128>>>(h2p, W_f2, b_f2, out);
}

// round 3
// speedup vs baseline: 3.4768x; 3.4768x over previous
#include <cuda_runtime.h>
#include <math.h>
#include <stdint.h>

#define N_ATOMS   100000
#define ATOM_FDIM 133
#define KPAD_F    160
#define HIDDEN    512
#define MAX_NEI   6
#define N_MOLS    4096
#define N_PAIRS   8192
#define FFN1      2048
#define FFN2      1024

// ---------------- scratch (device globals: allocation-free) ----------------
__device__ float g_bufA[N_ATOMS * HIDDEN];
__device__ float g_bufB[N_ATOMS * HIDDEN];
__device__ float g_bufC[N_ATOMS * HIDDEN];
__device__ float g_h2[N_PAIRS * FFN2];
__device__ float g_sums[N_MOLS * HIDDEN];
__device__ float g_cnt[N_MOLS];
__device__ float g_padA[N_ATOMS * KPAD_F];

// ---------------- PTX helpers ----------------------------------------------
__device__ __forceinline__ uint32_t smem_u32(const void* p) {
    return (uint32_t)__cvta_generic_to_shared(p);
}
__device__ __forceinline__ void cp16(uint32_t s, const void* g, uint32_t bytes) {
    asm volatile("cp.async.cg.shared.global [%0], [%1], 16, %2;\n"
                 :: "r"(s), "l"(g), "r"(bytes));
}
__device__ __forceinline__ void cp_commit() {
    asm volatile("cp.async.commit_group;\n" ::: "memory");
}
template <int N>
__device__ __forceinline__ void cp_wait() {
    asm volatile("cp.async.wait_group %0;\n" :: "n"(N) : "memory");
}
__device__ __forceinline__ uint32_t f2tf32(float f) {
    uint32_t u;
    asm("cvt.rna.tf32.f32 %0, %1;" : "=r"(u) : "f"(f));
    return u;
}
__device__ __forceinline__ void mma_tf32(float* c, const uint32_t* a, const uint32_t* b) {
    asm volatile(
        "mma.sync.aligned.m16n8k8.row.col.f32.tf32.tf32.f32 "
        "{%0,%1,%2,%3}, {%4,%5,%6,%7}, {%8,%9}, {%0,%1,%2,%3};\n"
        : "+f"(c[0]), "+f"(c[1]), "+f"(c[2]), "+f"(c[3])
        : "r"(a[0]), "r"(a[1]), "r"(a[2]), "r"(a[3]), "r"(b[0]), "r"(b[1]));
}

// ---------------- GEMM tile config ------------------------------------------
#define BM 128
#define BN 128
#define BK 32
#define A_STRIDE 36      // floats per A smem row (pad 4 -> conflict-free frags)
#define B_STRIDE 136     // floats per B smem row (pad 8 -> conflict-free frags)
#define A_ELEMS (BM * A_STRIDE)   // 4608
#define B_ELEMS (BK * B_STRIDE)   // 4352
#define SMEM_BYTES (2 * (A_ELEMS + B_ELEMS) * 4)  // 71680

// ---------------- tf32 mma.sync GEMM: C = A[MxK] @ B[KxN] -------------------
// A row-major with leading dim lda (lda >= ceil(K/32)*32, padded cols = 0).
// B row-major [K][N]. flags via template: RELU, ADDC (C += Cin), BIAS.
template <bool RELU, bool ADDC, bool BIAS>
__global__ __launch_bounds__(256, 2)
void mma_gemm(int M, int N, int K, int lda,
              const float* __restrict__ A, const float* __restrict__ B,
              const float* __restrict__ Cin, const float* __restrict__ bias,
              float* __restrict__ C)
{
    extern __shared__ float sm[];
    const uint32_t sbase = smem_u32(sm);
    const int tid = threadIdx.x;
    const int lane = tid & 31, wid = tid >> 5;
    const int wm = wid & 3, wn = wid >> 2;     // warp grid 4 x 2
    const int gid = lane >> 2, tig = lane & 3; // groupID, threadID_in_group
    const int rowBase = blockIdx.y * BM;
    const int colBase = blockIdx.x * BN;
    const int nk = (K + BK - 1) / BK;

    float acc[2][8][4];
#pragma unroll
    for (int mt = 0; mt < 2; mt++)
#pragma unroll
        for (int nt = 0; nt < 8; nt++)
#pragma unroll
            for (int i = 0; i < 4; i++) acc[mt][nt][i] = 0.f;

    // ---- tile loaders (cp.async, zfill on OOB) ----
    auto loadA = [&](int b, int kc0) {
#pragma unroll
        for (int j = 0; j < 4; j++) {
            int idx = tid + j * 256;
            int row = idx >> 3, c = idx & 7;
            uint32_t sa = sbase + (uint32_t)(b * A_ELEMS + row * A_STRIDE) * 4 + c * 16;
            int grow = rowBase + row;
            int crow = grow < M ? grow : 0;
            cp16(sa, A + (size_t)crow * lda + kc0 + c * 4, grow < M ? 16u : 0u);
        }
    };
    auto loadB = [&](int b, int kc0) {
#pragma unroll
        for (int j = 0; j < 4; j++) {
            int idx = tid + j * 256;
            int row = idx >> 5, c = idx & 31;
            uint32_t sa = sbase + (uint32_t)(2 * A_ELEMS + b * B_ELEMS + row * B_STRIDE) * 4 + c * 16;
            int gk = kc0 + row;
            int ck = gk < K ? gk : 0;
            cp16(sa, B + (size_t)ck * N + colBase + c * 4, gk < K ? 16u : 0u);
        }
    };

    loadA(0, 0); loadB(0, 0); cp_commit();

    for (int kt = 0; kt < nk; kt++) {
        const int b = kt & 1;
        if (kt + 1 < nk) {
            loadA(b ^ 1, (kt + 1) * BK);
            loadB(b ^ 1, (kt + 1) * BK);
            cp_commit();
            cp_wait<1>();
        } else {
            cp_wait<0>();
        }
        __syncthreads();

        const float* Asb = sm + b * A_ELEMS;
        const float* Bsb = sm + 2 * A_ELEMS + b * B_ELEMS;
#pragma unroll
        for (int ks = 0; ks < 4; ks++) {
            const int k0 = ks * 8;
            uint32_t af[2][4];
#pragma unroll
            for (int mt = 0; mt < 2; mt++) {
                const float* ap = Asb + (wm * 32 + mt * 16 + gid) * A_STRIDE + k0 + tig;
                af[mt][0] = f2tf32(ap[0]);
                af[mt][1] = f2tf32(ap[8 * A_STRIDE]);
                af[mt][2] = f2tf32(ap[4]);
                af[mt][3] = f2tf32(ap[8 * A_STRIDE + 4]);
            }
            uint32_t bf[8][2];
#pragma unroll
            for (int nt = 0; nt < 8; nt++) {
                const float* bp = Bsb + (k0 + tig) * B_STRIDE + wn * 64 + nt * 8 + gid;
                bf[nt][0] = f2tf32(bp[0]);
                bf[nt][1] = f2tf32(bp[4 * B_STRIDE]);
            }
#pragma unroll
            for (int mt = 0; mt < 2; mt++)
#pragma unroll
                for (int nt = 0; nt < 8; nt++)
                    mma_tf32(acc[mt][nt], af[mt], bf[nt]);
        }
        __syncthreads();
    }

    // ---- epilogue ----
#pragma unroll
    for (int mt = 0; mt < 2; mt++) {
        const int row0 = rowBase + wm * 32 + mt * 16 + gid;
        const int row1 = row0 + 8;
#pragma unroll
        for (int nt = 0; nt < 8; nt++) {
            const int gc = colBase + wn * 64 + nt * 8 + tig * 2;
            float2 v0 = make_float2(acc[mt][nt][0], acc[mt][nt][1]);
            float2 v1 = make_float2(acc[mt][nt][2], acc[mt][nt][3]);
            if (BIAS) {
                const float2 bb = *(const float2*)(bias + gc);
                v0.x += bb.x; v0.y += bb.y;
                v1.x += bb.x; v1.y += bb.y;
            }
            if (row0 < M) {
                if (ADDC) {
                    const float2 ci = *(const float2*)(Cin + (size_t)row0 * N + gc);
                    v0.x += ci.x; v0.y += ci.y;
                }
                if (RELU) { v0.x = fmaxf(v0.x, 0.f); v0.y = fmaxf(v0.y, 0.f); }
                *(float2*)(C + (size_t)row0 * N + gc) = v0;
            }
            if (row1 < M) {
                if (ADDC) {
                    const float2 ci = *(const float2*)(Cin + (size_t)row1 * N + gc);
                    v1.x += ci.x; v1.y += ci.y;
                }
                if (RELU) { v1.x = fmaxf(v1.x, 0.f); v1.y = fmaxf(v1.y, 0.f); }
                *(float2*)(C + (size_t)row1 * N + gc) = v1;
            }
        }
    }
}

// ---------------- prologue prep ---------------------------------------------
__global__ void pad_atoms_kernel(const float* __restrict__ f, float* __restrict__ out) {
    int idx = blockIdx.x * blockDim.x + threadIdx.x;
    if (idx >= N_ATOMS * KPAD_F) return;
    int a = idx / KPAD_F, k = idx - a * KPAD_F;
    out[idx] = (k < ATOM_FDIM) ? f[a * ATOM_FDIM + k] : 0.f;
}

// ---------------- neighbor gather-sum ---------------------------------------
__global__ void gather_sum_kernel(const float* __restrict__ src,
                                  const int* __restrict__ nei,
                                  float* __restrict__ dst, int relu_src)
{
    int atom = blockIdx.x;
    int c = threadIdx.x;
    const int* nrow = nei + atom * MAX_NEI;
    float4 acc = make_float4(0.f, 0.f, 0.f, 0.f);
#pragma unroll
    for (int j = 0; j < MAX_NEI; j++) {
        int n = __ldg(&nrow[j]);
        float4 v = __ldg((const float4*)(src + (size_t)n * HIDDEN) + c);
        if (relu_src) {
            v.x = fmaxf(v.x, 0.f); v.y = fmaxf(v.y, 0.f);
            v.z = fmaxf(v.z, 0.f); v.w = fmaxf(v.w, 0.f);
        }
        acc.x += v.x; acc.y += v.y; acc.z += v.z; acc.w += v.w;
    }
    ((float4*)(dst + (size_t)atom * HIDDEN))[c] = acc;
}

// ---------------- segment mean pieces ---------------------------------------
__global__ void zero_seg_kernel() {
    int i = blockIdx.x * blockDim.x + threadIdx.x;
    if (i < N_MOLS * HIDDEN) g_sums[i] = 0.f;
    if (i < N_MOLS) g_cnt[i] = 0.f;
}

__global__ void seg_accum_kernel(const float* __restrict__ ah,
                                 const int* __restrict__ mol_ids)
{
    int atom = blockIdx.x;
    int mol  = __ldg(&mol_ids[atom]);
    int c    = threadIdx.x;
    float4 v = __ldg((const float4*)(ah + (size_t)atom * HIDDEN) + c);
    float* s = g_sums + (size_t)mol * HIDDEN + c * 4;
    atomicAdd(s + 0, v.x);
    atomicAdd(s + 1, v.y);
    atomicAdd(s + 2, v.z);
    atomicAdd(s + 3, v.w);
    if (c == 0) atomicAdd(&g_cnt[mol], 1.f);
}

// ---------------- pairwise feature build ------------------------------------
__global__ void feature_kernel(const int* __restrict__ edges,
                               float* __restrict__ feat)
{
    int p = blockIdx.x;
    int a = __ldg(&edges[p]);
    int b = __ldg(&edges[N_PAIRS + p]);
    float ia = 1.f / fmaxf(__ldg(&g_cnt[a]), 1.f);
    float ib = 1.f / fmaxf(__ldg(&g_cnt[b]), 1.f);
    int c = threadIdx.x;
    float4 va = __ldg((const float4*)(g_sums + (size_t)a * HIDDEN) + c);
    float4 vb = __ldg((const float4*)(g_sums + (size_t)b * HIDDEN) + c);
    va.x *= ia; va.y *= ia; va.z *= ia; va.w *= ia;
    vb.x *= ib; vb.y *= ib; vb.z *= ib; vb.w *= ib;
    float* frow = feat + (size_t)p * (4 * HIDDEN);
    float4 s = make_float4(va.x + vb.x, va.y + vb.y, va.z + vb.z, va.w + vb.w);
    float4 m = make_float4(va.x * vb.x, va.y * vb.y, va.z * vb.z, va.w * vb.w);
    ((float4*)(frow + 0 * HIDDEN))[c] = s;
    ((float4*)(frow + 1 * HIDDEN))[c] = m;
    ((float4*)(frow + 2 * HIDDEN))[c] = va;
    ((float4*)(frow + 3 * HIDDEN))[c] = vb;
}

// ---------------- final dot + sigmoid ---------------------------------------
__global__ void ffn_last_kernel(const float* __restrict__ h2,
                                const float* __restrict__ W,
                                const float* __restrict__ b,
                                float* __restrict__ out)
{
    int p = blockIdx.x;
    float s = 0.f;
    for (int i = threadIdx.x; i < FFN2; i += 128)
        s += h2[(size_t)p * FFN2 + i] * W[i];
#pragma unroll
    for (int off = 16; off; off >>= 1)
        s += __shfl_down_sync(0xffffffffu, s, off);
    __shared__ float red[4];
    if ((threadIdx.x & 31) == 0) red[threadIdx.x >> 5] = s;
    __syncthreads();
    if (threadIdx.x == 0) {
        float t = red[0] + red[1] + red[2] + red[3] + b[0];
        out[p] = 1.f / (1.f + expf(-t));
    }
}

// ---------------- launch ----------------------------------------------------
extern "C" void kernel_launch(void* const* d_in, const int* in_sizes, int n_in,
                              void* d_out, int out_size)
{
    const float* f_atoms = (const float*)d_in[0];
    const int*   a_nei   = (const int*)d_in[1];
    const int*   mol_ids = (const int*)d_in[2];
    const int*   edges   = (const int*)d_in[3];
    const float* W_i     = (const float*)d_in[4];
    const float* W_h     = (const float*)d_in[5];
    const float* W_o     = (const float*)d_in[6];
    const float* b_o     = (const float*)d_in[7];
    const float* W_fi    = (const float*)d_in[8];
    const float* b_fi    = (const float*)d_in[9];
    const float* W_f1    = (const float*)d_in[10];
    const float* b_f1    = (const float*)d_in[11];
    const float* W_f2    = (const float*)d_in[12];
    const float* b_f2    = (const float*)d_in[13];
    float* out = (float*)d_out;

    float *bufA, *bufB, *bufC, *h2p, *padA;
    cudaGetSymbolAddress((void**)&bufA, g_bufA);
    cudaGetSymbolAddress((void**)&bufB, g_bufB);
    cudaGetSymbolAddress((void**)&bufC, g_bufC);
    cudaGetSymbolAddress((void**)&h2p,  g_h2);
    cudaGetSymbolAddress((void**)&padA, g_padA);

    cudaFuncSetAttribute(mma_gemm<false, false, false>,
                         cudaFuncAttributeMaxDynamicSharedMemorySize, SMEM_BYTES);
    cudaFuncSetAttribute(mma_gemm<true, true, false>,
                         cudaFuncAttributeMaxDynamicSharedMemorySize, SMEM_BYTES);
    cudaFuncSetAttribute(mma_gemm<true, true, true>,
                         cudaFuncAttributeMaxDynamicSharedMemorySize, SMEM_BYTES);
    cudaFuncSetAttribute(mma_gemm<true, false, true>,
                         cudaFuncAttributeMaxDynamicSharedMemorySize, SMEM_BYTES);

    pad_atoms_kernel<<<(N_ATOMS * KPAD_F + 255) / 256, 256>>>(f_atoms, padA);

    const int MT = (N_ATOMS + BM - 1) / BM;  // 782

    // 1. inp = f_atoms @ W_i                        -> bufA
    mma_gemm<false, false, false><<<dim3(HIDDEN / BN, MT), 256, SMEM_BYTES>>>(
        N_ATOMS, HIDDEN, ATOM_FDIM, KPAD_F, padA, W_i, nullptr, nullptr, bufA);
    // 2. bufB = sum_j relu(inp[nei])
    gather_sum_kernel<<<N_ATOMS, 128>>>(bufA, a_nei, bufB, 1);
    // 3. msg2 = relu(inp + bufB @ W_h)              -> bufC
    mma_gemm<true, true, false><<<dim3(HIDDEN / BN, MT), 256, SMEM_BYTES>>>(
        N_ATOMS, HIDDEN, HIDDEN, HIDDEN, bufB, W_h, bufA, nullptr, bufC);
    // 4. bufB = sum_j msg2[nei]
    gather_sum_kernel<<<N_ATOMS, 128>>>(bufC, a_nei, bufB, 0);
    // 5. ah_partial = f_atoms @ W_o[0:133]          -> bufA
    mma_gemm<false, false, false><<<dim3(HIDDEN / BN, MT), 256, SMEM_BYTES>>>(
        N_ATOMS, HIDDEN, ATOM_FDIM, KPAD_F, padA, W_o, nullptr, nullptr, bufA);
    // 6. atom_hiddens = relu(ah_partial + bufB @ W_o[133:645] + b_o) -> bufA
    mma_gemm<true, true, true><<<dim3(HIDDEN / BN, MT), 256, SMEM_BYTES>>>(
        N_ATOMS, HIDDEN, HIDDEN, HIDDEN, bufB, W_o + ATOM_FDIM * HIDDEN, bufA, b_o, bufA);
    // 7-8. segment sums + counts
    zero_seg_kernel<<<(N_MOLS * HIDDEN + 255) / 256, 256>>>();
    seg_accum_kernel<<<N_ATOMS, 128>>>(bufA, mol_ids);
    // 9. pairwise features [P, 4H]                   -> bufC
    feature_kernel<<<N_PAIRS, 128>>>(edges, bufC);
    // 10. h1 = relu(feat @ W_ffn_i + b_ffn_i)        -> bufB
    mma_gemm<true, false, true><<<dim3(FFN1 / BN, N_PAIRS / BM), 256, SMEM_BYTES>>>(
        N_PAIRS, FFN1, 4 * HIDDEN, 4 * HIDDEN, bufC, W_fi, nullptr, b_fi, bufB);
    // 11. h2 = relu(h1 @ W_ffn_1 + b_ffn_1)          -> g_h2
    mma_gemm<true, false, true><<<dim3(FFN2 / BN, N_PAIRS / BM), 256, SMEM_BYTES>>>(
        N_PAIRS, FFN2, FFN1, FFN1, bufB, W_f1, nullptr, b_f1, h2p);
    // 12. out = sigmoid(h2 . W_ffn_2 + b_ffn_2)
    ffn_last_kernel<<<N_PAIRS, 128>>>(h2p, W_f2, b_f2, out);
}

// round 5
// speedup vs baseline: 3.6245x; 1.0425x over previous
#include <cuda_runtime.h>
#include <math.h>
#include <stdint.h>

#define N_ATOMS   100000
#define ATOM_FDIM 133
#define KPAD_F    160
#define HIDDEN    512
#define MAX_NEI   6
#define N_MOLS    4096
#define N_PAIRS   8192
#define FFN1      2048
#define FFN2      1024

// ---------------- scratch (device globals: allocation-free) ----------------
__device__ float g_cat [N_ATOMS * 1024];   // cols 0-511: inp, 512-1023: ah_partial
__device__ float g_bufA[N_ATOMS * HIDDEN];
__device__ float g_bufB[N_ATOMS * HIDDEN];
__device__ float g_bufC[N_ATOMS * HIDDEN];
__device__ float g_h2[N_PAIRS * FFN2];
__device__ float g_sums[N_MOLS * HIDDEN];
__device__ float g_cnt[N_MOLS];
__device__ float g_padA[N_ATOMS * KPAD_F];
__device__ float g_Wcat[KPAD_F * 1024];    // [W_i | W_o_top], zero-padded rows

// ---------------- PTX helpers ----------------------------------------------
__device__ __forceinline__ uint32_t smem_u32(const void* p) {
    return (uint32_t)__cvta_generic_to_shared(p);
}
__device__ __forceinline__ void cp16(uint32_t s, const void* g, uint32_t bytes) {
    asm volatile("cp.async.cg.shared.global [%0], [%1], 16, %2;\n"
                 :: "r"(s), "l"(g), "r"(bytes));
}
__device__ __forceinline__ void cp_commit() {
    asm volatile("cp.async.commit_group;\n" ::: "memory");
}
template <int N>
__device__ __forceinline__ void cp_wait() {
    asm volatile("cp.async.wait_group %0;\n" :: "n"(N) : "memory");
}
// fp32 bits fed directly as tf32 operands (HW truncates low mantissa bits).
__device__ __forceinline__ void mma_tf32(float* c, const uint32_t* a, const uint32_t* b) {
    asm volatile(
        "mma.sync.aligned.m16n8k8.row.col.f32.tf32.tf32.f32 "
        "{%0,%1,%2,%3}, {%4,%5,%6,%7}, {%8,%9}, {%0,%1,%2,%3};\n"
        : "+f"(c[0]), "+f"(c[1]), "+f"(c[2]), "+f"(c[3])
        : "r"(a[0]), "r"(a[1]), "r"(a[2]), "r"(a[3]), "r"(b[0]), "r"(b[1]));
}

// ---------------- GEMM tile config ------------------------------------------
#define BM 128
#define BN 128
#define BK 32
#define STAGES 3
#define A_STRIDE 36
#define B_STRIDE 136
#define A_ELEMS (BM * A_STRIDE)             // 4608
#define B_ELEMS (BK * B_STRIDE)             // 4352
#define STAGE_ELEMS (A_ELEMS + B_ELEMS)     // 8960
#define SMEM_BYTES (STAGES * STAGE_ELEMS * 4)  // 107520

// ---------------- tf32 mma.sync GEMM: C = A[MxK] @ B[KxN] -------------------
// A row-major ld=lda; B row-major [K][N]; Cin ld=ldcin; C ld=ldc.
template <bool RELU, bool ADDC, bool BIAS>
__global__ __launch_bounds__(256, 2)
void mma_gemm(int M, int N, int K, int lda, int ldcin, int ldc,
              const float* __restrict__ A, const float* __restrict__ B,
              const float* __restrict__ Cin, const float* __restrict__ bias,
              float* __restrict__ C)
{
    extern __shared__ float sm[];
    const uint32_t sbase = smem_u32(sm);
    const int tid = threadIdx.x;
    const int lane = tid & 31, wid = tid >> 5;
    const int wm = wid & 3, wn = wid >> 2;
    const int gid = lane >> 2, tig = lane & 3;
    const int rowBase = blockIdx.y * BM;
    const int colBase = blockIdx.x * BN;
    const int nk = K / BK;

    // ---- hoisted per-thread load addressing ----
    const float* aPtr[4];  uint32_t aSm[4];  uint32_t aBytes[4];
    const float* bPtr[4];  uint32_t bSm[4];
#pragma unroll
    for (int j = 0; j < 4; j++) {
        int idx = tid + j * 256;
        int row = idx >> 3, c = idx & 7;
        int grow = rowBase + row;
        int crow = grow < M ? grow : 0;
        aPtr[j]   = A + (size_t)crow * lda + c * 4;
        aSm[j]    = sbase + (uint32_t)(row * A_STRIDE) * 4 + c * 16;
        aBytes[j] = grow < M ? 16u : 0u;
        int brow = idx >> 5, bc = idx & 31;
        bPtr[j] = B + (size_t)brow * N + colBase + bc * 4;
        bSm[j]  = sbase + (uint32_t)(A_ELEMS + brow * B_STRIDE) * 4 + bc * 16;
    }

    auto load_stage = [&](int buf, int kc0) {
        const uint32_t so = (uint32_t)(buf * STAGE_ELEMS) * 4;
#pragma unroll
        for (int j = 0; j < 4; j++)
            cp16(aSm[j] + so, aPtr[j] + kc0, aBytes[j]);
#pragma unroll
        for (int j = 0; j < 4; j++)
            cp16(bSm[j] + so, bPtr[j] + (size_t)kc0 * N, 16u);
        cp_commit();
    };

    float acc[2][8][4];
#pragma unroll
    for (int mt = 0; mt < 2; mt++)
#pragma unroll
        for (int nt = 0; nt < 8; nt++)
#pragma unroll
            for (int i = 0; i < 4; i++) acc[mt][nt][i] = 0.f;

    // prologue: fill STAGES-1 stages
    load_stage(0, 0);
    if (nk > 1) load_stage(1, BK);

    int buf = 0;
    for (int kt = 0; kt < nk; kt++) {
        cp_wait<STAGES - 2>();
        __syncthreads();
        if (kt + 2 < nk)
            load_stage((buf + 2) % STAGES, (kt + 2) * BK);

        const float* Asb = sm + buf * STAGE_ELEMS;
        const float* Bsb = Asb + A_ELEMS;
#pragma unroll
        for (int ks = 0; ks < 4; ks++) {
            const int k0 = ks * 8;
            uint32_t af[2][4];
#pragma unroll
            for (int mt = 0; mt < 2; mt++) {
                const float* ap = Asb + (wm * 32 + mt * 16 + gid) * A_STRIDE + k0 + tig;
                af[mt][0] = __float_as_uint(ap[0]);
                af[mt][1] = __float_as_uint(ap[8 * A_STRIDE]);
                af[mt][2] = __float_as_uint(ap[4]);
                af[mt][3] = __float_as_uint(ap[8 * A_STRIDE + 4]);
            }
            uint32_t bf[8][2];
#pragma unroll
            for (int nt = 0; nt < 8; nt++) {
                const float* bp = Bsb + (k0 + tig) * B_STRIDE + wn * 64 + nt * 8 + gid;
                bf[nt][0] = __float_as_uint(bp[0]);
                bf[nt][1] = __float_as_uint(bp[4 * B_STRIDE]);
            }
#pragma unroll
            for (int mt = 0; mt < 2; mt++)
#pragma unroll
                for (int nt = 0; nt < 8; nt++)
                    mma_tf32(acc[mt][nt], af[mt], bf[nt]);
        }
        __syncthreads();
        buf = (buf + 1) % STAGES;
    }

    // ---- epilogue ----
#pragma unroll
    for (int mt = 0; mt < 2; mt++) {
        const int row0 = rowBase + wm * 32 + mt * 16 + gid;
        const int row1 = row0 + 8;
#pragma unroll
        for (int nt = 0; nt < 8; nt++) {
            const int gc = colBase + wn * 64 + nt * 8 + tig * 2;
            float2 v0 = make_float2(acc[mt][nt][0], acc[mt][nt][1]);
            float2 v1 = make_float2(acc[mt][nt][2], acc[mt][nt][3]);
            if (BIAS) {
                const float2 bb = *(const float2*)(bias + gc);
                v0.x += bb.x; v0.y += bb.y;
                v1.x += bb.x; v1.y += bb.y;
            }
            if (row0 < M) {
                if (ADDC) {
                    const float2 ci = *(const float2*)(Cin + (size_t)row0 * ldcin + gc);
                    v0.x += ci.x; v0.y += ci.y;
                }
                if (RELU) { v0.x = fmaxf(v0.x, 0.f); v0.y = fmaxf(v0.y, 0.f); }
                *(float2*)(C + (size_t)row0 * ldc + gc) = v0;
            }
            if (row1 < M) {
                if (ADDC) {
                    const float2 ci = *(const float2*)(Cin + (size_t)row1 * ldcin + gc);
                    v1.x += ci.x; v1.y += ci.y;
                }
                if (RELU) { v1.x = fmaxf(v1.x, 0.f); v1.y = fmaxf(v1.y, 0.f); }
                *(float2*)(C + (size_t)row1 * ldc + gc) = v1;
            }
        }
    }
}

// ---------------- prologue prep ---------------------------------------------
__global__ void pad_atoms_kernel(const float* __restrict__ f, float* __restrict__ out) {
    int idx = blockIdx.x * blockDim.x + threadIdx.x;
    if (idx >= N_ATOMS * KPAD_F) return;
    int a = idx / KPAD_F, k = idx - a * KPAD_F;
    out[idx] = (k < ATOM_FDIM) ? f[a * ATOM_FDIM + k] : 0.f;
}

// g_Wcat[k][0:512] = W_i[k], g_Wcat[k][512:1024] = W_o_top[k]; rows >=133 zero
__global__ void build_wcat_kernel(const float* __restrict__ Wi,
                                  const float* __restrict__ Wo,
                                  float* __restrict__ out) {
    int idx = blockIdx.x * blockDim.x + threadIdx.x;
    if (idx >= KPAD_F * 1024) return;
    int k = idx >> 10, j = idx & 1023;
    float v = 0.f;
    if (k < ATOM_FDIM)
        v = (j < HIDDEN) ? Wi[k * HIDDEN + j] : Wo[k * HIDDEN + (j - HIDDEN)];
    out[idx] = v;
}

// ---------------- neighbor gather-sum ---------------------------------------
__global__ void gather_sum_kernel(const float* __restrict__ src, int srcStride,
                                  const int* __restrict__ nei,
                                  float* __restrict__ dst, int relu_src)
{
    int atom = blockIdx.x;
    int c = threadIdx.x;
    const int* nrow = nei + atom * MAX_NEI;
    float4 acc = make_float4(0.f, 0.f, 0.f, 0.f);
#pragma unroll
    for (int j = 0; j < MAX_NEI; j++) {
        int n = __ldg(&nrow[j]);
        float4 v = __ldg((const float4*)(src + (size_t)n * srcStride) + c);
        if (relu_src) {
            v.x = fmaxf(v.x, 0.f); v.y = fmaxf(v.y, 0.f);
            v.z = fmaxf(v.z, 0.f); v.w = fmaxf(v.w, 0.f);
        }
        acc.x += v.x; acc.y += v.y; acc.z += v.z; acc.w += v.w;
    }
    ((float4*)(dst + (size_t)atom * HIDDEN))[c] = acc;
}

// ---------------- segment mean pieces ---------------------------------------
__global__ void zero_seg_kernel() {
    int i = blockIdx.x * blockDim.x + threadIdx.x;
    if (i < N_MOLS * HIDDEN) g_sums[i] = 0.f;
    if (i < N_MOLS) g_cnt[i] = 0.f;
}

__global__ void seg_accum_kernel(const float* __restrict__ ah,
                                 const int* __restrict__ mol_ids)
{
    int atom = blockIdx.x;
    int mol  = __ldg(&mol_ids[atom]);
    int c    = threadIdx.x;
    float4 v = __ldg((const float4*)(ah + (size_t)atom * HIDDEN) + c);
    float* s = g_sums + (size_t)mol * HIDDEN + c * 4;
    atomicAdd(s + 0, v.x);
    atomicAdd(s + 1, v.y);
    atomicAdd(s + 2, v.z);
    atomicAdd(s + 3, v.w);
    if (c == 0) atomicAdd(&g_cnt[mol], 1.f);
}

// ---------------- pairwise feature build ------------------------------------
__global__ void feature_kernel(const int* __restrict__ edges,
                               float* __restrict__ feat)
{
    int p = blockIdx.x;
    int a = __ldg(&edges[p]);
    int b = __ldg(&edges[N_PAIRS + p]);
    float ia = 1.f / fmaxf(__ldg(&g_cnt[a]), 1.f);
    float ib = 1.f / fmaxf(__ldg(&g_cnt[b]), 1.f);
    int c = threadIdx.x;
    float4 va = __ldg((const float4*)(g_sums + (size_t)a * HIDDEN) + c);
    float4 vb = __ldg((const float4*)(g_sums + (size_t)b * HIDDEN) + c);
    va.x *= ia; va.y *= ia; va.z *= ia; va.w *= ia;
    vb.x *= ib; vb.y *= ib; vb.z *= ib; vb.w *= ib;
    float* frow = feat + (size_t)p * (4 * HIDDEN);
    float4 s = make_float4(va.x + vb.x, va.y + vb.y, va.z + vb.z, va.w + vb.w);
    float4 m = make_float4(va.x * vb.x, va.y * vb.y, va.z * vb.z, va.w * vb.w);
    ((float4*)(frow + 0 * HIDDEN))[c] = s;
    ((float4*)(frow + 1 * HIDDEN))[c] = m;
    ((float4*)(frow + 2 * HIDDEN))[c] = va;
    ((float4*)(frow + 3 * HIDDEN))[c] = vb;
}

// ---------------- final dot + sigmoid ---------------------------------------
__global__ void ffn_last_kernel(const float* __restrict__ h2,
                                const float* __restrict__ W,
                                const float* __restrict__ b,
                                float* __restrict__ out)
{
    int p = blockIdx.x;
    float s = 0.f;
    for (int i = threadIdx.x; i < FFN2; i += 128)
        s += h2[(size_t)p * FFN2 + i] * W[i];
#pragma unroll
    for (int off = 16; off; off >>= 1)
        s += __shfl_down_sync(0xffffffffu, s, off);
    __shared__ float red[4];
    if ((threadIdx.x & 31) == 0) red[threadIdx.x >> 5] = s;
    __syncthreads();
    if (threadIdx.x == 0) {
        float t = red[0] + red[1] + red[2] + red[3] + b[0];
        out[p] = 1.f / (1.f + expf(-t));
    }
}

// ---------------- launch ----------------------------------------------------
extern "C" void kernel_launch(void* const* d_in, const int* in_sizes, int n_in,
                              void* d_out, int out_size)
{
    const float* f_atoms = (const float*)d_in[0];
    const int*   a_nei   = (const int*)d_in[1];
    const int*   mol_ids = (const int*)d_in[2];
    const int*   edges   = (const int*)d_in[3];
    const float* W_i     = (const float*)d_in[4];
    const float* W_h     = (const float*)d_in[5];
    const float* W_o     = (const float*)d_in[6];
    const float* b_o     = (const float*)d_in[7];
    const float* W_fi    = (const float*)d_in[8];
    const float* b_fi    = (const float*)d_in[9];
    const float* W_f1    = (const float*)d_in[10];
    const float* b_f1    = (const float*)d_in[11];
    const float* W_f2    = (const float*)d_in[12];
    const float* b_f2    = (const float*)d_in[13];
    float* out = (float*)d_out;

    float *cat, *bufA, *bufB, *bufC, *h2p, *padA, *wcat;
    cudaGetSymbolAddress((void**)&cat,  g_cat);
    cudaGetSymbolAddress((void**)&bufA, g_bufA);
    cudaGetSymbolAddress((void**)&bufB, g_bufB);
    cudaGetSymbolAddress((void**)&bufC, g_bufC);
    cudaGetSymbolAddress((void**)&h2p,  g_h2);
    cudaGetSymbolAddress((void**)&padA, g_padA);
    cudaGetSymbolAddress((void**)&wcat, g_Wcat);

    cudaFuncSetAttribute(mma_gemm<false, false, false>,
                         cudaFuncAttributeMaxDynamicSharedMemorySize, SMEM_BYTES);
    cudaFuncSetAttribute(mma_gemm<true, true, false>,
                         cudaFuncAttributeMaxDynamicSharedMemorySize, SMEM_BYTES);
    cudaFuncSetAttribute(mma_gemm<true, true, true>,
                         cudaFuncAttributeMaxDynamicSharedMemorySize, SMEM_BYTES);
    cudaFuncSetAttribute(mma_gemm<true, false, true>,
                         cudaFuncAttributeMaxDynamicSharedMemorySize, SMEM_BYTES);

    pad_atoms_kernel<<<(N_ATOMS * KPAD_F + 255) / 256, 256>>>(f_atoms, padA);
    build_wcat_kernel<<<(KPAD_F * 1024 + 255) / 256, 256>>>(W_i, W_o, wcat);

    const int MT = (N_ATOMS + BM - 1) / BM;  // 782

    // 1+5. [inp | ah_partial] = padA @ [W_i | W_o_top]   -> g_cat [N,1024]
    mma_gemm<false, false, false><<<dim3(1024 / BN, MT), 256, SMEM_BYTES>>>(
        N_ATOMS, 1024, KPAD_F, KPAD_F, 0, 1024, padA, wcat, nullptr, nullptr, cat);
    // 2. bufB = sum_j relu(inp[nei])
    gather_sum_kernel<<<N_ATOMS, 128>>>(cat, 1024, a_nei, bufB, 1);
    // 3. msg2 = relu(inp + bufB @ W_h)                   -> bufC
    mma_gemm<true, true, false><<<dim3(HIDDEN / BN, MT), 256, SMEM_BYTES>>>(
        N_ATOMS, HIDDEN, HIDDEN, HIDDEN, 1024, HIDDEN, bufB, W_h, cat, nullptr, bufC);
    // 4. bufB = sum_j msg2[nei]
    gather_sum_kernel<<<N_ATOMS, 128>>>(bufC, HIDDEN, a_nei, bufB, 0);
    // 6. atom_hiddens = relu(ah_partial + bufB @ W_o_bot + b_o)  -> bufA
    mma_gemm<true, true, true><<<dim3(HIDDEN / BN, MT), 256, SMEM_BYTES>>>(
        N_ATOMS, HIDDEN, HIDDEN, HIDDEN, 1024, HIDDEN, bufB, W_o + ATOM_FDIM * HIDDEN,
        cat + HIDDEN, b_o, bufA);
    // 7-8. segment sums + counts
    zero_seg_kernel<<<(N_MOLS * HIDDEN + 255) / 256, 256>>>();
    seg_accum_kernel<<<N_ATOMS, 128>>>(bufA, mol_ids);
    // 9. pairwise features [P, 4H]                        -> bufC
    feature_kernel<<<N_PAIRS, 128>>>(edges, bufC);
    // 10. h1 = relu(feat @ W_ffn_i + b_ffn_i)             -> bufB
    mma_gemm<true, false, true><<<dim3(FFN1 / BN, N_PAIRS / BM), 256, SMEM_BYTES>>>(
        N_PAIRS, FFN1, 4 * HIDDEN, 4 * HIDDEN, 0, FFN1, bufC, W_fi, nullptr, b_fi, bufB);
    // 11. h2 = relu(h1 @ W_ffn_1 + b_ffn_1)               -> g_h2
    mma_gemm<true, false, true><<<dim3(FFN2 / BN, N_PAIRS / BM), 256, SMEM_BYTES>>>(
        N_PAIRS, FFN2, FFN1, FFN1, 0, FFN2, bufB, W_f1, nullptr, b_f1, h2p);
    // 12. out = sigmoid(h2 . W_ffn_2 + b_ffn_2)
    ffn_last_kernel<<<N_PAIRS, 128>>>(h2p, W_f2, b_f2, out);
}

// round 6
// speedup vs baseline: 3.7745x; 1.0414x over previous
#include <cuda_runtime.h>
#include <math.h>
#include <stdint.h>

#define N_ATOMS   100000
#define ATOM_FDIM 133
#define KPAD_F    160
#define HIDDEN    512
#define MAX_NEI   6
#define N_MOLS    4096
#define N_PAIRS   8192
#define FFN1      2048
#define FFN2      1024

// ---------------- scratch (device globals: allocation-free) ----------------
__device__ float g_cat [N_ATOMS * 1024];   // cols 0-511: inp, 512-1023: ah_partial
__device__ float g_bufA[N_ATOMS * HIDDEN];
__device__ float g_bufB[N_ATOMS * HIDDEN];
__device__ float g_bufC[N_ATOMS * HIDDEN];
__device__ float g_h2[N_PAIRS * FFN2];
__device__ float g_sums[N_MOLS * HIDDEN];
__device__ float g_cnt[N_MOLS];
__device__ float g_padA[N_ATOMS * KPAD_F];
// transposed weights [N][K] (K-contiguous)
__device__ float g_WcatT[1024 * KPAD_F];
__device__ float g_WhT  [HIDDEN * HIDDEN];
__device__ float g_Wo2T [HIDDEN * HIDDEN];
__device__ float g_WfiT [FFN1 * (4 * HIDDEN)];
__device__ float g_Wf1T [FFN2 * FFN1];

// ---------------- PTX helpers ----------------------------------------------
__device__ __forceinline__ uint32_t smem_u32(const void* p) {
    return (uint32_t)__cvta_generic_to_shared(p);
}
__device__ __forceinline__ void cp16(uint32_t s, const void* g, uint32_t bytes) {
    asm volatile("cp.async.cg.shared.global [%0], [%1], 16, %2;\n"
                 :: "r"(s), "l"(g), "r"(bytes));
}
__device__ __forceinline__ void cp_commit() {
    asm volatile("cp.async.commit_group;\n" ::: "memory");
}
template <int N>
__device__ __forceinline__ void cp_wait() {
    asm volatile("cp.async.wait_group %0;\n" :: "n"(N) : "memory");
}
__device__ __forceinline__ void ldsm4(uint32_t* r, uint32_t addr) {
    asm volatile("ldmatrix.sync.aligned.m8n8.x4.shared.b16 {%0,%1,%2,%3}, [%4];\n"
                 : "=r"(r[0]), "=r"(r[1]), "=r"(r[2]), "=r"(r[3]) : "r"(addr));
}
// fp32 bits fed directly as tf32 operands (HW truncates low mantissa bits).
__device__ __forceinline__ void mma_tf32(float* c, const uint32_t* a, const uint32_t* b) {
    asm volatile(
        "mma.sync.aligned.m16n8k8.row.col.f32.tf32.tf32.f32 "
        "{%0,%1,%2,%3}, {%4,%5,%6,%7}, {%8,%9}, {%0,%1,%2,%3};\n"
        : "+f"(c[0]), "+f"(c[1]), "+f"(c[2]), "+f"(c[3])
        : "r"(a[0]), "r"(a[1]), "r"(a[2]), "r"(a[3]), "r"(b[0]), "r"(b[1]));
}

// ---------------- GEMM tile config ------------------------------------------
#define BM 128
#define BN 128
#define BK 32
#define STAGES 3
#define T_STRIDE 36                          // floats per smem row (pad 4)
#define A_ELEMS (BM * T_STRIDE)              // 4608
#define B_ELEMS (BN * T_STRIDE)              // 4608
#define STAGE_ELEMS (A_ELEMS + B_ELEMS)      // 9216
#define STAGE_BYTES (STAGE_ELEMS * 4)        // 36864
#define SMEM_BYTES (STAGES * STAGE_BYTES)    // 110592

// ---------------- tf32 mma.sync GEMM: C = A[MxK] @ BT[NxK]^T ----------------
// A row-major ld=lda; BT row-major [N][K] ld=ldb; Cin ld=ldcin; C ld=ldc.
// N % 128 == 0, K % 32 == 0 required.
template <bool RELU, bool ADDC, bool BIAS>
__global__ __launch_bounds__(256, 2)
void mma_gemm(int M, int N, int K, int lda, int ldb, int ldcin, int ldc,
              const float* __restrict__ A, const float* __restrict__ BT,
              const float* __restrict__ Cin, const float* __restrict__ bias,
              float* __restrict__ C)
{
    extern __shared__ float sm[];
    const uint32_t sbase = smem_u32(sm);
    const int tid = threadIdx.x;
    const int lane = tid & 31, wid = tid >> 5;
    const int wm = wid & 3, wn = wid >> 2;     // warp grid 4 x 2
    const int gid = lane >> 2, tig = lane & 3;
    const int rowBase = blockIdx.y * BM;
    const int colBase = blockIdx.x * BN;
    const int nk = K / BK;

    // ---- hoisted gmem->smem addressing (both tiles are 128 rows x 32 floats)
    const float* aPtr[4]; uint32_t aSm[4]; uint32_t aBytes[4];
    const float* bPtr[4]; uint32_t bSm[4];
#pragma unroll
    for (int j = 0; j < 4; j++) {
        int idx = tid + j * 256;
        int row = idx >> 3, c = idx & 7;           // c: 16B chunk of 32-float row
        int grow = rowBase + row;
        int crow = grow < M ? grow : 0;
        aPtr[j]   = A + (size_t)crow * lda + c * 4;
        aSm[j]    = sbase + (uint32_t)(row * T_STRIDE + c * 4) * 4;
        aBytes[j] = grow < M ? 16u : 0u;
        bPtr[j] = BT + (size_t)(colBase + row) * ldb + c * 4;
        bSm[j]  = sbase + (uint32_t)(A_ELEMS + row * T_STRIDE + c * 4) * 4;
    }

    auto load_stage = [&](int stg, int kc0) {
        const uint32_t so = (uint32_t)stg * STAGE_BYTES;
#pragma unroll
        for (int j = 0; j < 4; j++)
            cp16(aSm[j] + so, aPtr[j] + kc0, aBytes[j]);
#pragma unroll
        for (int j = 0; j < 4; j++)
            cp16(bSm[j] + so, bPtr[j] + kc0, 16u);
        cp_commit();
    };

    // ---- hoisted ldmatrix addressing ----
    const int sel = lane >> 3, r8 = lane & 7;
    uint32_t aLd[2], bLd[4];
#pragma unroll
    for (int mt = 0; mt < 2; mt++) {
        int row = wm * 32 + mt * 16 + ((sel & 1) << 3) + r8;
        int col = (sel >> 1) << 2;
        aLd[mt] = sbase + (uint32_t)(row * T_STRIDE + col) * 4;
    }
#pragma unroll
    for (int j = 0; j < 4; j++) {
        int row = wn * 64 + j * 16 + ((sel >> 1) << 3) + r8;
        int col = (sel & 1) << 2;
        bLd[j] = sbase + (uint32_t)(A_ELEMS + row * T_STRIDE + col) * 4;
    }

    float acc[2][8][4];
#pragma unroll
    for (int mt = 0; mt < 2; mt++)
#pragma unroll
        for (int nt = 0; nt < 8; nt++)
#pragma unroll
            for (int i = 0; i < 4; i++) acc[mt][nt][i] = 0.f;

    load_stage(0, 0);
    if (nk > 1) load_stage(1, BK);

    int buf = 0;
    for (int kt = 0; kt < nk; kt++) {
        if (kt == nk - 1) cp_wait<0>(); else cp_wait<1>();
        __syncthreads();
        if (kt + 2 < nk)
            load_stage((buf + 2) % STAGES, (kt + 2) * BK);

        const uint32_t so = (uint32_t)buf * STAGE_BYTES;
#pragma unroll
        for (int ks = 0; ks < 4; ks++) {
            const uint32_t ko = so + ks * 32;   // 8 floats per k-step
            uint32_t af[2][4], bf[4][4];
            ldsm4(af[0], aLd[0] + ko);
            ldsm4(af[1], aLd[1] + ko);
#pragma unroll
            for (int j = 0; j < 4; j++)
                ldsm4(bf[j], bLd[j] + ko);
#pragma unroll
            for (int mt = 0; mt < 2; mt++)
#pragma unroll
                for (int j = 0; j < 4; j++) {
                    mma_tf32(acc[mt][2 * j],     af[mt], &bf[j][0]);
                    mma_tf32(acc[mt][2 * j + 1], af[mt], &bf[j][2]);
                }
        }
        buf = (buf + 1) % STAGES;
    }

    // ---- epilogue ----
#pragma unroll
    for (int mt = 0; mt < 2; mt++) {
        const int row0 = rowBase + wm * 32 + mt * 16 + gid;
        const int row1 = row0 + 8;
#pragma unroll
        for (int nt = 0; nt < 8; nt++) {
            const int gc = colBase + wn * 64 + nt * 8 + tig * 2;
            float2 v0 = make_float2(acc[mt][nt][0], acc[mt][nt][1]);
            float2 v1 = make_float2(acc[mt][nt][2], acc[mt][nt][3]);
            if (BIAS) {
                const float2 bb = *(const float2*)(bias + gc);
                v0.x += bb.x; v0.y += bb.y;
                v1.x += bb.x; v1.y += bb.y;
            }
            if (row0 < M) {
                if (ADDC) {
                    const float2 ci = *(const float2*)(Cin + (size_t)row0 * ldcin + gc);
                    v0.x += ci.x; v0.y += ci.y;
                }
                if (RELU) { v0.x = fmaxf(v0.x, 0.f); v0.y = fmaxf(v0.y, 0.f); }
                *(float2*)(C + (size_t)row0 * ldc + gc) = v0;
            }
            if (row1 < M) {
                if (ADDC) {
                    const float2 ci = *(const float2*)(Cin + (size_t)row1 * ldcin + gc);
                    v1.x += ci.x; v1.y += ci.y;
                }
                if (RELU) { v1.x = fmaxf(v1.x, 0.f); v1.y = fmaxf(v1.y, 0.f); }
                *(float2*)(C + (size_t)row1 * ldc + gc) = v1;
            }
        }
    }
}

// ---------------- prologue prep ---------------------------------------------
__global__ void pad_atoms_kernel(const float* __restrict__ f, float* __restrict__ out) {
    int idx = blockIdx.x * blockDim.x + threadIdx.x;
    if (idx >= N_ATOMS * KPAD_F) return;
    int a = idx / KPAD_F, k = idx - a * KPAD_F;
    out[idx] = (k < ATOM_FDIM) ? f[a * ATOM_FDIM + k] : 0.f;
}

// WT[n][k] = (k < K) ? W[k][n] : 0 ; WT is [N][Kpad]
__global__ void transpose_pad_kernel(const float* __restrict__ W, float* __restrict__ WT,
                                     int K, int N, int Kpad) {
    __shared__ float t[32][33];
    int kb = blockIdx.y * 32, nb = blockIdx.x * 32;
    int tx = threadIdx.x, ty = threadIdx.y;
#pragma unroll
    for (int i = 0; i < 4; i++) {
        int kk = kb + ty + i * 8;
        t[ty + i * 8][tx] = (kk < K) ? W[(size_t)kk * N + nb + tx] : 0.f;
    }
    __syncthreads();
#pragma unroll
    for (int i = 0; i < 4; i++) {
        int n = nb + ty + i * 8;
        WT[(size_t)n * Kpad + kb + tx] = t[tx][ty + i * 8];
    }
}

// WcatT[n][k]: n<512 -> W_i[k][n]; else W_o_top[k][n-512]; k>=133 -> 0
__global__ void build_wcatT_kernel(const float* __restrict__ Wi,
                                   const float* __restrict__ Wo,
                                   float* __restrict__ out) {
    int idx = blockIdx.x * blockDim.x + threadIdx.x;
    if (idx >= 1024 * KPAD_F) return;
    int n = idx / KPAD_F, k = idx - n * KPAD_F;
    float v = 0.f;
    if (k < ATOM_FDIM)
        v = (n < HIDDEN) ? Wi[k * HIDDEN + n] : Wo[k * HIDDEN + (n - HIDDEN)];
    out[idx] = v;
}

// ---------------- neighbor gather-sum ---------------------------------------
__global__ void gather_sum_kernel(const float* __restrict__ src, int srcStride,
                                  const int* __restrict__ nei,
                                  float* __restrict__ dst, int relu_src)
{
    int atom = blockIdx.x;
    int c = threadIdx.x;
    const int* nrow = nei + atom * MAX_NEI;
    float4 acc = make_float4(0.f, 0.f, 0.f, 0.f);
#pragma unroll
    for (int j = 0; j < MAX_NEI; j++) {
        int n = __ldg(&nrow[j]);
        float4 v = __ldg((const float4*)(src + (size_t)n * srcStride) + c);
        if (relu_src) {
            v.x = fmaxf(v.x, 0.f); v.y = fmaxf(v.y, 0.f);
            v.z = fmaxf(v.z, 0.f); v.w = fmaxf(v.w, 0.f);
        }
        acc.x += v.x; acc.y += v.y; acc.z += v.z; acc.w += v.w;
    }
    ((float4*)(dst + (size_t)atom * HIDDEN))[c] = acc;
}

// ---------------- segment mean pieces ---------------------------------------
__global__ void zero_seg_kernel() {
    int i = blockIdx.x * blockDim.x + threadIdx.x;
    if (i < N_MOLS * HIDDEN) g_sums[i] = 0.f;
    if (i < N_MOLS) g_cnt[i] = 0.f;
}

__global__ void seg_accum_kernel(const float* __restrict__ ah,
                                 const int* __restrict__ mol_ids)
{
    int atom = blockIdx.x;
    int mol  = __ldg(&mol_ids[atom]);
    int c    = threadIdx.x;
    float4 v = __ldg((const float4*)(ah + (size_t)atom * HIDDEN) + c);
    float* s = g_sums + (size_t)mol * HIDDEN + c * 4;
    atomicAdd(s + 0, v.x);
    atomicAdd(s + 1, v.y);
    atomicAdd(s + 2, v.z);
    atomicAdd(s + 3, v.w);
    if (c == 0) atomicAdd(&g_cnt[mol], 1.f);
}

// ---------------- pairwise feature build ------------------------------------
__global__ void feature_kernel(const int* __restrict__ edges,
                               float* __restrict__ feat)
{
    int p = blockIdx.x;
    int a = __ldg(&edges[p]);
    int b = __ldg(&edges[N_PAIRS + p]);
    float ia = 1.f / fmaxf(__ldg(&g_cnt[a]), 1.f);
    float ib = 1.f / fmaxf(__ldg(&g_cnt[b]), 1.f);
    int c = threadIdx.x;
    float4 va = __ldg((const float4*)(g_sums + (size_t)a * HIDDEN) + c);
    float4 vb = __ldg((const float4*)(g_sums + (size_t)b * HIDDEN) + c);
    va.x *= ia; va.y *= ia; va.z *= ia; va.w *= ia;
    vb.x *= ib; vb.y *= ib; vb.z *= ib; vb.w *= ib;
    float* frow = feat + (size_t)p * (4 * HIDDEN);
    float4 s = make_float4(va.x + vb.x, va.y + vb.y, va.z + vb.z, va.w + vb.w);
    float4 m = make_float4(va.x * vb.x, va.y * vb.y, va.z * vb.z, va.w * vb.w);
    ((float4*)(frow + 0 * HIDDEN))[c] = s;
    ((float4*)(frow + 1 * HIDDEN))[c] = m;
    ((float4*)(frow + 2 * HIDDEN))[c] = va;
    ((float4*)(frow + 3 * HIDDEN))[c] = vb;
}

// ---------------- final dot + sigmoid ---------------------------------------
__global__ void ffn_last_kernel(const float* __restrict__ h2,
                                const float* __restrict__ W,
                                const float* __restrict__ b,
                                float* __restrict__ out)
{
    int p = blockIdx.x;
    float s = 0.f;
    for (int i = threadIdx.x; i < FFN2; i += 128)
        s += h2[(size_t)p * FFN2 + i] * W[i];
#pragma unroll
    for (int off = 16; off; off >>= 1)
        s += __shfl_down_sync(0xffffffffu, s, off);
    __shared__ float red[4];
    if ((threadIdx.x & 31) == 0) red[threadIdx.x >> 5] = s;
    __syncthreads();
    if (threadIdx.x == 0) {
        float t = red[0] + red[1] + red[2] + red[3] + b[0];
        out[p] = 1.f / (1.f + expf(-t));
    }
}

// ---------------- launch ----------------------------------------------------
extern "C" void kernel_launch(void* const* d_in, const int* in_sizes, int n_in,
                              void* d_out, int out_size)
{
    const float* f_atoms = (const float*)d_in[0];
    const int*   a_nei   = (const int*)d_in[1];
    const int*   mol_ids = (const int*)d_in[2];
    const int*   edges   = (const int*)d_in[3];
    const float* W_i     = (const float*)d_in[4];
    const float* W_h     = (const float*)d_in[5];
    const float* W_o     = (const float*)d_in[6];
    const float* b_o     = (const float*)d_in[7];
    const float* W_fi    = (const float*)d_in[8];
    const float* b_fi    = (const float*)d_in[9];
    const float* W_f1    = (const float*)d_in[10];
    const float* b_f1    = (const float*)d_in[11];
    const float* W_f2    = (const float*)d_in[12];
    const float* b_f2    = (const float*)d_in[13];
    float* out = (float*)d_out;

    float *cat, *bufA, *bufB, *bufC, *h2p, *padA;
    float *wcatT, *whT, *wo2T, *wfiT, *wf1T;
    cudaGetSymbolAddress((void**)&cat,   g_cat);
    cudaGetSymbolAddress((void**)&bufA,  g_bufA);
    cudaGetSymbolAddress((void**)&bufB,  g_bufB);
    cudaGetSymbolAddress((void**)&bufC,  g_bufC);
    cudaGetSymbolAddress((void**)&h2p,   g_h2);
    cudaGetSymbolAddress((void**)&padA,  g_padA);
    cudaGetSymbolAddress((void**)&wcatT, g_WcatT);
    cudaGetSymbolAddress((void**)&whT,   g_WhT);
    cudaGetSymbolAddress((void**)&wo2T,  g_Wo2T);
    cudaGetSymbolAddress((void**)&wfiT,  g_WfiT);
    cudaGetSymbolAddress((void**)&wf1T,  g_Wf1T);

    cudaFuncSetAttribute(mma_gemm<false, false, false>,
                         cudaFuncAttributeMaxDynamicSharedMemorySize, SMEM_BYTES);
    cudaFuncSetAttribute(mma_gemm<true, true, false>,
                         cudaFuncAttributeMaxDynamicSharedMemorySize, SMEM_BYTES);
    cudaFuncSetAttribute(mma_gemm<true, true, true>,
                         cudaFuncAttributeMaxDynamicSharedMemorySize, SMEM_BYTES);
    cudaFuncSetAttribute(mma_gemm<true, false, true>,
                         cudaFuncAttributeMaxDynamicSharedMemorySize, SMEM_BYTES);

    // prep: pad A, transpose weights to [N][K]
    pad_atoms_kernel<<<(N_ATOMS * KPAD_F + 255) / 256, 256>>>(f_atoms, padA);
    build_wcatT_kernel<<<(1024 * KPAD_F + 255) / 256, 256>>>(W_i, W_o, wcatT);
    dim3 tb(32, 8);
    transpose_pad_kernel<<<dim3(HIDDEN / 32, HIDDEN / 32), tb>>>(W_h, whT, HIDDEN, HIDDEN, HIDDEN);
    transpose_pad_kernel<<<dim3(HIDDEN / 32, HIDDEN / 32), tb>>>(W_o + ATOM_FDIM * HIDDEN, wo2T, HIDDEN, HIDDEN, HIDDEN);
    transpose_pad_kernel<<<dim3(FFN1 / 32, (4 * HIDDEN) / 32), tb>>>(W_fi, wfiT, 4 * HIDDEN, FFN1, 4 * HIDDEN);
    transpose_pad_kernel<<<dim3(FFN2 / 32, FFN1 / 32), tb>>>(W_f1, wf1T, FFN1, FFN2, FFN1);

    const int MT = (N_ATOMS + BM - 1) / BM;  // 782

    // 1+5. [inp | ah_partial] = padA @ Wcat              -> g_cat [N,1024]
    mma_gemm<false, false, false><<<dim3(1024 / BN, MT), 256, SMEM_BYTES>>>(
        N_ATOMS, 1024, KPAD_F, KPAD_F, KPAD_F, 0, 1024, padA, wcatT, nullptr, nullptr, cat);
    // 2. bufB = sum_j relu(inp[nei])
    gather_sum_kernel<<<N_ATOMS, 128>>>(cat, 1024, a_nei, bufB, 1);
    // 3. msg2 = relu(inp + bufB @ W_h)                   -> bufC
    mma_gemm<true, true, false><<<dim3(HIDDEN / BN, MT), 256, SMEM_BYTES>>>(
        N_ATOMS, HIDDEN, HIDDEN, HIDDEN, HIDDEN, 1024, HIDDEN, bufB, whT, cat, nullptr, bufC);
    // 4. bufB = sum_j msg2[nei]
    gather_sum_kernel<<<N_ATOMS, 128>>>(bufC, HIDDEN, a_nei, bufB, 0);
    // 6. atom_hiddens = relu(ah_partial + bufB @ W_o_bot + b_o)  -> bufA
    mma_gemm<true, true, true><<<dim3(HIDDEN / BN, MT), 256, SMEM_BYTES>>>(
        N_ATOMS, HIDDEN, HIDDEN, HIDDEN, HIDDEN, 1024, HIDDEN, bufB, wo2T,
        cat + HIDDEN, b_o, bufA);
    // 7-8. segment sums + counts
    zero_seg_kernel<<<(N_MOLS * HIDDEN + 255) / 256, 256>>>();
    seg_accum_kernel<<<N_ATOMS, 128>>>(bufA, mol_ids);
    // 9. pairwise features [P, 4H]                        -> bufC
    feature_kernel<<<N_PAIRS, 128>>>(edges, bufC);
    // 10. h1 = relu(feat @ W_ffn_i + b_ffn_i)             -> bufB
    mma_gemm<true, false, true><<<dim3(FFN1 / BN, N_PAIRS / BM), 256, SMEM_BYTES>>>(
        N_PAIRS, FFN1, 4 * HIDDEN, 4 * HIDDEN, 4 * HIDDEN, 0, FFN1, bufC, wfiT, nullptr, b_fi, bufB);
    // 11. h2 = relu(h1 @ W_ffn_1 + b_ffn_1)               -> g_h2
    mma_gemm<true, false, true><<<dim3(FFN2 / BN, N_PAIRS / BM), 256, SMEM_BYTES>>>(
        N_PAIRS, FFN2, FFN1, FFN1, FFN1, 0, FFN2, bufB, wf1T, nullptr, b_f1, h2p);
    // 12. out = sigmoid(h2 . W_ffn_2 + b_ffn_2)
    ffn_last_kernel<<<N_PAIRS, 128>>>(h2p, W_f2, b_f2, out);
}

// round 7
// speedup vs baseline: 4.0241x; 1.0661x over previous
#include <cuda_runtime.h>
#include <math.h>
#include <stdint.h>

#define N_ATOMS   100000
#define ATOM_FDIM 133
#define KPAD_F    160
#define HIDDEN    512
#define MAX_NEI   6
#define N_MOLS    4096
#define N_PAIRS   8192
#define FFN1      2048
#define FFN2      1024

// ---------------- scratch (device globals: allocation-free) ----------------
__device__ float g_cat [N_ATOMS * 1024];   // cols 0-511: inp, 512-1023: ah_partial
__device__ float g_bufA[N_ATOMS * HIDDEN];
__device__ float g_bufB[N_ATOMS * HIDDEN];
__device__ float g_bufC[N_ATOMS * HIDDEN];
__device__ float g_h2[N_PAIRS * FFN2];
__device__ float g_sums[N_MOLS * HIDDEN];
__device__ float g_cnt[N_MOLS];
__device__ float g_mv[N_MOLS * HIDDEN];
__device__ float g_U[N_MOLS * 4096];       // [U1 | U2] per molecule
__device__ float g_padA[N_ATOMS * KPAD_F];
// transposed weights [N][K] (K-contiguous)
__device__ float g_WcatT [1024 * KPAD_F];
__device__ float g_WhT   [HIDDEN * HIDDEN];
__device__ float g_Wo2T  [HIDDEN * HIDDEN];
__device__ float g_WcombT[4096 * HIDDEN];  // [(Ws+W1)^T | (Ws+W2)^T]
__device__ float g_WmT   [FFN1 * HIDDEN];
__device__ float g_Wf1T  [FFN2 * FFN1];

// ---------------- PTX helpers ----------------------------------------------
__device__ __forceinline__ uint32_t smem_u32(const void* p) {
    return (uint32_t)__cvta_generic_to_shared(p);
}
__device__ __forceinline__ void cp16(uint32_t s, const void* g, uint32_t bytes) {
    asm volatile("cp.async.cg.shared.global [%0], [%1], 16, %2;\n"
                 :: "r"(s), "l"(g), "r"(bytes));
}
__device__ __forceinline__ void cp_commit() {
    asm volatile("cp.async.commit_group;\n" ::: "memory");
}
template <int N>
__device__ __forceinline__ void cp_wait() {
    asm volatile("cp.async.wait_group %0;\n" :: "n"(N) : "memory");
}
__device__ __forceinline__ void ldsm4(uint32_t* r, uint32_t addr) {
    asm volatile("ldmatrix.sync.aligned.m8n8.x4.shared.b16 {%0,%1,%2,%3}, [%4];\n"
                 : "=r"(r[0]), "=r"(r[1]), "=r"(r[2]), "=r"(r[3]) : "r"(addr));
}
// fp32 bits fed directly as tf32 operands (HW truncates low mantissa bits).
__device__ __forceinline__ void mma_tf32(float* c, const uint32_t* a, const uint32_t* b) {
    asm volatile(
        "mma.sync.aligned.m16n8k8.row.col.f32.tf32.tf32.f32 "
        "{%0,%1,%2,%3}, {%4,%5,%6,%7}, {%8,%9}, {%0,%1,%2,%3};\n"
        : "+f"(c[0]), "+f"(c[1]), "+f"(c[2]), "+f"(c[3])
        : "r"(a[0]), "r"(a[1]), "r"(a[2]), "r"(a[3]), "r"(b[0]), "r"(b[1]));
}

// ---------------- GEMM tile config ------------------------------------------
#define BM 128
#define BN 128
#define BK 32
#define STAGES 3
#define T_STRIDE 36
#define A_ELEMS (BM * T_STRIDE)
#define B_ELEMS (BN * T_STRIDE)
#define STAGE_ELEMS (A_ELEMS + B_ELEMS)
#define STAGE_BYTES (STAGE_ELEMS * 4)
#define SMEM_BYTES (STAGES * STAGE_BYTES)   // 110592

// ---------------- tf32 mma.sync GEMM: C = A[MxK] @ BT[NxK]^T ----------------
template <bool RELU, bool ADDC, bool BIAS>
__global__ __launch_bounds__(256, 2)
void mma_gemm(int M, int N, int K, int lda, int ldb, int ldcin, int ldc,
              const float* __restrict__ A, const float* __restrict__ BT,
              const float* __restrict__ Cin, const float* __restrict__ bias,
              float* __restrict__ C)
{
    extern __shared__ float sm[];
    const uint32_t sbase = smem_u32(sm);
    const int tid = threadIdx.x;
    const int lane = tid & 31, wid = tid >> 5;
    const int wm = wid & 3, wn = wid >> 2;
    const int gid = lane >> 2, tig = lane & 3;
    const int rowBase = blockIdx.y * BM;
    const int colBase = blockIdx.x * BN;
    const int nk = K / BK;

    const float* aPtr[4]; uint32_t aSm[4]; uint32_t aBytes[4];
    const float* bPtr[4]; uint32_t bSm[4];
#pragma unroll
    for (int j = 0; j < 4; j++) {
        int idx = tid + j * 256;
        int row = idx >> 3, c = idx & 7;
        int grow = rowBase + row;
        int crow = grow < M ? grow : 0;
        aPtr[j]   = A + (size_t)crow * lda + c * 4;
        aSm[j]    = sbase + (uint32_t)(row * T_STRIDE + c * 4) * 4;
        aBytes[j] = grow < M ? 16u : 0u;
        bPtr[j] = BT + (size_t)(colBase + row) * ldb + c * 4;
        bSm[j]  = sbase + (uint32_t)(A_ELEMS + row * T_STRIDE + c * 4) * 4;
    }

    auto load_stage = [&](int stg, int kc0) {
        const uint32_t so = (uint32_t)stg * STAGE_BYTES;
#pragma unroll
        for (int j = 0; j < 4; j++)
            cp16(aSm[j] + so, aPtr[j] + kc0, aBytes[j]);
#pragma unroll
        for (int j = 0; j < 4; j++)
            cp16(bSm[j] + so, bPtr[j] + kc0, 16u);
        cp_commit();
    };

    const int sel = lane >> 3, r8 = lane & 7;
    uint32_t aLd[2], bLd[4];
#pragma unroll
    for (int mt = 0; mt < 2; mt++) {
        int row = wm * 32 + mt * 16 + ((sel & 1) << 3) + r8;
        int col = (sel >> 1) << 2;
        aLd[mt] = sbase + (uint32_t)(row * T_STRIDE + col) * 4;
    }
#pragma unroll
    for (int j = 0; j < 4; j++) {
        int row = wn * 64 + j * 16 + ((sel >> 1) << 3) + r8;
        int col = (sel & 1) << 2;
        bLd[j] = sbase + (uint32_t)(A_ELEMS + row * T_STRIDE + col) * 4;
    }

    float acc[2][8][4];
#pragma unroll
    for (int mt = 0; mt < 2; mt++)
#pragma unroll
        for (int nt = 0; nt < 8; nt++)
#pragma unroll
            for (int i = 0; i < 4; i++) acc[mt][nt][i] = 0.f;

    load_stage(0, 0);
    if (nk > 1) load_stage(1, BK);

    int buf = 0;
    for (int kt = 0; kt < nk; kt++) {
        if (kt == nk - 1) cp_wait<0>(); else cp_wait<1>();
        __syncthreads();
        if (kt + 2 < nk)
            load_stage((buf + 2) % STAGES, (kt + 2) * BK);

        const uint32_t so = (uint32_t)buf * STAGE_BYTES;
#pragma unroll
        for (int ks = 0; ks < 4; ks++) {
            const uint32_t ko = so + ks * 32;
            uint32_t af[2][4], bf[4][4];
            ldsm4(af[0], aLd[0] + ko);
            ldsm4(af[1], aLd[1] + ko);
#pragma unroll
            for (int j = 0; j < 4; j++)
                ldsm4(bf[j], bLd[j] + ko);
#pragma unroll
            for (int mt = 0; mt < 2; mt++)
#pragma unroll
                for (int j = 0; j < 4; j++) {
                    mma_tf32(acc[mt][2 * j],     af[mt], &bf[j][0]);
                    mma_tf32(acc[mt][2 * j + 1], af[mt], &bf[j][2]);
                }
        }
        buf = (buf + 1) % STAGES;
    }

#pragma unroll
    for (int mt = 0; mt < 2; mt++) {
        const int row0 = rowBase + wm * 32 + mt * 16 + gid;
        const int row1 = row0 + 8;
#pragma unroll
        for (int nt = 0; nt < 8; nt++) {
            const int gc = colBase + wn * 64 + nt * 8 + tig * 2;
            float2 v0 = make_float2(acc[mt][nt][0], acc[mt][nt][1]);
            float2 v1 = make_float2(acc[mt][nt][2], acc[mt][nt][3]);
            if (BIAS) {
                const float2 bb = *(const float2*)(bias + gc);
                v0.x += bb.x; v0.y += bb.y;
                v1.x += bb.x; v1.y += bb.y;
            }
            if (row0 < M) {
                if (ADDC) {
                    const float2 ci = *(const float2*)(Cin + (size_t)row0 * ldcin + gc);
                    v0.x += ci.x; v0.y += ci.y;
                }
                if (RELU) { v0.x = fmaxf(v0.x, 0.f); v0.y = fmaxf(v0.y, 0.f); }
                *(float2*)(C + (size_t)row0 * ldc + gc) = v0;
            }
            if (row1 < M) {
                if (ADDC) {
                    const float2 ci = *(const float2*)(Cin + (size_t)row1 * ldcin + gc);
                    v1.x += ci.x; v1.y += ci.y;
                }
                if (RELU) { v1.x = fmaxf(v1.x, 0.f); v1.y = fmaxf(v1.y, 0.f); }
                *(float2*)(C + (size_t)row1 * ldc + gc) = v1;
            }
        }
    }
}

// ---------------- prologue prep ---------------------------------------------
__global__ void pad_atoms_kernel(const float* __restrict__ f, float* __restrict__ out) {
    int idx = blockIdx.x * blockDim.x + threadIdx.x;
    if (idx >= N_ATOMS * KPAD_F) return;
    int a = idx / KPAD_F, k = idx - a * KPAD_F;
    out[idx] = (k < ATOM_FDIM) ? f[a * ATOM_FDIM + k] : 0.f;
}

__global__ void transpose_pad_kernel(const float* __restrict__ W, float* __restrict__ WT,
                                     int K, int N, int Kpad) {
    __shared__ float t[32][33];
    int kb = blockIdx.y * 32, nb = blockIdx.x * 32;
    int tx = threadIdx.x, ty = threadIdx.y;
#pragma unroll
    for (int i = 0; i < 4; i++) {
        int kk = kb + ty + i * 8;
        t[ty + i * 8][tx] = (kk < K) ? W[(size_t)kk * N + nb + tx] : 0.f;
    }
    __syncthreads();
#pragma unroll
    for (int i = 0; i < 4; i++) {
        int n = nb + ty + i * 8;
        WT[(size_t)n * Kpad + kb + tx] = t[tx][ty + i * 8];
    }
}

__global__ void build_wcatT_kernel(const float* __restrict__ Wi,
                                   const float* __restrict__ Wo,
                                   float* __restrict__ out) {
    int idx = blockIdx.x * blockDim.x + threadIdx.x;
    if (idx >= 1024 * KPAD_F) return;
    int n = idx / KPAD_F, k = idx - n * KPAD_F;
    float v = 0.f;
    if (k < ATOM_FDIM)
        v = (n < HIDDEN) ? Wi[k * HIDDEN + n] : Wo[k * HIDDEN + (n - HIDDEN)];
    out[idx] = v;
}

// WcombT[n][k]: n<2048 -> Wfi[k][n]+Wfi[1024+k][n]; else Wfi[k][n']+Wfi[1536+k][n']
__global__ void build_wcombT_kernel(const float* __restrict__ Wfi,
                                    float* __restrict__ out) {
    int idx = blockIdx.x * blockDim.x + threadIdx.x;
    if (idx >= 4096 * HIDDEN) return;
    int n = idx / HIDDEN, k = idx - n * HIDDEN;
    float v;
    if (n < FFN1)
        v = Wfi[(size_t)k * FFN1 + n] + Wfi[(size_t)(1024 + k) * FFN1 + n];
    else {
        int n2 = n - FFN1;
        v = Wfi[(size_t)k * FFN1 + n2] + Wfi[(size_t)(1536 + k) * FFN1 + n2];
    }
    out[idx] = v;
}

// ---------------- neighbor gather-sum ---------------------------------------
__global__ void gather_sum_kernel(const float* __restrict__ src, int srcStride,
                                  const int* __restrict__ nei,
                                  float* __restrict__ dst, int relu_src)
{
    int atom = blockIdx.x;
    int c = threadIdx.x;
    const int* nrow = nei + atom * MAX_NEI;
    float4 acc = make_float4(0.f, 0.f, 0.f, 0.f);
#pragma unroll
    for (int j = 0; j < MAX_NEI; j++) {
        int n = __ldg(&nrow[j]);
        float4 v = __ldg((const float4*)(src + (size_t)n * srcStride) + c);
        if (relu_src) {
            v.x = fmaxf(v.x, 0.f); v.y = fmaxf(v.y, 0.f);
            v.z = fmaxf(v.z, 0.f); v.w = fmaxf(v.w, 0.f);
        }
        acc.x += v.x; acc.y += v.y; acc.z += v.z; acc.w += v.w;
    }
    ((float4*)(dst + (size_t)atom * HIDDEN))[c] = acc;
}

// ---------------- segment mean pieces ---------------------------------------
__global__ void zero_seg_kernel() {
    int i = blockIdx.x * blockDim.x + threadIdx.x;
    if (i < N_MOLS * HIDDEN) g_sums[i] = 0.f;
    if (i < N_MOLS) g_cnt[i] = 0.f;
}

__global__ void seg_accum_kernel(const float* __restrict__ ah,
                                 const int* __restrict__ mol_ids)
{
    int atom = blockIdx.x;
    int mol  = __ldg(&mol_ids[atom]);
    int c    = threadIdx.x;
    float4 v = __ldg((const float4*)(ah + (size_t)atom * HIDDEN) + c);
    float* s = g_sums + (size_t)mol * HIDDEN + c * 4;
    atomicAdd(s + 0, v.x);
    atomicAdd(s + 1, v.y);
    atomicAdd(s + 2, v.z);
    atomicAdd(s + 3, v.w);
    if (c == 0) atomicAdd(&g_cnt[mol], 1.f);
}

// mv[m] = sums[m] / max(cnt[m], 1)
__global__ void mv_kernel()
{
    int m = blockIdx.x;
    int c = threadIdx.x;
    float inv = 1.f / fmaxf(g_cnt[m], 1.f);
    float4 v = ((const float4*)(g_sums + (size_t)m * HIDDEN))[c];
    v.x *= inv; v.y *= inv; v.z *= inv; v.w *= inv;
    ((float4*)(g_mv + (size_t)m * HIDDEN))[c] = v;
}

// prod[p] = mv[a] * mv[b]                     [P, 512]
__global__ void prod_kernel(const int* __restrict__ edges,
                            float* __restrict__ prod)
{
    int p = blockIdx.x;
    int a = __ldg(&edges[p]);
    int b = __ldg(&edges[N_PAIRS + p]);
    int c = threadIdx.x;
    float4 va = __ldg((const float4*)(g_mv + (size_t)a * HIDDEN) + c);
    float4 vb = __ldg((const float4*)(g_mv + (size_t)b * HIDDEN) + c);
    float4 m = make_float4(va.x * vb.x, va.y * vb.y, va.z * vb.z, va.w * vb.w);
    ((float4*)(prod + (size_t)p * HIDDEN))[c] = m;
}

// base[p] = U1[a] + U2[b] + b_fi              [P, 2048]
__global__ void pair_base_kernel(const int* __restrict__ edges,
                                 const float* __restrict__ bias,
                                 float* __restrict__ base)
{
    int p = blockIdx.x;
    int a = __ldg(&edges[p]);
    int b = __ldg(&edges[N_PAIRS + p]);
    const float4* u1 = (const float4*)(g_U + (size_t)a * 4096);
    const float4* u2 = (const float4*)(g_U + (size_t)b * 4096 + FFN1);
    const float4* bb = (const float4*)bias;
    float4* o = (float4*)(base + (size_t)p * FFN1);
#pragma unroll
    for (int i = 0; i < 2; i++) {
        int c = threadIdx.x + i * 256;
        float4 x = __ldg(u1 + c), y = __ldg(u2 + c), z = __ldg(bb + c);
        x.x += y.x + z.x; x.y += y.y + z.y; x.z += y.z + z.z; x.w += y.w + z.w;
        o[c] = x;
    }
}

// ---------------- final dot + sigmoid ---------------------------------------
__global__ void ffn_last_kernel(const float* __restrict__ h2,
                                const float* __restrict__ W,
                                const float* __restrict__ b,
                                float* __restrict__ out)
{
    int p = blockIdx.x;
    float s = 0.f;
    for (int i = threadIdx.x; i < FFN2; i += 128)
        s += h2[(size_t)p * FFN2 + i] * W[i];
#pragma unroll
    for (int off = 16; off; off >>= 1)
        s += __shfl_down_sync(0xffffffffu, s, off);
    __shared__ float red[4];
    if ((threadIdx.x & 31) == 0) red[threadIdx.x >> 5] = s;
    __syncthreads();
    if (threadIdx.x == 0) {
        float t = red[0] + red[1] + red[2] + red[3] + b[0];
        out[p] = 1.f / (1.f + expf(-t));
    }
}

// ---------------- launch ----------------------------------------------------
extern "C" void kernel_launch(void* const* d_in, const int* in_sizes, int n_in,
                              void* d_out, int out_size)
{
    const float* f_atoms = (const float*)d_in[0];
    const int*   a_nei   = (const int*)d_in[1];
    const int*   mol_ids = (const int*)d_in[2];
    const int*   edges   = (const int*)d_in[3];
    const float* W_i     = (const float*)d_in[4];
    const float* W_h     = (const float*)d_in[5];
    const float* W_o     = (const float*)d_in[6];
    const float* b_o     = (const float*)d_in[7];
    const float* W_fi    = (const float*)d_in[8];
    const float* b_fi    = (const float*)d_in[9];
    const float* W_f1    = (const float*)d_in[10];
    const float* b_f1    = (const float*)d_in[11];
    const float* W_f2    = (const float*)d_in[12];
    const float* b_f2    = (const float*)d_in[13];
    float* out = (float*)d_out;

    float *cat, *bufA, *bufB, *bufC, *h2p, *padA, *mvp, *Up;
    float *wcatT, *whT, *wo2T, *wcombT, *wmT, *wf1T;
    cudaGetSymbolAddress((void**)&cat,    g_cat);
    cudaGetSymbolAddress((void**)&bufA,   g_bufA);
    cudaGetSymbolAddress((void**)&bufB,   g_bufB);
    cudaGetSymbolAddress((void**)&bufC,   g_bufC);
    cudaGetSymbolAddress((void**)&h2p,    g_h2);
    cudaGetSymbolAddress((void**)&padA,   g_padA);
    cudaGetSymbolAddress((void**)&mvp,    g_mv);
    cudaGetSymbolAddress((void**)&Up,     g_U);
    cudaGetSymbolAddress((void**)&wcatT,  g_WcatT);
    cudaGetSymbolAddress((void**)&whT,    g_WhT);
    cudaGetSymbolAddress((void**)&wo2T,   g_Wo2T);
    cudaGetSymbolAddress((void**)&wcombT, g_WcombT);
    cudaGetSymbolAddress((void**)&wmT,    g_WmT);
    cudaGetSymbolAddress((void**)&wf1T,   g_Wf1T);

    cudaFuncSetAttribute(mma_gemm<false, false, false>,
                         cudaFuncAttributeMaxDynamicSharedMemorySize, SMEM_BYTES);
    cudaFuncSetAttribute(mma_gemm<true, true, false>,
                         cudaFuncAttributeMaxDynamicSharedMemorySize, SMEM_BYTES);
    cudaFuncSetAttribute(mma_gemm<true, true, true>,
                         cudaFuncAttributeMaxDynamicSharedMemorySize, SMEM_BYTES);
    cudaFuncSetAttribute(mma_gemm<true, false, true>,
                         cudaFuncAttributeMaxDynamicSharedMemorySize, SMEM_BYTES);

    // prep: pad A, build transposed weights
    pad_atoms_kernel<<<(N_ATOMS * KPAD_F + 255) / 256, 256>>>(f_atoms, padA);
    build_wcatT_kernel<<<(1024 * KPAD_F + 255) / 256, 256>>>(W_i, W_o, wcatT);
    build_wcombT_kernel<<<(4096 * HIDDEN + 255) / 256, 256>>>(W_fi, wcombT);
    dim3 tb(32, 8);
    transpose_pad_kernel<<<dim3(HIDDEN / 32, HIDDEN / 32), tb>>>(W_h, whT, HIDDEN, HIDDEN, HIDDEN);
    transpose_pad_kernel<<<dim3(HIDDEN / 32, HIDDEN / 32), tb>>>(W_o + ATOM_FDIM * HIDDEN, wo2T, HIDDEN, HIDDEN, HIDDEN);
    transpose_pad_kernel<<<dim3(FFN1 / 32, HIDDEN / 32), tb>>>(W_fi + (size_t)512 * FFN1, wmT, HIDDEN, FFN1, HIDDEN);
    transpose_pad_kernel<<<dim3(FFN2 / 32, FFN1 / 32), tb>>>(W_f1, wf1T, FFN1, FFN2, FFN1);

    const int MT = (N_ATOMS + BM - 1) / BM;  // 782

    // 1+5. [inp | ah_partial] = padA @ Wcat              -> g_cat [N,1024]
    mma_gemm<false, false, false><<<dim3(1024 / BN, MT), 256, SMEM_BYTES>>>(
        N_ATOMS, 1024, KPAD_F, KPAD_F, KPAD_F, 0, 1024, padA, wcatT, nullptr, nullptr, cat);
    // 2. bufB = sum_j relu(inp[nei])
    gather_sum_kernel<<<N_ATOMS, 128>>>(cat, 1024, a_nei, bufB, 1);
    // 3. msg2 = relu(inp + bufB @ W_h)                   -> bufC
    mma_gemm<true, true, false><<<dim3(HIDDEN / BN, MT), 256, SMEM_BYTES>>>(
        N_ATOMS, HIDDEN, HIDDEN, HIDDEN, HIDDEN, 1024, HIDDEN, bufB, whT, cat, nullptr, bufC);
    // 4. bufB = sum_j msg2[nei]
    gather_sum_kernel<<<N_ATOMS, 128>>>(bufC, HIDDEN, a_nei, bufB, 0);
    // 6. atom_hiddens = relu(ah_partial + bufB @ W_o_bot + b_o)  -> bufA
    mma_gemm<true, true, true><<<dim3(HIDDEN / BN, MT), 256, SMEM_BYTES>>>(
        N_ATOMS, HIDDEN, HIDDEN, HIDDEN, HIDDEN, 1024, HIDDEN, bufB, wo2T,
        cat + HIDDEN, b_o, bufA);
    // 7-8. segment mean
    zero_seg_kernel<<<(N_MOLS * HIDDEN + 255) / 256, 256>>>();
    seg_accum_kernel<<<N_ATOMS, 128>>>(bufA, mol_ids);
    mv_kernel<<<N_MOLS, 128>>>();
    // 9a. U = mv @ [(Ws+W1) | (Ws+W2)]                    -> g_U [M,4096]
    mma_gemm<false, false, false><<<dim3(4096 / BN, N_MOLS / BM), 256, SMEM_BYTES>>>(
        N_MOLS, 4096, HIDDEN, HIDDEN, HIDDEN, 0, 4096, mvp, wcombT, nullptr, nullptr, Up);
    // 9b. prod[p] = mv[a]*mv[b]                           -> bufC [P,512]
    prod_kernel<<<N_PAIRS, 128>>>(edges, bufC);
    // 9c. base[p] = U1[a] + U2[b] + b_fi                  -> bufB [P,2048]
    pair_base_kernel<<<N_PAIRS, 256>>>(edges, b_fi, bufB);
    // 10. h1 = relu(prod @ Wm + base)                     -> bufB
    mma_gemm<true, true, false><<<dim3(FFN1 / BN, N_PAIRS / BM), 256, SMEM_BYTES>>>(
        N_PAIRS, FFN1, HIDDEN, HIDDEN, HIDDEN, FFN1, FFN1, bufC, wmT, bufB, nullptr, bufB);
    // 11. h2 = relu(h1 @ W_ffn_1 + b_ffn_1)               -> g_h2
    mma_gemm<true, false, true><<<dim3(FFN2 / BN, N_PAIRS / BM), 256, SMEM_BYTES>>>(
        N_PAIRS, FFN2, FFN1, FFN1, FFN1, 0, FFN2, bufB, wf1T, nullptr, b_f1, h2p);
    // 12. out = sigmoid(h2 . W_ffn_2 + b_ffn_2)
    ffn_last_kernel<<<N_PAIRS, 128>>>(h2p, W_f2, b_f2, out);
}

// round 8
// speedup vs baseline: 5.9997x; 1.4910x over previous
#include <cuda_runtime.h>
#include <cuda_fp16.h>
#include <math.h>
#include <stdint.h>

#define N_ATOMS   100000
#define ATOM_FDIM 133
#define KPAD_F    160
#define HIDDEN    512
#define MAX_NEI   6
#define N_MOLS    4096
#define N_PAIRS   8192
#define FFN1      2048
#define FFN2      1024

// ---------------- scratch (device globals: allocation-free) ----------------
__device__ alignas(16) __half g_padAh [N_ATOMS * KPAD_F];
__device__ alignas(16) __half g_cath  [N_ATOMS * 1024];   // [inp | ah_partial]
__device__ alignas(16) __half g_bufBh [N_ATOMS * HIDDEN];
__device__ alignas(16) __half g_bufCh [N_ATOMS * HIDDEN];
__device__ alignas(16) __half g_h1h   [N_PAIRS * FFN1];
__device__ alignas(16) __half g_prodh [N_PAIRS * HIDDEN];
__device__ alignas(16) __half g_mvh   [N_MOLS * HIDDEN];
__device__ float g_bufA[N_ATOMS * HIDDEN];
__device__ float g_base[N_PAIRS * FFN1];
__device__ float g_h2  [N_PAIRS * FFN2];
__device__ float g_sums[N_MOLS * HIDDEN];
__device__ float g_cnt [N_MOLS];
__device__ float g_mv  [N_MOLS * HIDDEN];
__device__ float g_U   [N_MOLS * 4096];
// transposed half weights [N][K] (K-contiguous)
__device__ alignas(16) __half g_WcatTh [1024 * KPAD_F];
__device__ alignas(16) __half g_WhTh   [HIDDEN * HIDDEN];
__device__ alignas(16) __half g_Wo2Th  [HIDDEN * HIDDEN];
__device__ alignas(16) __half g_WcombTh[4096 * HIDDEN];
__device__ alignas(16) __half g_WmTh   [FFN1 * HIDDEN];
__device__ alignas(16) __half g_Wf1Th  [FFN2 * FFN1];

// ---------------- PTX helpers ----------------------------------------------
__device__ __forceinline__ uint32_t smem_u32(const void* p) {
    return (uint32_t)__cvta_generic_to_shared(p);
}
__device__ __forceinline__ void cp16(uint32_t s, const void* g, uint32_t bytes) {
    asm volatile("cp.async.cg.shared.global [%0], [%1], 16, %2;\n"
                 :: "r"(s), "l"(g), "r"(bytes));
}
__device__ __forceinline__ void cp_commit() {
    asm volatile("cp.async.commit_group;\n" ::: "memory");
}
template <int N>
__device__ __forceinline__ void cp_wait() {
    asm volatile("cp.async.wait_group %0;\n" :: "n"(N) : "memory");
}
__device__ __forceinline__ void ldsm4(uint32_t* r, uint32_t addr) {
    asm volatile("ldmatrix.sync.aligned.m8n8.x4.shared.b16 {%0,%1,%2,%3}, [%4];\n"
                 : "=r"(r[0]), "=r"(r[1]), "=r"(r[2]), "=r"(r[3]) : "r"(addr));
}
__device__ __forceinline__ void mma_f16(float* c, const uint32_t* a,
                                        uint32_t b0, uint32_t b1) {
    asm volatile(
        "mma.sync.aligned.m16n8k16.row.col.f32.f16.f16.f32 "
        "{%0,%1,%2,%3}, {%4,%5,%6,%7}, {%8,%9}, {%0,%1,%2,%3};\n"
        : "+f"(c[0]), "+f"(c[1]), "+f"(c[2]), "+f"(c[3])
        : "r"(a[0]), "r"(a[1]), "r"(a[2]), "r"(a[3]), "r"(b0), "r"(b1));
}

// ---------------- GEMM tile config ------------------------------------------
#define BM 128
#define BN 128
#define BK 32
#define STAGES 3
#define AT 40                                 // halves per smem row (pad 8)
#define A_H (BM * AT)                         // 5120 halves
#define STAGE_H (2 * A_H)                     // 10240 halves
#define STAGE_BYTES (STAGE_H * 2)             // 20480
#define SMEM_BYTES (STAGES * STAGE_BYTES)     // 61440

// ---------------- fp16 mma GEMM: C = A[MxK] @ BT[NxK]^T ---------------------
// A, BT half (K-contig); Cin fp32 or half per CINH; bias fp32; out per OUTH.
template <bool RELU, bool ADDC, bool CINH, bool BIAS, bool OUTH>
__global__ __launch_bounds__(256, 2)
void hgemm(int M, int N, int K, int lda, int ldb, int ldcin, int ldc,
           const __half* __restrict__ A, const __half* __restrict__ BT,
           const void* __restrict__ Cin, const float* __restrict__ bias,
           void* __restrict__ Cout)
{
    extern __shared__ __half sm[];
    const uint32_t sbase = smem_u32(sm);
    const int tid = threadIdx.x;
    const int lane = tid & 31, wid = tid >> 5;
    const int wm = wid & 3, wn = wid >> 2;     // warp grid 4 x 2
    const int gid = lane >> 2, tig = lane & 3;
    const int rowBase = blockIdx.y * BM;
    const int colBase = blockIdx.x * BN;
    const int nk = K / BK;

    // ---- hoisted gmem->smem addressing (tiles: 128 rows x 32 halves) ----
    const __half* aPtr[2]; uint32_t aSm[2]; uint32_t aBytes[2];
    const __half* bPtr[2]; uint32_t bSm[2];
#pragma unroll
    for (int j = 0; j < 2; j++) {
        int idx = tid + j * 256;
        int row = idx >> 2, c = idx & 3;       // c: 16B (8-half) chunk
        int grow = rowBase + row;
        int crow = grow < M ? grow : 0;
        aPtr[j]   = A + (size_t)crow * lda + c * 8;
        aSm[j]    = sbase + (uint32_t)(row * AT + c * 8) * 2;
        aBytes[j] = grow < M ? 16u : 0u;
        bPtr[j] = BT + (size_t)(colBase + row) * ldb + c * 8;
        bSm[j]  = sbase + (uint32_t)(A_H + row * AT + c * 8) * 2;
    }

    auto load_stage = [&](int stg, int kc0) {
        const uint32_t so = (uint32_t)stg * STAGE_BYTES;
#pragma unroll
        for (int j = 0; j < 2; j++)
            cp16(aSm[j] + so, aPtr[j] + kc0, aBytes[j]);
#pragma unroll
        for (int j = 0; j < 2; j++)
            cp16(bSm[j] + so, bPtr[j] + kc0, 16u);
        cp_commit();
    };

    // ---- hoisted ldmatrix addressing ----
    const int lr = lane & 15, lc = lane >> 4;
    uint32_t aLd[2], bLd[4];
#pragma unroll
    for (int mt = 0; mt < 2; mt++)
        aLd[mt] = sbase + (uint32_t)((wm * 32 + mt * 16 + lr) * AT + lc * 8) * 2;
#pragma unroll
    for (int j = 0; j < 4; j++)
        bLd[j] = sbase + (uint32_t)(A_H + (wn * 64 + j * 16 + lr) * AT + lc * 8) * 2;

    float acc[2][8][4];
#pragma unroll
    for (int mt = 0; mt < 2; mt++)
#pragma unroll
        for (int nt = 0; nt < 8; nt++)
#pragma unroll
            for (int i = 0; i < 4; i++) acc[mt][nt][i] = 0.f;

    load_stage(0, 0);
    if (nk > 1) load_stage(1, BK);

    int buf = 0;
    for (int kt = 0; kt < nk; kt++) {
        if (kt == nk - 1) cp_wait<0>(); else cp_wait<1>();
        __syncthreads();
        if (kt + 2 < nk)
            load_stage((buf + 2) % STAGES, (kt + 2) * BK);

        const uint32_t so = (uint32_t)buf * STAGE_BYTES;
#pragma unroll
        for (int ks = 0; ks < 2; ks++) {       // two k16 steps per BK=32
            const uint32_t ko = so + ks * 32;  // 16 halves = 32 bytes
            uint32_t af[2][4], bf[4][4];
            ldsm4(af[0], aLd[0] + ko);
            ldsm4(af[1], aLd[1] + ko);
#pragma unroll
            for (int j = 0; j < 4; j++)
                ldsm4(bf[j], bLd[j] + ko);
#pragma unroll
            for (int mt = 0; mt < 2; mt++)
#pragma unroll
                for (int j = 0; j < 4; j++) {
                    mma_f16(acc[mt][2 * j],     af[mt], bf[j][0], bf[j][2]);
                    mma_f16(acc[mt][2 * j + 1], af[mt], bf[j][1], bf[j][3]);
                }
        }
        buf = (buf + 1) % STAGES;
    }

    // ---- epilogue ----
#pragma unroll
    for (int mt = 0; mt < 2; mt++) {
        const int row0 = rowBase + wm * 32 + mt * 16 + gid;
        const int row1 = row0 + 8;
#pragma unroll
        for (int nt = 0; nt < 8; nt++) {
            const int gc = colBase + wn * 64 + nt * 8 + tig * 2;
            float2 v0 = make_float2(acc[mt][nt][0], acc[mt][nt][1]);
            float2 v1 = make_float2(acc[mt][nt][2], acc[mt][nt][3]);
            if (BIAS) {
                const float2 bb = *(const float2*)(bias + gc);
                v0.x += bb.x; v0.y += bb.y;
                v1.x += bb.x; v1.y += bb.y;
            }
#pragma unroll
            for (int h = 0; h < 2; h++) {
                const int row = h ? row1 : row0;
                float2 v = h ? v1 : v0;
                if (row >= M) continue;
                if (ADDC) {
                    float2 ci;
                    if (CINH) {
                        __half2 c2 = *(const __half2*)((const __half*)Cin + (size_t)row * ldcin + gc);
                        ci = __half22float2(c2);
                    } else {
                        ci = *(const float2*)((const float*)Cin + (size_t)row * ldcin + gc);
                    }
                    v.x += ci.x; v.y += ci.y;
                }
                if (RELU) { v.x = fmaxf(v.x, 0.f); v.y = fmaxf(v.y, 0.f); }
                if (OUTH)
                    *(__half2*)((__half*)Cout + (size_t)row * ldc + gc) = __floats2half2_rn(v.x, v.y);
                else
                    *(float2*)((float*)Cout + (size_t)row * ldc + gc) = v;
            }
        }
    }
}

// ---------------- prep kernels ----------------------------------------------
__global__ void pad_atoms_h_kernel(const float* __restrict__ f, __half* __restrict__ out) {
    int idx = blockIdx.x * blockDim.x + threadIdx.x;
    if (idx >= N_ATOMS * KPAD_F) return;
    int a = idx / KPAD_F, k = idx - a * KPAD_F;
    out[idx] = __float2half((k < ATOM_FDIM) ? f[a * ATOM_FDIM + k] : 0.f);
}

__global__ void transpose_pad_h_kernel(const float* __restrict__ W, __half* __restrict__ WT,
                                       int K, int N, int Kpad) {
    __shared__ float t[32][33];
    int kb = blockIdx.y * 32, nb = blockIdx.x * 32;
    int tx = threadIdx.x, ty = threadIdx.y;
#pragma unroll
    for (int i = 0; i < 4; i++) {
        int kk = kb + ty + i * 8;
        t[ty + i * 8][tx] = (kk < K) ? W[(size_t)kk * N + nb + tx] : 0.f;
    }
    __syncthreads();
#pragma unroll
    for (int i = 0; i < 4; i++) {
        int n = nb + ty + i * 8;
        WT[(size_t)n * Kpad + kb + tx] = __float2half(t[tx][ty + i * 8]);
    }
}

__global__ void build_wcatT_h_kernel(const float* __restrict__ Wi,
                                     const float* __restrict__ Wo,
                                     __half* __restrict__ out) {
    int idx = blockIdx.x * blockDim.x + threadIdx.x;
    if (idx >= 1024 * KPAD_F) return;
    int n = idx / KPAD_F, k = idx - n * KPAD_F;
    float v = 0.f;
    if (k < ATOM_FDIM)
        v = (n < HIDDEN) ? Wi[k * HIDDEN + n] : Wo[k * HIDDEN + (n - HIDDEN)];
    out[idx] = __float2half(v);
}

// WcombT[n][k]: n<2048 -> Wfi[k][n]+Wfi[1024+k][n]; else Wfi[k][n-2048]+Wfi[1536+k][n-2048]
__global__ void build_wcombT_h_kernel(const float* __restrict__ Wfi,
                                      __half* __restrict__ out) {
    int idx = blockIdx.x * blockDim.x + threadIdx.x;
    if (idx >= 4096 * HIDDEN) return;
    int n = idx / HIDDEN, k = idx - n * HIDDEN;
    float v;
    if (n < FFN1)
        v = Wfi[(size_t)k * FFN1 + n] + Wfi[(size_t)(1024 + k) * FFN1 + n];
    else {
        int n2 = n - FFN1;
        v = Wfi[(size_t)k * FFN1 + n2] + Wfi[(size_t)(1536 + k) * FFN1 + n2];
    }
    out[idx] = __float2half(v);
}

// ---------------- neighbor gather-sum (half in/out, fp32 accumulate) --------
__global__ void gather_sum_h_kernel(const __half* __restrict__ src, int srcStride,
                                    const int* __restrict__ nei,
                                    __half* __restrict__ dst, int relu_src)
{
    int atom = blockIdx.x;
    int c = threadIdx.x;  // 0..63, each 8 halves (16B)
    const int* nrow = nei + atom * MAX_NEI;
    float2 acc[4] = {{0.f,0.f},{0.f,0.f},{0.f,0.f},{0.f,0.f}};
#pragma unroll
    for (int j = 0; j < MAX_NEI; j++) {
        int n = __ldg(&nrow[j]);
        uint4 v = __ldg((const uint4*)(src + (size_t)n * srcStride) + c);
        uint32_t w[4] = {v.x, v.y, v.z, v.w};
#pragma unroll
        for (int i = 0; i < 4; i++) {
            float2 f = __half22float2(*(__half2*)&w[i]);
            if (relu_src) { f.x = fmaxf(f.x, 0.f); f.y = fmaxf(f.y, 0.f); }
            acc[i].x += f.x; acc[i].y += f.y;
        }
    }
    uint4 o;
    uint32_t* ow = (uint32_t*)&o;
#pragma unroll
    for (int i = 0; i < 4; i++) {
        __half2 h = __floats2half2_rn(acc[i].x, acc[i].y);
        ow[i] = *(uint32_t*)&h;
    }
    ((uint4*)(dst + (size_t)atom * HIDDEN))[c] = o;
}

// ---------------- segment mean pieces ---------------------------------------
__global__ void zero_seg_kernel() {
    int i = blockIdx.x * blockDim.x + threadIdx.x;
    if (i < N_MOLS * HIDDEN) g_sums[i] = 0.f;
    if (i < N_MOLS) g_cnt[i] = 0.f;
}

__global__ void seg_accum_kernel(const float* __restrict__ ah,
                                 const int* __restrict__ mol_ids)
{
    int atom = blockIdx.x;
    int mol  = __ldg(&mol_ids[atom]);
    int c    = threadIdx.x;
    float4 v = __ldg((const float4*)(ah + (size_t)atom * HIDDEN) + c);
    float* s = g_sums + (size_t)mol * HIDDEN + c * 4;
    atomicAdd(s + 0, v.x);
    atomicAdd(s + 1, v.y);
    atomicAdd(s + 2, v.z);
    atomicAdd(s + 3, v.w);
    if (c == 0) atomicAdd(&g_cnt[mol], 1.f);
}

// mv = sums / max(cnt,1) -> fp32 + half copies
__global__ void mv_kernel()
{
    int m = blockIdx.x;
    int c = threadIdx.x;  // 0..127
    float inv = 1.f / fmaxf(g_cnt[m], 1.f);
    float4 v = ((const float4*)(g_sums + (size_t)m * HIDDEN))[c];
    v.x *= inv; v.y *= inv; v.z *= inv; v.w *= inv;
    ((float4*)(g_mv + (size_t)m * HIDDEN))[c] = v;
    __half2 h0 = __floats2half2_rn(v.x, v.y);
    __half2 h1 = __floats2half2_rn(v.z, v.w);
    uint2 o = make_uint2(*(uint32_t*)&h0, *(uint32_t*)&h1);
    ((uint2*)(g_mvh + (size_t)m * HIDDEN))[c] = o;
}

// prod[p] = mv[a] * mv[b] (half out)
__global__ void prod_kernel(const int* __restrict__ edges)
{
    int p = blockIdx.x;
    int a = __ldg(&edges[p]);
    int b = __ldg(&edges[N_PAIRS + p]);
    int c = threadIdx.x;  // 0..127
    float4 va = __ldg((const float4*)(g_mv + (size_t)a * HIDDEN) + c);
    float4 vb = __ldg((const float4*)(g_mv + (size_t)b * HIDDEN) + c);
    __half2 h0 = __floats2half2_rn(va.x * vb.x, va.y * vb.y);
    __half2 h1 = __floats2half2_rn(va.z * vb.z, va.w * vb.w);
    uint2 o = make_uint2(*(uint32_t*)&h0, *(uint32_t*)&h1);
    ((uint2*)(g_prodh + (size_t)p * HIDDEN))[c] = o;
}

// base[p] = U1[a] + U2[b] + b_fi   [P, 2048] fp32
__global__ void pair_base_kernel(const int* __restrict__ edges,
                                 const float* __restrict__ bias)
{
    int p = blockIdx.x;
    int a = __ldg(&edges[p]);
    int b = __ldg(&edges[N_PAIRS + p]);
    const float4* u1 = (const float4*)(g_U + (size_t)a * 4096);
    const float4* u2 = (const float4*)(g_U + (size_t)b * 4096 + FFN1);
    const float4* bb = (const float4*)bias;
    float4* o = (float4*)(g_base + (size_t)p * FFN1);
#pragma unroll
    for (int i = 0; i < 2; i++) {
        int c = threadIdx.x + i * 256;
        float4 x = __ldg(u1 + c), y = __ldg(u2 + c), z = __ldg(bb + c);
        x.x += y.x + z.x; x.y += y.y + z.y; x.z += y.z + z.z; x.w += y.w + z.w;
        o[c] = x;
    }
}

// ---------------- final dot + sigmoid ---------------------------------------
__global__ void ffn_last_kernel(const float* __restrict__ h2,
                                const float* __restrict__ W,
                                const float* __restrict__ b,
                                float* __restrict__ out)
{
    int p = blockIdx.x;
    float s = 0.f;
    for (int i = threadIdx.x; i < FFN2; i += 128)
        s += h2[(size_t)p * FFN2 + i] * W[i];
#pragma unroll
    for (int off = 16; off; off >>= 1)
        s += __shfl_down_sync(0xffffffffu, s, off);
    __shared__ float red[4];
    if ((threadIdx.x & 31) == 0) red[threadIdx.x >> 5] = s;
    __syncthreads();
    if (threadIdx.x == 0) {
        float t = red[0] + red[1] + red[2] + red[3] + b[0];
        out[p] = 1.f / (1.f + expf(-t));
    }
}

// ---------------- launch ----------------------------------------------------
extern "C" void kernel_launch(void* const* d_in, const int* in_sizes, int n_in,
                              void* d_out, int out_size)
{
    const float* f_atoms = (const float*)d_in[0];
    const int*   a_nei   = (const int*)d_in[1];
    const int*   mol_ids = (const int*)d_in[2];
    const int*   edges   = (const int*)d_in[3];
    const float* W_i     = (const float*)d_in[4];
    const float* W_h     = (const float*)d_in[5];
    const float* W_o     = (const float*)d_in[6];
    const float* b_o     = (const float*)d_in[7];
    const float* W_fi    = (const float*)d_in[8];
    const float* b_fi    = (const float*)d_in[9];
    const float* W_f1    = (const float*)d_in[10];
    const float* b_f1    = (const float*)d_in[11];
    const float* W_f2    = (const float*)d_in[12];
    const float* b_f2    = (const float*)d_in[13];
    float* out = (float*)d_out;

    __half *padAh, *cath, *bufBh, *bufCh, *h1h, *prodh, *mvh;
    __half *wcatTh, *whTh, *wo2Th, *wcombTh, *wmTh, *wf1Th;
    float *bufA, *base, *h2p, *mvp, *Up;
    cudaGetSymbolAddress((void**)&padAh,   g_padAh);
    cudaGetSymbolAddress((void**)&cath,    g_cath);
    cudaGetSymbolAddress((void**)&bufBh,   g_bufBh);
    cudaGetSymbolAddress((void**)&bufCh,   g_bufCh);
    cudaGetSymbolAddress((void**)&h1h,     g_h1h);
    cudaGetSymbolAddress((void**)&prodh,   g_prodh);
    cudaGetSymbolAddress((void**)&mvh,     g_mvh);
    cudaGetSymbolAddress((void**)&wcatTh,  g_WcatTh);
    cudaGetSymbolAddress((void**)&whTh,    g_WhTh);
    cudaGetSymbolAddress((void**)&wo2Th,   g_Wo2Th);
    cudaGetSymbolAddress((void**)&wcombTh, g_WcombTh);
    cudaGetSymbolAddress((void**)&wmTh,    g_WmTh);
    cudaGetSymbolAddress((void**)&wf1Th,   g_Wf1Th);
    cudaGetSymbolAddress((void**)&bufA,    g_bufA);
    cudaGetSymbolAddress((void**)&base,    g_base);
    cudaGetSymbolAddress((void**)&h2p,     g_h2);
    cudaGetSymbolAddress((void**)&mvp,     g_mv);
    cudaGetSymbolAddress((void**)&Up,      g_U);

    cudaFuncSetAttribute(hgemm<false, false, false, false, true>,
                         cudaFuncAttributeMaxDynamicSharedMemorySize, SMEM_BYTES);
    cudaFuncSetAttribute(hgemm<true, true, true, false, true>,
                         cudaFuncAttributeMaxDynamicSharedMemorySize, SMEM_BYTES);
    cudaFuncSetAttribute(hgemm<true, true, true, true, false>,
                         cudaFuncAttributeMaxDynamicSharedMemorySize, SMEM_BYTES);
    cudaFuncSetAttribute(hgemm<false, false, false, false, false>,
                         cudaFuncAttributeMaxDynamicSharedMemorySize, SMEM_BYTES);
    cudaFuncSetAttribute(hgemm<true, true, false, false, true>,
                         cudaFuncAttributeMaxDynamicSharedMemorySize, SMEM_BYTES);
    cudaFuncSetAttribute(hgemm<true, false, false, true, false>,
                         cudaFuncAttributeMaxDynamicSharedMemorySize, SMEM_BYTES);

    // prep: pad + convert A, build transposed half weights
    pad_atoms_h_kernel<<<(N_ATOMS * KPAD_F + 255) / 256, 256>>>(f_atoms, padAh);
    build_wcatT_h_kernel<<<(1024 * KPAD_F + 255) / 256, 256>>>(W_i, W_o, wcatTh);
    build_wcombT_h_kernel<<<(4096 * HIDDEN + 255) / 256, 256>>>(W_fi, wcombTh);
    dim3 tb(32, 8);
    transpose_pad_h_kernel<<<dim3(HIDDEN / 32, HIDDEN / 32), tb>>>(W_h, whTh, HIDDEN, HIDDEN, HIDDEN);
    transpose_pad_h_kernel<<<dim3(HIDDEN / 32, HIDDEN / 32), tb>>>(W_o + ATOM_FDIM * HIDDEN, wo2Th, HIDDEN, HIDDEN, HIDDEN);
    transpose_pad_h_kernel<<<dim3(FFN1 / 32, HIDDEN / 32), tb>>>(W_fi + (size_t)512 * FFN1, wmTh, HIDDEN, FFN1, HIDDEN);
    transpose_pad_h_kernel<<<dim3(FFN2 / 32, FFN1 / 32), tb>>>(W_f1, wf1Th, FFN1, FFN2, FFN1);

    const int MT = (N_ATOMS + BM - 1) / BM;  // 782

    // 1+5. [inp | ah_partial] = padA @ Wcat              -> cath [N,1024] half
    hgemm<false, false, false, false, true><<<dim3(1024 / BN, MT), 256, SMEM_BYTES>>>(
        N_ATOMS, 1024, KPAD_F, KPAD_F, KPAD_F, 0, 1024, padAh, wcatTh, nullptr, nullptr, cath);
    // 2. bufBh = sum_j relu(inp[nei])
    gather_sum_h_kernel<<<N_ATOMS, 64>>>(cath, 1024, a_nei, bufBh, 1);
    // 3. msg2 = relu(inp + bufBh @ W_h)                  -> bufCh half
    hgemm<true, true, true, false, true><<<dim3(HIDDEN / BN, MT), 256, SMEM_BYTES>>>(
        N_ATOMS, HIDDEN, HIDDEN, HIDDEN, HIDDEN, 1024, HIDDEN, bufBh, whTh, cath, nullptr, bufCh);
    // 4. bufBh = sum_j msg2[nei]
    gather_sum_h_kernel<<<N_ATOMS, 64>>>(bufCh, HIDDEN, a_nei, bufBh, 0);
    // 6. atom_hiddens = relu(ah_partial + bufBh @ W_o_bot + b_o) -> bufA fp32
    hgemm<true, true, true, true, false><<<dim3(HIDDEN / BN, MT), 256, SMEM_BYTES>>>(
        N_ATOMS, HIDDEN, HIDDEN, HIDDEN, HIDDEN, 1024, HIDDEN, bufBh, wo2Th,
        cath + HIDDEN, b_o, bufA);
    // 7-8. segment mean
    zero_seg_kernel<<<(N_MOLS * HIDDEN + 255) / 256, 256>>>();
    seg_accum_kernel<<<N_ATOMS, 128>>>(bufA, mol_ids);
    mv_kernel<<<N_MOLS, 128>>>();
    // 9a. U = mv @ [(Ws+W1) | (Ws+W2)]                    -> g_U [M,4096] fp32
    hgemm<false, false, false, false, false><<<dim3(4096 / BN, N_MOLS / BM), 256, SMEM_BYTES>>>(
        N_MOLS, 4096, HIDDEN, HIDDEN, HIDDEN, 0, 4096, mvh, wcombTh, nullptr, nullptr, Up);
    // 9b. prod[p] = mv[a]*mv[b]                           -> prodh half
    prod_kernel<<<N_PAIRS, 128>>>(edges);
    // 9c. base[p] = U1[a] + U2[b] + b_fi                  -> g_base fp32
    pair_base_kernel<<<N_PAIRS, 256>>>(edges, b_fi);
    // 10. h1 = relu(prod @ Wm + base)                     -> h1h half
    hgemm<true, true, false, false, true><<<dim3(FFN1 / BN, N_PAIRS / BM), 256, SMEM_BYTES>>>(
        N_PAIRS, FFN1, HIDDEN, HIDDEN, HIDDEN, FFN1, FFN1, prodh, wmTh, base, nullptr, h1h);
    // 11. h2 = relu(h1 @ W_ffn_1 + b_ffn_1)               -> g_h2 fp32
    hgemm<true, false, false, true, false><<<dim3(FFN2 / BN, N_PAIRS / BM), 256, SMEM_BYTES>>>(
        N_PAIRS, FFN2, FFN1, FFN1, FFN1, 0, FFN2, h1h, wf1Th, nullptr, b_f1, h2p);
    // 12. out = sigmoid(h2 . W_ffn_2 + b_ffn_2)
    ffn_last_kernel<<<N_PAIRS, 128>>>(h2p, W_f2, b_f2, out);
}

// round 9
// speedup vs baseline: 6.5211x; 1.0869x over previous
#include <cuda_runtime.h>
#include <cuda_fp16.h>
#include <math.h>
#include <stdint.h>

#define N_ATOMS   100000
#define ATOM_FDIM 133
#define KPAD_F    160
#define HIDDEN    512
#define MAX_NEI   6
#define N_MOLS    4096
#define N_PAIRS   8192
#define FFN1      2048
#define FFN2      1024

#define MODE_N    0
#define MODE_SEG  1
#define MODE_PAIR 2

// ---------------- scratch (device globals: allocation-free) ----------------
__device__ alignas(16) __half g_padAh [N_ATOMS * KPAD_F];
__device__ alignas(16) __half g_cath  [N_ATOMS * 1024];   // [inp | ah_partial]
__device__ alignas(16) __half g_bufBh [N_ATOMS * HIDDEN];
__device__ alignas(16) __half g_bufCh [N_ATOMS * HIDDEN];
__device__ alignas(16) __half g_h1h   [N_PAIRS * FFN1];
__device__ alignas(16) __half g_prodh [N_PAIRS * HIDDEN];
__device__ alignas(16) __half g_mvh   [N_MOLS * HIDDEN];
__device__ float g_h2  [N_PAIRS * FFN2];
__device__ float g_sums[N_MOLS * HIDDEN];
__device__ float g_cnt [N_MOLS];
__device__ float g_mv  [N_MOLS * HIDDEN];
__device__ float g_U   [N_MOLS * 4096];
// transposed half weights [N][K] (K-contiguous)
__device__ alignas(16) __half g_WcatTh [1024 * KPAD_F];
__device__ alignas(16) __half g_WhTh   [HIDDEN * HIDDEN];
__device__ alignas(16) __half g_Wo2Th  [HIDDEN * HIDDEN];
__device__ alignas(16) __half g_WcombTh[4096 * HIDDEN];
__device__ alignas(16) __half g_WmTh   [FFN1 * HIDDEN];
__device__ alignas(16) __half g_Wf1Th  [FFN2 * FFN1];

// ---------------- PTX helpers ----------------------------------------------
__device__ __forceinline__ uint32_t smem_u32(const void* p) {
    return (uint32_t)__cvta_generic_to_shared(p);
}
__device__ __forceinline__ void cp16(uint32_t s, const void* g, uint32_t bytes) {
    asm volatile("cp.async.cg.shared.global [%0], [%1], 16, %2;\n"
                 :: "r"(s), "l"(g), "r"(bytes));
}
__device__ __forceinline__ void cp_commit() {
    asm volatile("cp.async.commit_group;\n" ::: "memory");
}
template <int N>
__device__ __forceinline__ void cp_wait() {
    asm volatile("cp.async.wait_group %0;\n" :: "n"(N) : "memory");
}
__device__ __forceinline__ void ldsm4(uint32_t* r, uint32_t addr) {
    asm volatile("ldmatrix.sync.aligned.m8n8.x4.shared.b16 {%0,%1,%2,%3}, [%4];\n"
                 : "=r"(r[0]), "=r"(r[1]), "=r"(r[2]), "=r"(r[3]) : "r"(addr));
}
__device__ __forceinline__ void mma_f16(float* c, const uint32_t* a,
                                        uint32_t b0, uint32_t b1) {
    asm volatile(
        "mma.sync.aligned.m16n8k16.row.col.f32.f16.f16.f32 "
        "{%0,%1,%2,%3}, {%4,%5,%6,%7}, {%8,%9}, {%0,%1,%2,%3};\n"
        : "+f"(c[0]), "+f"(c[1]), "+f"(c[2]), "+f"(c[3])
        : "r"(a[0]), "r"(a[1]), "r"(a[2]), "r"(a[3]), "r"(b0), "r"(b1));
}

// ---------------- GEMM tile config ------------------------------------------
#define BM 128
#define BN 128
#define BK 32
#define STAGES 4
#define AT 40                                 // halves per smem row (pad 8)
#define A_H (BM * AT)                         // 5120 halves
#define STAGE_H (2 * A_H)
#define STAGE_BYTES (STAGE_H * 2)             // 20480
#define SMEM_BYTES (STAGES * STAGE_BYTES)     // 81920

// ---------------- fp16 mma GEMM: C = A[MxK] @ BT[NxK]^T ---------------------
// MODE_N: normal store. MODE_SEG: atomicAdd rows into sums[mol_ids[row]].
// MODE_PAIR: add U1[e0[row]] + U2[e1[row]] then store.
template <int MODE, bool RELU, bool ADDC, bool CINH, bool BIAS, bool OUTH>
__global__ __launch_bounds__(256, 2)
void hgemm(int M, int N, int K, int lda, int ldb, int ldcin, int ldc,
           const __half* __restrict__ A, const __half* __restrict__ BT,
           const void* __restrict__ Cin, const float* __restrict__ bias,
           void* __restrict__ Cout,
           const int* __restrict__ idx, const float* __restrict__ U,
           float* __restrict__ sums)
{
    extern __shared__ __half sm[];
    const uint32_t sbase = smem_u32(sm);
    const int tid = threadIdx.x;
    const int lane = tid & 31, wid = tid >> 5;
    const int wm = wid & 3, wn = wid >> 2;     // warp grid 4 x 2
    const int gid = lane >> 2, tig = lane & 3;
    const int rowBase = blockIdx.y * BM;
    const int colBase = blockIdx.x * BN;
    const int nk = K / BK;

    const __half* aPtr[2]; uint32_t aSm[2]; uint32_t aBytes[2];
    const __half* bPtr[2]; uint32_t bSm[2];
#pragma unroll
    for (int j = 0; j < 2; j++) {
        int idx2 = tid + j * 256;
        int row = idx2 >> 2, c = idx2 & 3;
        int grow = rowBase + row;
        int crow = grow < M ? grow : 0;
        aPtr[j]   = A + (size_t)crow * lda + c * 8;
        aSm[j]    = sbase + (uint32_t)(row * AT + c * 8) * 2;
        aBytes[j] = grow < M ? 16u : 0u;
        bPtr[j] = BT + (size_t)(colBase + row) * ldb + c * 8;
        bSm[j]  = sbase + (uint32_t)(A_H + row * AT + c * 8) * 2;
    }

    auto load_stage = [&](int stg, int kc0) {
        const uint32_t so = (uint32_t)stg * STAGE_BYTES;
#pragma unroll
        for (int j = 0; j < 2; j++)
            cp16(aSm[j] + so, aPtr[j] + kc0, aBytes[j]);
#pragma unroll
        for (int j = 0; j < 2; j++)
            cp16(bSm[j] + so, bPtr[j] + kc0, 16u);
        cp_commit();
    };

    const int lr = lane & 15, lc = lane >> 4;
    uint32_t aLd[2], bLd[4];
#pragma unroll
    for (int mt = 0; mt < 2; mt++)
        aLd[mt] = sbase + (uint32_t)((wm * 32 + mt * 16 + lr) * AT + lc * 8) * 2;
#pragma unroll
    for (int j = 0; j < 4; j++)
        bLd[j] = sbase + (uint32_t)(A_H + (wn * 64 + j * 16 + lr) * AT + lc * 8) * 2;

    float acc[2][8][4];
#pragma unroll
    for (int mt = 0; mt < 2; mt++)
#pragma unroll
        for (int nt = 0; nt < 8; nt++)
#pragma unroll
            for (int i = 0; i < 4; i++) acc[mt][nt][i] = 0.f;

    load_stage(0, 0);
    if (nk > 1) load_stage(1, BK);
    if (nk > 2) load_stage(2, 2 * BK);

    int buf = 0;
    for (int kt = 0; kt < nk; kt++) {
        if (kt == nk - 1)      cp_wait<0>();
        else if (kt == nk - 2) cp_wait<1>();
        else                   cp_wait<2>();
        __syncthreads();
        if (kt + 3 < nk)
            load_stage((buf + 3) % STAGES, (kt + 3) * BK);

        const uint32_t so = (uint32_t)buf * STAGE_BYTES;
#pragma unroll
        for (int ks = 0; ks < 2; ks++) {
            const uint32_t ko = so + ks * 32;
            uint32_t af[2][4], bf[4][4];
            ldsm4(af[0], aLd[0] + ko);
            ldsm4(af[1], aLd[1] + ko);
#pragma unroll
            for (int j = 0; j < 4; j++)
                ldsm4(bf[j], bLd[j] + ko);
#pragma unroll
            for (int mt = 0; mt < 2; mt++)
#pragma unroll
                for (int j = 0; j < 4; j++) {
                    mma_f16(acc[mt][2 * j],     af[mt], bf[j][0], bf[j][2]);
                    mma_f16(acc[mt][2 * j + 1], af[mt], bf[j][1], bf[j][3]);
                }
        }
        buf = (buf + 1) % STAGES;
    }

    // ---- epilogue (row-major order: per row, then columns) ----
#pragma unroll
    for (int mt = 0; mt < 2; mt++) {
#pragma unroll
        for (int h = 0; h < 2; h++) {
            const int row = rowBase + wm * 32 + mt * 16 + gid + h * 8;
            if (row >= M) continue;
            int mol = 0, e0 = 0, e1 = 0;
            if (MODE == MODE_SEG)  mol = __ldg(&idx[row]);
            if (MODE == MODE_PAIR) { e0 = __ldg(&idx[row]); e1 = __ldg(&idx[N_PAIRS + row]); }
#pragma unroll
            for (int nt = 0; nt < 8; nt++) {
                const int gc = colBase + wn * 64 + nt * 8 + tig * 2;
                float2 v = make_float2(acc[mt][nt][2 * h], acc[mt][nt][2 * h + 1]);
                if (BIAS) {
                    const float2 bb = *(const float2*)(bias + gc);
                    v.x += bb.x; v.y += bb.y;
                }
                if (ADDC) {
                    float2 ci;
                    if (CINH) {
                        __half2 c2 = *(const __half2*)((const __half*)Cin + (size_t)row * ldcin + gc);
                        ci = __half22float2(c2);
                    } else {
                        ci = *(const float2*)((const float*)Cin + (size_t)row * ldcin + gc);
                    }
                    v.x += ci.x; v.y += ci.y;
                }
                if (MODE == MODE_PAIR) {
                    const float2 u1 = *(const float2*)(U + (size_t)e0 * 4096 + gc);
                    const float2 u2 = *(const float2*)(U + (size_t)e1 * 4096 + FFN1 + gc);
                    v.x += u1.x + u2.x; v.y += u1.y + u2.y;
                }
                if (RELU) { v.x = fmaxf(v.x, 0.f); v.y = fmaxf(v.y, 0.f); }
                if (MODE == MODE_SEG) {
                    float* s = sums + (size_t)mol * HIDDEN + gc;
                    atomicAdd(s,     v.x);
                    atomicAdd(s + 1, v.y);
                } else if (OUTH) {
                    *(__half2*)((__half*)Cout + (size_t)row * ldc + gc) = __floats2half2_rn(v.x, v.y);
                } else {
                    *(float2*)((float*)Cout + (size_t)row * ldc + gc) = v;
                }
            }
        }
    }
}

// ---------------- prep kernels ----------------------------------------------
__global__ void pad_atoms_h_kernel(const float* __restrict__ f, __half* __restrict__ out) {
    int idx = blockIdx.x * blockDim.x + threadIdx.x;
    if (idx >= N_ATOMS * KPAD_F) return;
    int a = idx / KPAD_F, k = idx - a * KPAD_F;
    out[idx] = __float2half((k < ATOM_FDIM) ? f[a * ATOM_FDIM + k] : 0.f);
}

__global__ void transpose_pad_h_kernel(const float* __restrict__ W, __half* __restrict__ WT,
                                       int K, int N, int Kpad) {
    __shared__ float t[32][33];
    int kb = blockIdx.y * 32, nb = blockIdx.x * 32;
    int tx = threadIdx.x, ty = threadIdx.y;
#pragma unroll
    for (int i = 0; i < 4; i++) {
        int kk = kb + ty + i * 8;
        t[ty + i * 8][tx] = (kk < K) ? W[(size_t)kk * N + nb + tx] : 0.f;
    }
    __syncthreads();
#pragma unroll
    for (int i = 0; i < 4; i++) {
        int n = nb + ty + i * 8;
        WT[(size_t)n * Kpad + kb + tx] = __float2half(t[tx][ty + i * 8]);
    }
}

__global__ void build_wcatT_h_kernel(const float* __restrict__ Wi,
                                     const float* __restrict__ Wo,
                                     __half* __restrict__ out) {
    int idx = blockIdx.x * blockDim.x + threadIdx.x;
    if (idx >= 1024 * KPAD_F) return;
    int n = idx / KPAD_F, k = idx - n * KPAD_F;
    float v = 0.f;
    if (k < ATOM_FDIM)
        v = (n < HIDDEN) ? Wi[k * HIDDEN + n] : Wo[k * HIDDEN + (n - HIDDEN)];
    out[idx] = __float2half(v);
}

__global__ void build_wcombT_h_kernel(const float* __restrict__ Wfi,
                                      __half* __restrict__ out) {
    int idx = blockIdx.x * blockDim.x + threadIdx.x;
    if (idx >= 4096 * HIDDEN) return;
    int n = idx / HIDDEN, k = idx - n * HIDDEN;
    float v;
    if (n < FFN1)
        v = Wfi[(size_t)k * FFN1 + n] + Wfi[(size_t)(1024 + k) * FFN1 + n];
    else {
        int n2 = n - FFN1;
        v = Wfi[(size_t)k * FFN1 + n2] + Wfi[(size_t)(1536 + k) * FFN1 + n2];
    }
    out[idx] = __float2half(v);
}

// ---------------- neighbor gather-sum (half) --------------------------------
__global__ void gather_sum_h_kernel(const __half* __restrict__ src, int srcStride,
                                    const int* __restrict__ nei,
                                    __half* __restrict__ dst, int relu_src)
{
    int atom = blockIdx.x;
    int c = threadIdx.x;  // 0..63
    const int* nrow = nei + atom * MAX_NEI;
    float2 acc[4] = {{0.f,0.f},{0.f,0.f},{0.f,0.f},{0.f,0.f}};
#pragma unroll
    for (int j = 0; j < MAX_NEI; j++) {
        int n = __ldg(&nrow[j]);
        uint4 v = __ldg((const uint4*)(src + (size_t)n * srcStride) + c);
        uint32_t w[4] = {v.x, v.y, v.z, v.w};
#pragma unroll
        for (int i = 0; i < 4; i++) {
            float2 f = __half22float2(*(__half2*)&w[i]);
            if (relu_src) { f.x = fmaxf(f.x, 0.f); f.y = fmaxf(f.y, 0.f); }
            acc[i].x += f.x; acc[i].y += f.y;
        }
    }
    uint4 o;
    uint32_t* ow = (uint32_t*)&o;
#pragma unroll
    for (int i = 0; i < 4; i++) {
        __half2 h = __floats2half2_rn(acc[i].x, acc[i].y);
        ow[i] = *(uint32_t*)&h;
    }
    ((uint4*)(dst + (size_t)atom * HIDDEN))[c] = o;
}

// ---------------- segment mean pieces ---------------------------------------
__global__ void zero_seg_kernel() {
    int i = blockIdx.x * blockDim.x + threadIdx.x;
    if (i < N_MOLS * HIDDEN) g_sums[i] = 0.f;
    if (i < N_MOLS) g_cnt[i] = 0.f;
}

__global__ void count_kernel(const int* __restrict__ mol_ids) {
    int i = blockIdx.x * blockDim.x + threadIdx.x;
    if (i < N_ATOMS) atomicAdd(&g_cnt[__ldg(&mol_ids[i])], 1.f);
}

// mv = sums / max(cnt,1) -> fp32 + half
__global__ void mv_kernel()
{
    int m = blockIdx.x;
    int c = threadIdx.x;
    float inv = 1.f / fmaxf(g_cnt[m], 1.f);
    float4 v = ((const float4*)(g_sums + (size_t)m * HIDDEN))[c];
    v.x *= inv; v.y *= inv; v.z *= inv; v.w *= inv;
    ((float4*)(g_mv + (size_t)m * HIDDEN))[c] = v;
    __half2 h0 = __floats2half2_rn(v.x, v.y);
    __half2 h1 = __floats2half2_rn(v.z, v.w);
    uint2 o = make_uint2(*(uint32_t*)&h0, *(uint32_t*)&h1);
    ((uint2*)(g_mvh + (size_t)m * HIDDEN))[c] = o;
}

// prod[p] = mv[a] * mv[b] (half out)
__global__ void prod_kernel(const int* __restrict__ edges)
{
    int p = blockIdx.x;
    int a = __ldg(&edges[p]);
    int b = __ldg(&edges[N_PAIRS + p]);
    int c = threadIdx.x;
    float4 va = __ldg((const float4*)(g_mv + (size_t)a * HIDDEN) + c);
    float4 vb = __ldg((const float4*)(g_mv + (size_t)b * HIDDEN) + c);
    __half2 h0 = __floats2half2_rn(va.x * vb.x, va.y * vb.y);
    __half2 h1 = __floats2half2_rn(va.z * vb.z, va.w * vb.w);
    uint2 o = make_uint2(*(uint32_t*)&h0, *(uint32_t*)&h1);
    ((uint2*)(g_prodh + (size_t)p * HIDDEN))[c] = o;
}

// ---------------- final dot + sigmoid ---------------------------------------
__global__ void ffn_last_kernel(const float* __restrict__ h2,
                                const float* __restrict__ W,
                                const float* __restrict__ b,
                                float* __restrict__ out)
{
    int p = blockIdx.x;
    float s = 0.f;
    for (int i = threadIdx.x; i < FFN2; i += 128)
        s += h2[(size_t)p * FFN2 + i] * W[i];
#pragma unroll
    for (int off = 16; off; off >>= 1)
        s += __shfl_down_sync(0xffffffffu, s, off);
    __shared__ float red[4];
    if ((threadIdx.x & 31) == 0) red[threadIdx.x >> 5] = s;
    __syncthreads();
    if (threadIdx.x == 0) {
        float t = red[0] + red[1] + red[2] + red[3] + b[0];
        out[p] = 1.f / (1.f + expf(-t));
    }
}

// ---------------- launch ----------------------------------------------------
extern "C" void kernel_launch(void* const* d_in, const int* in_sizes, int n_in,
                              void* d_out, int out_size)
{
    const float* f_atoms = (const float*)d_in[0];
    const int*   a_nei   = (const int*)d_in[1];
    const int*   mol_ids = (const int*)d_in[2];
    const int*   edges   = (const int*)d_in[3];
    const float* W_i     = (const float*)d_in[4];
    const float* W_h     = (const float*)d_in[5];
    const float* W_o     = (const float*)d_in[6];
    const float* b_o     = (const float*)d_in[7];
    const float* W_fi    = (const float*)d_in[8];
    const float* b_fi    = (const float*)d_in[9];
    const float* W_f1    = (const float*)d_in[10];
    const float* b_f1    = (const float*)d_in[11];
    const float* W_f2    = (const float*)d_in[12];
    const float* b_f2    = (const float*)d_in[13];
    float* out = (float*)d_out;

    __half *padAh, *cath, *bufBh, *bufCh, *h1h, *prodh, *mvh;
    __half *wcatTh, *whTh, *wo2Th, *wcombTh, *wmTh, *wf1Th;
    float *h2p, *Up, *sums;
    cudaGetSymbolAddress((void**)&padAh,   g_padAh);
    cudaGetSymbolAddress((void**)&cath,    g_cath);
    cudaGetSymbolAddress((void**)&bufBh,   g_bufBh);
    cudaGetSymbolAddress((void**)&bufCh,   g_bufCh);
    cudaGetSymbolAddress((void**)&h1h,     g_h1h);
    cudaGetSymbolAddress((void**)&prodh,   g_prodh);
    cudaGetSymbolAddress((void**)&mvh,     g_mvh);
    cudaGetSymbolAddress((void**)&wcatTh,  g_WcatTh);
    cudaGetSymbolAddress((void**)&whTh,    g_WhTh);
    cudaGetSymbolAddress((void**)&wo2Th,   g_Wo2Th);
    cudaGetSymbolAddress((void**)&wcombTh, g_WcombTh);
    cudaGetSymbolAddress((void**)&wmTh,    g_WmTh);
    cudaGetSymbolAddress((void**)&wf1Th,   g_Wf1Th);
    cudaGetSymbolAddress((void**)&h2p,     g_h2);
    cudaGetSymbolAddress((void**)&Up,      g_U);
    cudaGetSymbolAddress((void**)&sums,    g_sums);

    cudaFuncSetAttribute(hgemm<MODE_N, false, false, false, false, true>,
                         cudaFuncAttributeMaxDynamicSharedMemorySize, SMEM_BYTES);
    cudaFuncSetAttribute(hgemm<MODE_N, true, true, true, false, true>,
                         cudaFuncAttributeMaxDynamicSharedMemorySize, SMEM_BYTES);
    cudaFuncSetAttribute(hgemm<MODE_SEG, true, true, true, true, false>,
                         cudaFuncAttributeMaxDynamicSharedMemorySize, SMEM_BYTES);
    cudaFuncSetAttribute(hgemm<MODE_N, false, false, false, false, false>,
                         cudaFuncAttributeMaxDynamicSharedMemorySize, SMEM_BYTES);
    cudaFuncSetAttribute(hgemm<MODE_PAIR, true, false, false, true, true>,
                         cudaFuncAttributeMaxDynamicSharedMemorySize, SMEM_BYTES);
    cudaFuncSetAttribute(hgemm<MODE_N, true, false, false, true, false>,
                         cudaFuncAttributeMaxDynamicSharedMemorySize, SMEM_BYTES);

    // prep
    pad_atoms_h_kernel<<<(N_ATOMS * KPAD_F + 255) / 256, 256>>>(f_atoms, padAh);
    build_wcatT_h_kernel<<<(1024 * KPAD_F + 255) / 256, 256>>>(W_i, W_o, wcatTh);
    build_wcombT_h_kernel<<<(4096 * HIDDEN + 255) / 256, 256>>>(W_fi, wcombTh);
    dim3 tb(32, 8);
    transpose_pad_h_kernel<<<dim3(HIDDEN / 32, HIDDEN / 32), tb>>>(W_h, whTh, HIDDEN, HIDDEN, HIDDEN);
    transpose_pad_h_kernel<<<dim3(HIDDEN / 32, HIDDEN / 32), tb>>>(W_o + ATOM_FDIM * HIDDEN, wo2Th, HIDDEN, HIDDEN, HIDDEN);
    transpose_pad_h_kernel<<<dim3(FFN1 / 32, HIDDEN / 32), tb>>>(W_fi + (size_t)512 * FFN1, wmTh, HIDDEN, FFN1, HIDDEN);
    transpose_pad_h_kernel<<<dim3(FFN2 / 32, FFN1 / 32), tb>>>(W_f1, wf1Th, FFN1, FFN2, FFN1);
    zero_seg_kernel<<<(N_MOLS * HIDDEN + 255) / 256, 256>>>();
    count_kernel<<<(N_ATOMS + 255) / 256, 256>>>(mol_ids);

    const int MT = (N_ATOMS + BM - 1) / BM;  // 782

    // 1+5. [inp | ah_partial] = padA @ Wcat              -> cath [N,1024] half
    hgemm<MODE_N, false, false, false, false, true><<<dim3(1024 / BN, MT), 256, SMEM_BYTES>>>(
        N_ATOMS, 1024, KPAD_F, KPAD_F, KPAD_F, 0, 1024, padAh, wcatTh,
        nullptr, nullptr, cath, nullptr, nullptr, nullptr);
    // 2. bufBh = sum_j relu(inp[nei])
    gather_sum_h_kernel<<<N_ATOMS, 64>>>(cath, 1024, a_nei, bufBh, 1);
    // 3. msg2 = relu(inp + bufBh @ W_h)                  -> bufCh half
    hgemm<MODE_N, true, true, true, false, true><<<dim3(HIDDEN / BN, MT), 256, SMEM_BYTES>>>(
        N_ATOMS, HIDDEN, HIDDEN, HIDDEN, HIDDEN, 1024, HIDDEN, bufBh, whTh,
        cath, nullptr, bufCh, nullptr, nullptr, nullptr);
    // 4. bufBh = sum_j msg2[nei]
    gather_sum_h_kernel<<<N_ATOMS, 64>>>(bufCh, HIDDEN, a_nei, bufBh, 0);
    // 6. fused: atom_hiddens = relu(ah_partial + bufBh @ W_o_bot + b_o),
    //    atomically accumulated into g_sums[mol_ids[row]]
    hgemm<MODE_SEG, true, true, true, true, false><<<dim3(HIDDEN / BN, MT), 256, SMEM_BYTES>>>(
        N_ATOMS, HIDDEN, HIDDEN, HIDDEN, HIDDEN, 1024, HIDDEN, bufBh, wo2Th,
        cath + HIDDEN, b_o, nullptr, mol_ids, nullptr, sums);
    // 8. mv = sums / counts (fp32 + half)
    mv_kernel<<<N_MOLS, 128>>>();
    // 9a. U = mv @ [(Ws+W1) | (Ws+W2)]                    -> g_U [M,4096] fp32
    hgemm<MODE_N, false, false, false, false, false><<<dim3(4096 / BN, N_MOLS / BM), 256, SMEM_BYTES>>>(
        N_MOLS, 4096, HIDDEN, HIDDEN, HIDDEN, 0, 4096, mvh, wcombTh,
        nullptr, nullptr, Up, nullptr, nullptr, nullptr);
    // 9b. prod[p] = mv[a]*mv[b]                           -> prodh half
    prod_kernel<<<N_PAIRS, 128>>>(edges);
    // 10. fused: h1 = relu(prod @ Wm + U1[a] + U2[b] + b_fi) -> h1h half
    hgemm<MODE_PAIR, true, false, false, true, true><<<dim3(FFN1 / BN, N_PAIRS / BM), 256, SMEM_BYTES>>>(
        N_PAIRS, FFN1, HIDDEN, HIDDEN, HIDDEN, FFN1, FFN1, prodh, wmTh,
        nullptr, b_fi, h1h, edges, Up, nullptr);
    // 11. h2 = relu(h1 @ W_ffn_1 + b_ffn_1)               -> g_h2 fp32
    hgemm<MODE_N, true, false, false, true, false><<<dim3(FFN2 / BN, N_PAIRS / BM), 256, SMEM_BYTES>>>(
        N_PAIRS, FFN2, FFN1, FFN1, FFN1, 0, FFN2, h1h, wf1Th,
        nullptr, b_f1, h2p, nullptr, nullptr, nullptr);
    // 12. out = sigmoid(h2 . W_ffn_2 + b_ffn_2)
    ffn_last_kernel<<<N_PAIRS, 128>>>(h2p, W_f2, b_f2, out);
}

// round 10
// speedup vs baseline: 6.5598x; 1.0059x over previous
#include <cuda_runtime.h>
#include <cuda_fp16.h>
#include <math.h>
#include <stdint.h>

#define N_ATOMS   100000
#define ATOM_FDIM 133
#define KPAD_F    160
#define HIDDEN    512
#define MAX_NEI   6
#define N_MOLS    4096
#define N_PAIRS   8192
#define FFN1      2048
#define FFN2      1024

#define MODE_N    0
#define MODE_SEG  1
#define MODE_PAIR 2

// ---------------- scratch (device globals: allocation-free) ----------------
__device__ alignas(16) __half g_padAh [N_ATOMS * KPAD_F];
__device__ alignas(16) __half g_cath  [N_ATOMS * 1024];   // [inp | ah_partial]
__device__ alignas(16) __half g_bufBh [N_ATOMS * HIDDEN];
__device__ alignas(16) __half g_bufCh [N_ATOMS * HIDDEN];
__device__ alignas(16) __half g_h1h   [N_PAIRS * FFN1];
__device__ alignas(16) __half g_prodh [N_PAIRS * HIDDEN];
__device__ alignas(16) __half g_mvh   [N_MOLS * HIDDEN];
__device__ float g_h2  [N_PAIRS * FFN2];
__device__ float g_sums[N_MOLS * HIDDEN];
__device__ float g_cnt [N_MOLS];
__device__ float g_U   [N_MOLS * 4096];
// transposed half weights [N][K] (K-contiguous)
__device__ alignas(16) __half g_WcatTh [1024 * KPAD_F];
__device__ alignas(16) __half g_WhTh   [HIDDEN * HIDDEN];
__device__ alignas(16) __half g_Wo2Th  [HIDDEN * HIDDEN];
__device__ alignas(16) __half g_WcombTh[4096 * HIDDEN];
__device__ alignas(16) __half g_WmTh   [FFN1 * HIDDEN];
__device__ alignas(16) __half g_Wf1Th  [FFN2 * FFN1];

// ---------------- PTX helpers ----------------------------------------------
__device__ __forceinline__ uint32_t smem_u32(const void* p) {
    return (uint32_t)__cvta_generic_to_shared(p);
}
__device__ __forceinline__ void cp16(uint32_t s, const void* g, uint32_t bytes) {
    asm volatile("cp.async.cg.shared.global [%0], [%1], 16, %2;\n"
                 :: "r"(s), "l"(g), "r"(bytes));
}
__device__ __forceinline__ void cp_commit() {
    asm volatile("cp.async.commit_group;\n" ::: "memory");
}
template <int N>
__device__ __forceinline__ void cp_wait() {
    asm volatile("cp.async.wait_group %0;\n" :: "n"(N) : "memory");
}
__device__ __forceinline__ void ldsm4(uint32_t* r, uint32_t addr) {
    asm volatile("ldmatrix.sync.aligned.m8n8.x4.shared.b16 {%0,%1,%2,%3}, [%4];\n"
                 : "=r"(r[0]), "=r"(r[1]), "=r"(r[2]), "=r"(r[3]) : "r"(addr));
}
__device__ __forceinline__ void mma_f16(float* c, const uint32_t* a,
                                        uint32_t b0, uint32_t b1) {
    asm volatile(
        "mma.sync.aligned.m16n8k16.row.col.f32.f16.f16.f32 "
        "{%0,%1,%2,%3}, {%4,%5,%6,%7}, {%8,%9}, {%0,%1,%2,%3};\n"
        : "+f"(c[0]), "+f"(c[1]), "+f"(c[2]), "+f"(c[3])
        : "r"(a[0]), "r"(a[1]), "r"(a[2]), "r"(a[3]), "r"(b0), "r"(b1));
}

// ---------------- GEMM tile config ------------------------------------------
#define BM 128
#define BN 128
#define BK 32
#define STAGES 4
#define AT 40                                 // halves per smem row (pad 8)
#define A_H (BM * AT)                         // 5120 halves
#define STAGE_H (2 * A_H)
#define STAGE_BYTES (STAGE_H * 2)             // 20480
#define SMEM_BYTES (STAGES * STAGE_BYTES)     // 81920

// ---------------- fp16 mma GEMM: C = A[MxK] @ BT[NxK]^T ---------------------
template <int MODE, bool RELU, bool ADDC, bool CINH, bool BIAS, bool OUTH>
__global__ __launch_bounds__(256, 2)
void hgemm(int M, int N, int K, int lda, int ldb, int ldcin, int ldc,
           const __half* __restrict__ A, const __half* __restrict__ BT,
           const void* __restrict__ Cin, const float* __restrict__ bias,
           void* __restrict__ Cout,
           const int* __restrict__ idx, const float* __restrict__ U,
           float* __restrict__ sums)
{
    extern __shared__ __half sm[];
    const uint32_t sbase = smem_u32(sm);
    const int tid = threadIdx.x;
    const int lane = tid & 31, wid = tid >> 5;
    const int wm = wid & 3, wn = wid >> 2;     // warp grid 4 x 2
    const int gid = lane >> 2, tig = lane & 3;
    const int rowBase = blockIdx.y * BM;
    const int colBase = blockIdx.x * BN;
    const int nk = K / BK;

    const __half* aPtr[2]; uint32_t aSm[2]; uint32_t aBytes[2];
    const __half* bPtr[2]; uint32_t bSm[2];
#pragma unroll
    for (int j = 0; j < 2; j++) {
        int idx2 = tid + j * 256;
        int row = idx2 >> 2, c = idx2 & 3;
        int grow = rowBase + row;
        int crow = grow < M ? grow : 0;
        aPtr[j]   = A + (size_t)crow * lda + c * 8;
        aSm[j]    = sbase + (uint32_t)(row * AT + c * 8) * 2;
        aBytes[j] = grow < M ? 16u : 0u;
        bPtr[j] = BT + (size_t)(colBase + row) * ldb + c * 8;
        bSm[j]  = sbase + (uint32_t)(A_H + row * AT + c * 8) * 2;
    }

    auto load_stage = [&](int stg, int kc0) {
        const uint32_t so = (uint32_t)stg * STAGE_BYTES;
#pragma unroll
        for (int j = 0; j < 2; j++)
            cp16(aSm[j] + so, aPtr[j] + kc0, aBytes[j]);
#pragma unroll
        for (int j = 0; j < 2; j++)
            cp16(bSm[j] + so, bPtr[j] + kc0, 16u);
        cp_commit();
    };

    const int lr = lane & 15, lc = lane >> 4;
    uint32_t aLd[2], bLd[4];
#pragma unroll
    for (int mt = 0; mt < 2; mt++)
        aLd[mt] = sbase + (uint32_t)((wm * 32 + mt * 16 + lr) * AT + lc * 8) * 2;
#pragma unroll
    for (int j = 0; j < 4; j++)
        bLd[j] = sbase + (uint32_t)(A_H + (wn * 64 + j * 16 + lr) * AT + lc * 8) * 2;

    float acc[2][8][4];
#pragma unroll
    for (int mt = 0; mt < 2; mt++)
#pragma unroll
        for (int nt = 0; nt < 8; nt++)
#pragma unroll
            for (int i = 0; i < 4; i++) acc[mt][nt][i] = 0.f;

    load_stage(0, 0);
    if (nk > 1) load_stage(1, BK);
    if (nk > 2) load_stage(2, 2 * BK);

    int buf = 0;
    for (int kt = 0; kt < nk; kt++) {
        if (kt == nk - 1)      cp_wait<0>();
        else if (kt == nk - 2) cp_wait<1>();
        else                   cp_wait<2>();
        __syncthreads();
        if (kt + 3 < nk)
            load_stage((buf + 3) % STAGES, (kt + 3) * BK);

        const uint32_t so = (uint32_t)buf * STAGE_BYTES;
        // ---- preload ALL fragments for this chunk (12 ldmatrix) ----
        uint32_t af[2][2][4], bf[2][4][4];
#pragma unroll
        for (int ks = 0; ks < 2; ks++) {
            const uint32_t ko = so + ks * 32;
            ldsm4(af[ks][0], aLd[0] + ko);
            ldsm4(af[ks][1], aLd[1] + ko);
#pragma unroll
            for (int j = 0; j < 4; j++)
                ldsm4(bf[ks][j], bLd[j] + ko);
        }
        // ---- issue all 32 MMAs back-to-back ----
#pragma unroll
        for (int ks = 0; ks < 2; ks++)
#pragma unroll
            for (int mt = 0; mt < 2; mt++)
#pragma unroll
                for (int j = 0; j < 4; j++) {
                    mma_f16(acc[mt][2 * j],     af[ks][mt], bf[ks][j][0], bf[ks][j][2]);
                    mma_f16(acc[mt][2 * j + 1], af[ks][mt], bf[ks][j][1], bf[ks][j][3]);
                }
        buf = (buf + 1) % STAGES;
    }

    // ---- epilogue ----
#pragma unroll
    for (int mt = 0; mt < 2; mt++) {
#pragma unroll
        for (int h = 0; h < 2; h++) {
            const int row = rowBase + wm * 32 + mt * 16 + gid + h * 8;
            if (row >= M) continue;
            int mol = 0, e0 = 0, e1 = 0;
            if (MODE == MODE_SEG)  mol = __ldg(&idx[row]);
            if (MODE == MODE_PAIR) { e0 = __ldg(&idx[row]); e1 = __ldg(&idx[N_PAIRS + row]); }
#pragma unroll
            for (int nt = 0; nt < 8; nt++) {
                const int gc = colBase + wn * 64 + nt * 8 + tig * 2;
                float2 v = make_float2(acc[mt][nt][2 * h], acc[mt][nt][2 * h + 1]);
                if (BIAS) {
                    const float2 bb = *(const float2*)(bias + gc);
                    v.x += bb.x; v.y += bb.y;
                }
                if (ADDC) {
                    float2 ci;
                    if (CINH) {
                        __half2 c2 = *(const __half2*)((const __half*)Cin + (size_t)row * ldcin + gc);
                        ci = __half22float2(c2);
                    } else {
                        ci = *(const float2*)((const float*)Cin + (size_t)row * ldcin + gc);
                    }
                    v.x += ci.x; v.y += ci.y;
                }
                if (MODE == MODE_PAIR) {
                    const float2 u1 = *(const float2*)(U + (size_t)e0 * 4096 + gc);
                    const float2 u2 = *(const float2*)(U + (size_t)e1 * 4096 + FFN1 + gc);
                    v.x += u1.x + u2.x; v.y += u1.y + u2.y;
                }
                if (RELU) { v.x = fmaxf(v.x, 0.f); v.y = fmaxf(v.y, 0.f); }
                if (MODE == MODE_SEG) {
                    float* s = sums + (size_t)mol * HIDDEN + gc;
                    atomicAdd(s,     v.x);
                    atomicAdd(s + 1, v.y);
                } else if (OUTH) {
                    *(__half2*)((__half*)Cout + (size_t)row * ldc + gc) = __floats2half2_rn(v.x, v.y);
                } else {
                    *(float2*)((float*)Cout + (size_t)row * ldc + gc) = v;
                }
            }
        }
    }
}

// ---------------- prep kernels ----------------------------------------------
__global__ void pad_atoms_h_kernel(const float* __restrict__ f, __half* __restrict__ out) {
    int idx = blockIdx.x * blockDim.x + threadIdx.x;
    if (idx >= N_ATOMS * KPAD_F) return;
    int a = idx / KPAD_F, k = idx - a * KPAD_F;
    out[idx] = __float2half((k < ATOM_FDIM) ? f[a * ATOM_FDIM + k] : 0.f);
}

__global__ void transpose_pad_h_kernel(const float* __restrict__ W, __half* __restrict__ WT,
                                       int K, int N, int Kpad) {
    __shared__ float t[32][33];
    int kb = blockIdx.y * 32, nb = blockIdx.x * 32;
    int tx = threadIdx.x, ty = threadIdx.y;
#pragma unroll
    for (int i = 0; i < 4; i++) {
        int kk = kb + ty + i * 8;
        t[ty + i * 8][tx] = (kk < K) ? W[(size_t)kk * N + nb + tx] : 0.f;
    }
    __syncthreads();
#pragma unroll
    for (int i = 0; i < 4; i++) {
        int n = nb + ty + i * 8;
        WT[(size_t)n * Kpad + kb + tx] = __float2half(t[tx][ty + i * 8]);
    }
}

__global__ void build_wcatT_h_kernel(const float* __restrict__ Wi,
                                     const float* __restrict__ Wo,
                                     __half* __restrict__ out) {
    int idx = blockIdx.x * blockDim.x + threadIdx.x;
    if (idx >= 1024 * KPAD_F) return;
    int n = idx / KPAD_F, k = idx - n * KPAD_F;
    float v = 0.f;
    if (k < ATOM_FDIM)
        v = (n < HIDDEN) ? Wi[k * HIDDEN + n] : Wo[k * HIDDEN + (n - HIDDEN)];
    out[idx] = __float2half(v);
}

__global__ void build_wcombT_h_kernel(const float* __restrict__ Wfi,
                                      __half* __restrict__ out) {
    int idx = blockIdx.x * blockDim.x + threadIdx.x;
    if (idx >= 4096 * HIDDEN) return;
    int n = idx / HIDDEN, k = idx - n * HIDDEN;
    float v;
    if (n < FFN1)
        v = Wfi[(size_t)k * FFN1 + n] + Wfi[(size_t)(1024 + k) * FFN1 + n];
    else {
        int n2 = n - FFN1;
        v = Wfi[(size_t)k * FFN1 + n2] + Wfi[(size_t)(1536 + k) * FFN1 + n2];
    }
    out[idx] = __float2half(v);
}

// ---------------- neighbor gather-sum (half) --------------------------------
__global__ void gather_sum_h_kernel(const __half* __restrict__ src, int srcStride,
                                    const int* __restrict__ nei,
                                    __half* __restrict__ dst, int relu_src)
{
    int atom = blockIdx.x;
    int c = threadIdx.x;  // 0..63
    const int* nrow = nei + atom * MAX_NEI;
    float2 acc[4] = {{0.f,0.f},{0.f,0.f},{0.f,0.f},{0.f,0.f}};
#pragma unroll
    for (int j = 0; j < MAX_NEI; j++) {
        int n = __ldg(&nrow[j]);
        uint4 v = __ldg((const uint4*)(src + (size_t)n * srcStride) + c);
        uint32_t w[4] = {v.x, v.y, v.z, v.w};
#pragma unroll
        for (int i = 0; i < 4; i++) {
            float2 f = __half22float2(*(__half2*)&w[i]);
            if (relu_src) { f.x = fmaxf(f.x, 0.f); f.y = fmaxf(f.y, 0.f); }
            acc[i].x += f.x; acc[i].y += f.y;
        }
    }
    uint4 o;
    uint32_t* ow = (uint32_t*)&o;
#pragma unroll
    for (int i = 0; i < 4; i++) {
        __half2 h = __floats2half2_rn(acc[i].x, acc[i].y);
        ow[i] = *(uint32_t*)&h;
    }
    ((uint4*)(dst + (size_t)atom * HIDDEN))[c] = o;
}

// ---------------- segment mean pieces ---------------------------------------
__global__ void zero_seg_kernel() {
    int i = blockIdx.x * blockDim.x + threadIdx.x;
    if (i < N_MOLS * HIDDEN) g_sums[i] = 0.f;
    if (i < N_MOLS) g_cnt[i] = 0.f;
}

__global__ void count_kernel(const int* __restrict__ mol_ids) {
    int i = blockIdx.x * blockDim.x + threadIdx.x;
    if (i < N_ATOMS) atomicAdd(&g_cnt[__ldg(&mol_ids[i])], 1.f);
}

// mvh = (sums / max(cnt,1)) as half  (half copy only; fp32 mv not stored)
__global__ void mv_kernel()
{
    int m = blockIdx.x;
    int c = threadIdx.x;
    float inv = 1.f / fmaxf(g_cnt[m], 1.f);
    float4 v = ((const float4*)(g_sums + (size_t)m * HIDDEN))[c];
    v.x *= inv; v.y *= inv; v.z *= inv; v.w *= inv;
    __half2 h0 = __floats2half2_rn(v.x, v.y);
    __half2 h1 = __floats2half2_rn(v.z, v.w);
    uint2 o = make_uint2(*(uint32_t*)&h0, *(uint32_t*)&h1);
    ((uint2*)(g_mvh + (size_t)m * HIDDEN))[c] = o;
}

// prod[p] = (sums[a]*inv_a) * (sums[b]*inv_b)  (half out)
__global__ void prod_kernel(const int* __restrict__ edges)
{
    int p = blockIdx.x;
    int a = __ldg(&edges[p]);
    int b = __ldg(&edges[N_PAIRS + p]);
    float ia = 1.f / fmaxf(__ldg(&g_cnt[a]), 1.f);
    float ib = 1.f / fmaxf(__ldg(&g_cnt[b]), 1.f);
    int c = threadIdx.x;
    float4 va = __ldg((const float4*)(g_sums + (size_t)a * HIDDEN) + c);
    float4 vb = __ldg((const float4*)(g_sums + (size_t)b * HIDDEN) + c);
    va.x *= ia; va.y *= ia; va.z *= ia; va.w *= ia;
    vb.x *= ib; vb.y *= ib; vb.z *= ib; vb.w *= ib;
    __half2 h0 = __floats2half2_rn(va.x * vb.x, va.y * vb.y);
    __half2 h1 = __floats2half2_rn(va.z * vb.z, va.w * vb.w);
    uint2 o = make_uint2(*(uint32_t*)&h0, *(uint32_t*)&h1);
    ((uint2*)(g_prodh + (size_t)p * HIDDEN))[c] = o;
}

// ---------------- final dot + sigmoid ---------------------------------------
__global__ void ffn_last_kernel(const float* __restrict__ h2,
                                const float* __restrict__ W,
                                const float* __restrict__ b,
                                float* __restrict__ out)
{
    int p = blockIdx.x;
    float s = 0.f;
    for (int i = threadIdx.x; i < FFN2; i += 128)
        s += h2[(size_t)p * FFN2 + i] * W[i];
#pragma unroll
    for (int off = 16; off; off >>= 1)
        s += __shfl_down_sync(0xffffffffu, s, off);
    __shared__ float red[4];
    if ((threadIdx.x & 31) == 0) red[threadIdx.x >> 5] = s;
    __syncthreads();
    if (threadIdx.x == 0) {
        float t = red[0] + red[1] + red[2] + red[3] + b[0];
        out[p] = 1.f / (1.f + expf(-t));
    }
}

// ---------------- launch ----------------------------------------------------
extern "C" void kernel_launch(void* const* d_in, const int* in_sizes, int n_in,
                              void* d_out, int out_size)
{
    const float* f_atoms = (const float*)d_in[0];
    const int*   a_nei   = (const int*)d_in[1];
    const int*   mol_ids = (const int*)d_in[2];
    const int*   edges   = (const int*)d_in[3];
    const float* W_i     = (const float*)d_in[4];
    const float* W_h     = (const float*)d_in[5];
    const float* W_o     = (const float*)d_in[6];
    const float* b_o     = (const float*)d_in[7];
    const float* W_fi    = (const float*)d_in[8];
    const float* b_fi    = (const float*)d_in[9];
    const float* W_f1    = (const float*)d_in[10];
    const float* b_f1    = (const float*)d_in[11];
    const float* W_f2    = (const float*)d_in[12];
    const float* b_f2    = (const float*)d_in[13];
    float* out = (float*)d_out;

    __half *padAh, *cath, *bufBh, *bufCh, *h1h, *prodh, *mvh;
    __half *wcatTh, *whTh, *wo2Th, *wcombTh, *wmTh, *wf1Th;
    float *h2p, *Up, *sums;
    cudaGetSymbolAddress((void**)&padAh,   g_padAh);
    cudaGetSymbolAddress((void**)&cath,    g_cath);
    cudaGetSymbolAddress((void**)&bufBh,   g_bufBh);
    cudaGetSymbolAddress((void**)&bufCh,   g_bufCh);
    cudaGetSymbolAddress((void**)&h1h,     g_h1h);
    cudaGetSymbolAddress((void**)&prodh,   g_prodh);
    cudaGetSymbolAddress((void**)&mvh,     g_mvh);
    cudaGetSymbolAddress((void**)&wcatTh,  g_WcatTh);
    cudaGetSymbolAddress((void**)&whTh,    g_WhTh);
    cudaGetSymbolAddress((void**)&wo2Th,   g_Wo2Th);
    cudaGetSymbolAddress((void**)&wcombTh, g_WcombTh);
    cudaGetSymbolAddress((void**)&wmTh,    g_WmTh);
    cudaGetSymbolAddress((void**)&wf1Th,   g_Wf1Th);
    cudaGetSymbolAddress((void**)&h2p,     g_h2);
    cudaGetSymbolAddress((void**)&Up,      g_U);
    cudaGetSymbolAddress((void**)&sums,    g_sums);

    cudaFuncSetAttribute(hgemm<MODE_N, false, false, false, false, true>,
                         cudaFuncAttributeMaxDynamicSharedMemorySize, SMEM_BYTES);
    cudaFuncSetAttribute(hgemm<MODE_N, true, true, true, false, true>,
                         cudaFuncAttributeMaxDynamicSharedMemorySize, SMEM_BYTES);
    cudaFuncSetAttribute(hgemm<MODE_SEG, true, true, true, true, false>,
                         cudaFuncAttributeMaxDynamicSharedMemorySize, SMEM_BYTES);
    cudaFuncSetAttribute(hgemm<MODE_N, false, false, false, false, false>,
                         cudaFuncAttributeMaxDynamicSharedMemorySize, SMEM_BYTES);
    cudaFuncSetAttribute(hgemm<MODE_PAIR, true, false, false, true, true>,
                         cudaFuncAttributeMaxDynamicSharedMemorySize, SMEM_BYTES);
    cudaFuncSetAttribute(hgemm<MODE_N, true, false, false, true, false>,
                         cudaFuncAttributeMaxDynamicSharedMemorySize, SMEM_BYTES);

    // prep
    pad_atoms_h_kernel<<<(N_ATOMS * KPAD_F + 255) / 256, 256>>>(f_atoms, padAh);
    build_wcatT_h_kernel<<<(1024 * KPAD_F + 255) / 256, 256>>>(W_i, W_o, wcatTh);
    build_wcombT_h_kernel<<<(4096 * HIDDEN + 255) / 256, 256>>>(W_fi, wcombTh);
    dim3 tb(32, 8);
    transpose_pad_h_kernel<<<dim3(HIDDEN / 32, HIDDEN / 32), tb>>>(W_h, whTh, HIDDEN, HIDDEN, HIDDEN);
    transpose_pad_h_kernel<<<dim3(HIDDEN / 32, HIDDEN / 32), tb>>>(W_o + ATOM_FDIM * HIDDEN, wo2Th, HIDDEN, HIDDEN, HIDDEN);
    transpose_pad_h_kernel<<<dim3(FFN1 / 32, HIDDEN / 32), tb>>>(W_fi + (size_t)512 * FFN1, wmTh, HIDDEN, FFN1, HIDDEN);
    transpose_pad_h_kernel<<<dim3(FFN2 / 32, FFN1 / 32), tb>>>(W_f1, wf1Th, FFN1, FFN2, FFN1);
    zero_seg_kernel<<<(N_MOLS * HIDDEN + 255) / 256, 256>>>();
    count_kernel<<<(N_ATOMS + 255) / 256, 256>>>(mol_ids);

    const int MT = (N_ATOMS + BM - 1) / BM;  // 782

    // 1+5. [inp | ah_partial] = padA @ Wcat              -> cath [N,1024] half
    hgemm<MODE_N, false, false, false, false, true><<<dim3(1024 / BN, MT), 256, SMEM_BYTES>>>(
        N_ATOMS, 1024, KPAD_F, KPAD_F, KPAD_F, 0, 1024, padAh, wcatTh,
        nullptr, nullptr, cath, nullptr, nullptr, nullptr);
    // 2. bufBh = sum_j relu(inp[nei])
    gather_sum_h_kernel<<<N_ATOMS, 64>>>(cath, 1024, a_nei, bufBh, 1);
    // 3. msg2 = relu(inp + bufBh @ W_h)                  -> bufCh half
    hgemm<MODE_N, true, true, true, false, true><<<dim3(HIDDEN / BN, MT), 256, SMEM_BYTES>>>(
        N_ATOMS, HIDDEN, HIDDEN, HIDDEN, HIDDEN, 1024, HIDDEN, bufBh, whTh,
        cath, nullptr, bufCh, nullptr, nullptr, nullptr);
    // 4. bufBh = sum_j msg2[nei]
    gather_sum_h_kernel<<<N_ATOMS, 64>>>(bufCh, HIDDEN, a_nei, bufBh, 0);
    // 6. fused: relu(ah_partial + bufBh @ W_o_bot + b_o) -> atomic into g_sums
    hgemm<MODE_SEG, true, true, true, true, false><<<dim3(HIDDEN / BN, MT), 256, SMEM_BYTES>>>(
        N_ATOMS, HIDDEN, HIDDEN, HIDDEN, HIDDEN, 1024, HIDDEN, bufBh, wo2Th,
        cath + HIDDEN, b_o, nullptr, mol_ids, nullptr, sums);
    // 8. mvh = sums / counts (half)
    mv_kernel<<<N_MOLS, 128>>>();
    // 9a. U = mv @ [(Ws+W1) | (Ws+W2)]                    -> g_U [M,4096] fp32
    hgemm<MODE_N, false, false, false, false, false><<<dim3(4096 / BN, N_MOLS / BM), 256, SMEM_BYTES>>>(
        N_MOLS, 4096, HIDDEN, HIDDEN, HIDDEN, 0, 4096, mvh, wcombTh,
        nullptr, nullptr, Up, nullptr, nullptr, nullptr);
    // 9b. prod[p] = mv[a]*mv[b]                           -> prodh half
    prod_kernel<<<N_PAIRS, 128>>>(edges);
    // 10. fused: h1 = relu(prod @ Wm + U1[a] + U2[b] + b_fi) -> h1h half
    hgemm<MODE_PAIR, true, false, false, true, true><<<dim3(FFN1 / BN, N_PAIRS / BM), 256, SMEM_BYTES>>>(
        N_PAIRS, FFN1, HIDDEN, HIDDEN, HIDDEN, FFN1, FFN1, prodh, wmTh,
        nullptr, b_fi, h1h, edges, Up, nullptr);
    // 11. h2 = relu(h1 @ W_ffn_1 + b_ffn_1)               -> g_h2 fp32
    hgemm<MODE_N, true, false, false, true, false><<<dim3(FFN2 / BN, N_PAIRS / BM), 256, SMEM_BYTES>>>(
        N_PAIRS, FFN2, FFN1, FFN1, FFN1, 0, FFN2, h1h, wf1Th,
        nullptr, b_f1, h2p, nullptr, nullptr, nullptr);
    // 12. out = sigmoid(h2 . W_ffn_2 + b_ffn_2)
    ffn_last_kernel<<<N_PAIRS, 128>>>(h2p, W_f2, b_f2, out);
}

// round 11
// speedup vs baseline: 6.5716x; 1.0018x over previous
#include <cuda_runtime.h>
#include <cuda_fp16.h>
#include <math.h>
#include <stdint.h>

#define N_ATOMS   100000
#define ATOM_FDIM 133
#define KPAD_F    160
#define HIDDEN    512
#define MAX_NEI   6
#define N_MOLS    4096
#define N_PAIRS   8192
#define FFN1      2048
#define FFN2      1024

#define MODE_N    0
#define MODE_PAIR 2

// ---------------- scratch (device globals: allocation-free) ----------------
__device__ alignas(16) __half g_padAh [N_ATOMS * KPAD_F];
__device__ alignas(16) __half g_cath  [N_ATOMS * 1024];   // [inp | ah_partial]
__device__ alignas(16) __half g_bufBh [N_ATOMS * HIDDEN];
__device__ alignas(16) __half g_bufCh [N_ATOMS * HIDDEN];
__device__ alignas(16) __half g_h1h   [N_PAIRS * FFN1];
__device__ alignas(16) __half g_prodh [N_PAIRS * HIDDEN];
__device__ alignas(16) __half g_mvh   [N_MOLS * HIDDEN];
__device__ float g_h2  [N_PAIRS * FFN2];
__device__ float g_sums[N_MOLS * HIDDEN];
__device__ float g_cnt [N_MOLS];
__device__ float g_U   [N_MOLS * 4096];
__device__ int   g_segStart[N_MOLS + 1];
// transposed half weights [N][K] (K-contiguous)
__device__ alignas(16) __half g_WcatTh [1024 * KPAD_F];
__device__ alignas(16) __half g_WhTh   [HIDDEN * HIDDEN];
__device__ alignas(16) __half g_Wo2Th  [HIDDEN * HIDDEN];
__device__ alignas(16) __half g_WcombTh[4096 * HIDDEN];
__device__ alignas(16) __half g_WmTh   [FFN1 * HIDDEN];
__device__ alignas(16) __half g_Wf1Th  [FFN2 * FFN1];

// ---------------- PTX helpers ----------------------------------------------
__device__ __forceinline__ uint32_t smem_u32(const void* p) {
    return (uint32_t)__cvta_generic_to_shared(p);
}
__device__ __forceinline__ void cp16(uint32_t s, const void* g, uint32_t bytes) {
    asm volatile("cp.async.cg.shared.global [%0], [%1], 16, %2;\n"
                 :: "r"(s), "l"(g), "r"(bytes));
}
__device__ __forceinline__ void cp_commit() {
    asm volatile("cp.async.commit_group;\n" ::: "memory");
}
template <int N>
__device__ __forceinline__ void cp_wait() {
    asm volatile("cp.async.wait_group %0;\n" :: "n"(N) : "memory");
}
__device__ __forceinline__ void ldsm4(uint32_t* r, uint32_t addr) {
    asm volatile("ldmatrix.sync.aligned.m8n8.x4.shared.b16 {%0,%1,%2,%3}, [%4];\n"
                 : "=r"(r[0]), "=r"(r[1]), "=r"(r[2]), "=r"(r[3]) : "r"(addr));
}
__device__ __forceinline__ void mma_f16(float* c, const uint32_t* a,
                                        uint32_t b0, uint32_t b1) {
    asm volatile(
        "mma.sync.aligned.m16n8k16.row.col.f32.f16.f16.f32 "
        "{%0,%1,%2,%3}, {%4,%5,%6,%7}, {%8,%9}, {%0,%1,%2,%3};\n"
        : "+f"(c[0]), "+f"(c[1]), "+f"(c[2]), "+f"(c[3])
        : "r"(a[0]), "r"(a[1]), "r"(a[2]), "r"(a[3]), "r"(b0), "r"(b1));
}

// ---------------- GEMM tile config ------------------------------------------
#define BM 128
#define BN 128
#define BK 32
#define STAGES 4
#define AT 40                                 // halves per smem row (pad 8)
#define A_H (BM * AT)                         // 5120 halves
#define STAGE_H (2 * A_H)
#define STAGE_BYTES (STAGE_H * 2)             // 20480
#define SMEM_BYTES (STAGES * STAGE_BYTES)     // 81920

// ---------------- fp16 mma GEMM: C = A[MxK] @ BT[NxK]^T ---------------------
template <int MODE, bool RELU, bool ADDC, bool CINH, bool BIAS, bool OUTH>
__global__ __launch_bounds__(256, 2)
void hgemm(int M, int N, int K, int lda, int ldb, int ldcin, int ldc,
           const __half* __restrict__ A, const __half* __restrict__ BT,
           const void* __restrict__ Cin, const float* __restrict__ bias,
           void* __restrict__ Cout,
           const int* __restrict__ idx, const float* __restrict__ U)
{
    extern __shared__ __half sm[];
    const uint32_t sbase = smem_u32(sm);
    const int tid = threadIdx.x;
    const int lane = tid & 31, wid = tid >> 5;
    const int wm = wid & 3, wn = wid >> 2;     // warp grid 4 x 2
    const int gid = lane >> 2, tig = lane & 3;
    const int rowBase = blockIdx.y * BM;
    const int colBase = blockIdx.x * BN;
    const int nk = K / BK;

    const __half* aPtr[2]; uint32_t aSm[2]; uint32_t aBytes[2];
    const __half* bPtr[2]; uint32_t bSm[2];
#pragma unroll
    for (int j = 0; j < 2; j++) {
        int idx2 = tid + j * 256;
        int row = idx2 >> 2, c = idx2 & 3;
        int grow = rowBase + row;
        int crow = grow < M ? grow : 0;
        aPtr[j]   = A + (size_t)crow * lda + c * 8;
        aSm[j]    = sbase + (uint32_t)(row * AT + c * 8) * 2;
        aBytes[j] = grow < M ? 16u : 0u;
        bPtr[j] = BT + (size_t)(colBase + row) * ldb + c * 8;
        bSm[j]  = sbase + (uint32_t)(A_H + row * AT + c * 8) * 2;
    }

    auto load_stage = [&](int stg, int kc0) {
        const uint32_t so = (uint32_t)stg * STAGE_BYTES;
#pragma unroll
        for (int j = 0; j < 2; j++)
            cp16(aSm[j] + so, aPtr[j] + kc0, aBytes[j]);
#pragma unroll
        for (int j = 0; j < 2; j++)
            cp16(bSm[j] + so, bPtr[j] + kc0, 16u);
        cp_commit();
    };

    const int lr = lane & 15, lc = lane >> 4;
    uint32_t aLd[2], bLd[4];
#pragma unroll
    for (int mt = 0; mt < 2; mt++)
        aLd[mt] = sbase + (uint32_t)((wm * 32 + mt * 16 + lr) * AT + lc * 8) * 2;
#pragma unroll
    for (int j = 0; j < 4; j++)
        bLd[j] = sbase + (uint32_t)(A_H + (wn * 64 + j * 16 + lr) * AT + lc * 8) * 2;

    float acc[2][8][4];
#pragma unroll
    for (int mt = 0; mt < 2; mt++)
#pragma unroll
        for (int nt = 0; nt < 8; nt++)
#pragma unroll
            for (int i = 0; i < 4; i++) acc[mt][nt][i] = 0.f;

    load_stage(0, 0);
    if (nk > 1) load_stage(1, BK);
    if (nk > 2) load_stage(2, 2 * BK);

    int buf = 0;
    for (int kt = 0; kt < nk; kt++) {
        if (kt == nk - 1)      cp_wait<0>();
        else if (kt == nk - 2) cp_wait<1>();
        else                   cp_wait<2>();
        __syncthreads();
        if (kt + 3 < nk)
            load_stage((buf + 3) % STAGES, (kt + 3) * BK);

        const uint32_t so = (uint32_t)buf * STAGE_BYTES;
        uint32_t af[2][2][4], bf[2][4][4];
#pragma unroll
        for (int ks = 0; ks < 2; ks++) {
            const uint32_t ko = so + ks * 32;
            ldsm4(af[ks][0], aLd[0] + ko);
            ldsm4(af[ks][1], aLd[1] + ko);
#pragma unroll
            for (int j = 0; j < 4; j++)
                ldsm4(bf[ks][j], bLd[j] + ko);
        }
#pragma unroll
        for (int ks = 0; ks < 2; ks++)
#pragma unroll
            for (int mt = 0; mt < 2; mt++)
#pragma unroll
                for (int j = 0; j < 4; j++) {
                    mma_f16(acc[mt][2 * j],     af[ks][mt], bf[ks][j][0], bf[ks][j][2]);
                    mma_f16(acc[mt][2 * j + 1], af[ks][mt], bf[ks][j][1], bf[ks][j][3]);
                }
        buf = (buf + 1) % STAGES;
    }

    // ---- epilogue ----
#pragma unroll
    for (int mt = 0; mt < 2; mt++) {
#pragma unroll
        for (int h = 0; h < 2; h++) {
            const int row = rowBase + wm * 32 + mt * 16 + gid + h * 8;
            if (row >= M) continue;
            int e0 = 0, e1 = 0;
            if (MODE == MODE_PAIR) { e0 = __ldg(&idx[row]); e1 = __ldg(&idx[N_PAIRS + row]); }
#pragma unroll
            for (int nt = 0; nt < 8; nt++) {
                const int gc = colBase + wn * 64 + nt * 8 + tig * 2;
                float2 v = make_float2(acc[mt][nt][2 * h], acc[mt][nt][2 * h + 1]);
                if (BIAS) {
                    const float2 bb = *(const float2*)(bias + gc);
                    v.x += bb.x; v.y += bb.y;
                }
                if (ADDC) {
                    float2 ci;
                    if (CINH) {
                        __half2 c2 = *(const __half2*)((const __half*)Cin + (size_t)row * ldcin + gc);
                        ci = __half22float2(c2);
                    } else {
                        ci = *(const float2*)((const float*)Cin + (size_t)row * ldcin + gc);
                    }
                    v.x += ci.x; v.y += ci.y;
                }
                if (MODE == MODE_PAIR) {
                    const float2 u1 = *(const float2*)(U + (size_t)e0 * 4096 + gc);
                    const float2 u2 = *(const float2*)(U + (size_t)e1 * 4096 + FFN1 + gc);
                    v.x += u1.x + u2.x; v.y += u1.y + u2.y;
                }
                if (RELU) { v.x = fmaxf(v.x, 0.f); v.y = fmaxf(v.y, 0.f); }
                if (OUTH)
                    *(__half2*)((__half*)Cout + (size_t)row * ldc + gc) = __floats2half2_rn(v.x, v.y);
                else
                    *(float2*)((float*)Cout + (size_t)row * ldc + gc) = v;
            }
        }
    }
}

// ---------------- prep kernels ----------------------------------------------
__global__ void pad_atoms_h_kernel(const float* __restrict__ f, __half* __restrict__ out) {
    int idx = blockIdx.x * blockDim.x + threadIdx.x;
    if (idx >= N_ATOMS * KPAD_F) return;
    int a = idx / KPAD_F, k = idx - a * KPAD_F;
    out[idx] = __float2half((k < ATOM_FDIM) ? f[a * ATOM_FDIM + k] : 0.f);
}

__global__ void transpose_pad_h_kernel(const float* __restrict__ W, __half* __restrict__ WT,
                                       int K, int N, int Kpad) {
    __shared__ float t[32][33];
    int kb = blockIdx.y * 32, nb = blockIdx.x * 32;
    int tx = threadIdx.x, ty = threadIdx.y;
#pragma unroll
    for (int i = 0; i < 4; i++) {
        int kk = kb + ty + i * 8;
        t[ty + i * 8][tx] = (kk < K) ? W[(size_t)kk * N + nb + tx] : 0.f;
    }
    __syncthreads();
#pragma unroll
    for (int i = 0; i < 4; i++) {
        int n = nb + ty + i * 8;
        WT[(size_t)n * Kpad + kb + tx] = __float2half(t[tx][ty + i * 8]);
    }
}

__global__ void build_wcatT_h_kernel(const float* __restrict__ Wi,
                                     const float* __restrict__ Wo,
                                     __half* __restrict__ out) {
    int idx = blockIdx.x * blockDim.x + threadIdx.x;
    if (idx >= 1024 * KPAD_F) return;
    int n = idx / KPAD_F, k = idx - n * KPAD_F;
    float v = 0.f;
    if (k < ATOM_FDIM)
        v = (n < HIDDEN) ? Wi[k * HIDDEN + n] : Wo[k * HIDDEN + (n - HIDDEN)];
    out[idx] = __float2half(v);
}

__global__ void build_wcombT_h_kernel(const float* __restrict__ Wfi,
                                      __half* __restrict__ out) {
    int idx = blockIdx.x * blockDim.x + threadIdx.x;
    if (idx >= 4096 * HIDDEN) return;
    int n = idx / HIDDEN, k = idx - n * HIDDEN;
    float v;
    if (n < FFN1)
        v = Wfi[(size_t)k * FFN1 + n] + Wfi[(size_t)(1024 + k) * FFN1 + n];
    else {
        int n2 = n - FFN1;
        v = Wfi[(size_t)k * FFN1 + n2] + Wfi[(size_t)(1536 + k) * FFN1 + n2];
    }
    out[idx] = __float2half(v);
}

// ---------------- neighbor gather-sum (half) --------------------------------
__global__ void gather_sum_h_kernel(const __half* __restrict__ src, int srcStride,
                                    const int* __restrict__ nei,
                                    __half* __restrict__ dst, int relu_src)
{
    int atom = blockIdx.x;
    int c = threadIdx.x;  // 0..63
    const int* nrow = nei + atom * MAX_NEI;
    float2 acc[4] = {{0.f,0.f},{0.f,0.f},{0.f,0.f},{0.f,0.f}};
#pragma unroll
    for (int j = 0; j < MAX_NEI; j++) {
        int n = __ldg(&nrow[j]);
        uint4 v = __ldg((const uint4*)(src + (size_t)n * srcStride) + c);
        uint32_t w[4] = {v.x, v.y, v.z, v.w};
#pragma unroll
        for (int i = 0; i < 4; i++) {
            float2 f = __half22float2(*(__half2*)&w[i]);
            if (relu_src) { f.x = fmaxf(f.x, 0.f); f.y = fmaxf(f.y, 0.f); }
            acc[i].x += f.x; acc[i].y += f.y;
        }
    }
    uint4 o;
    uint32_t* ow = (uint32_t*)&o;
#pragma unroll
    for (int i = 0; i < 4; i++) {
        __half2 h = __floats2half2_rn(acc[i].x, acc[i].y);
        ow[i] = *(uint32_t*)&h;
    }
    ((uint4*)(dst + (size_t)atom * HIDDEN))[c] = o;
}

// ---------------- sorted-segment mean ---------------------------------------
// start[m] = lower_bound(mol_ids, m); start[N_MOLS] = N_ATOMS
__global__ void seg_bounds_kernel(const int* __restrict__ mol_ids)
{
    int m = blockIdx.x * blockDim.x + threadIdx.x;
    if (m > N_MOLS) return;
    if (m == N_MOLS) { g_segStart[N_MOLS] = N_ATOMS; return; }
    int lo = 0, hi = N_ATOMS;
    while (lo < hi) {
        int mid = (lo + hi) >> 1;
        if (__ldg(&mol_ids[mid]) < m) lo = mid + 1; else hi = mid;
    }
    g_segStart[m] = lo;
}

// block (m, chunk): sum rows [start[m], start[m+1]) over 128 cols; no atomics.
__global__ void seg_reduce_kernel(const __half* __restrict__ ah)
{
    int m = blockIdx.x;
    int col = blockIdx.y * 128 + threadIdx.x;
    int s = __ldg(&g_segStart[m]);
    int e = __ldg(&g_segStart[m + 1]);
    float acc = 0.f;
    for (int r = s; r < e; r++)
        acc += __half2float(__ldg(&ah[(size_t)r * HIDDEN + col]));
    g_sums[(size_t)m * HIDDEN + col] = acc;
    float inv = 1.f / fmaxf((float)(e - s), 1.f);
    g_mvh[(size_t)m * HIDDEN + col] = __float2half(acc * inv);
    if (threadIdx.x == 0 && blockIdx.y == 0) g_cnt[m] = (float)(e - s);
}

// prod[p] = (sums[a]*inv_a) * (sums[b]*inv_b)  (half out)
__global__ void prod_kernel(const int* __restrict__ edges)
{
    int p = blockIdx.x;
    int a = __ldg(&edges[p]);
    int b = __ldg(&edges[N_PAIRS + p]);
    float ia = 1.f / fmaxf(__ldg(&g_cnt[a]), 1.f);
    float ib = 1.f / fmaxf(__ldg(&g_cnt[b]), 1.f);
    int c = threadIdx.x;
    float4 va = __ldg((const float4*)(g_sums + (size_t)a * HIDDEN) + c);
    float4 vb = __ldg((const float4*)(g_sums + (size_t)b * HIDDEN) + c);
    va.x *= ia; va.y *= ia; va.z *= ia; va.w *= ia;
    vb.x *= ib; vb.y *= ib; vb.z *= ib; vb.w *= ib;
    __half2 h0 = __floats2half2_rn(va.x * vb.x, va.y * vb.y);
    __half2 h1 = __floats2half2_rn(va.z * vb.z, va.w * vb.w);
    uint2 o = make_uint2(*(uint32_t*)&h0, *(uint32_t*)&h1);
    ((uint2*)(g_prodh + (size_t)p * HIDDEN))[c] = o;
}

// ---------------- final dot + sigmoid ---------------------------------------
__global__ void ffn_last_kernel(const float* __restrict__ h2,
                                const float* __restrict__ W,
                                const float* __restrict__ b,
                                float* __restrict__ out)
{
    int p = blockIdx.x;
    float s = 0.f;
    for (int i = threadIdx.x; i < FFN2; i += 128)
        s += h2[(size_t)p * FFN2 + i] * W[i];
#pragma unroll
    for (int off = 16; off; off >>= 1)
        s += __shfl_down_sync(0xffffffffu, s, off);
    __shared__ float red[4];
    if ((threadIdx.x & 31) == 0) red[threadIdx.x >> 5] = s;
    __syncthreads();
    if (threadIdx.x == 0) {
        float t = red[0] + red[1] + red[2] + red[3] + b[0];
        out[p] = 1.f / (1.f + expf(-t));
    }
}

// ---------------- launch ----------------------------------------------------
extern "C" void kernel_launch(void* const* d_in, const int* in_sizes, int n_in,
                              void* d_out, int out_size)
{
    const float* f_atoms = (const float*)d_in[0];
    const int*   a_nei   = (const int*)d_in[1];
    const int*   mol_ids = (const int*)d_in[2];
    const int*   edges   = (const int*)d_in[3];
    const float* W_i     = (const float*)d_in[4];
    const float* W_h     = (const float*)d_in[5];
    const float* W_o     = (const float*)d_in[6];
    const float* b_o     = (const float*)d_in[7];
    const float* W_fi    = (const float*)d_in[8];
    const float* b_fi    = (const float*)d_in[9];
    const float* W_f1    = (const float*)d_in[10];
    const float* b_f1    = (const float*)d_in[11];
    const float* W_f2    = (const float*)d_in[12];
    const float* b_f2    = (const float*)d_in[13];
    float* out = (float*)d_out;

    __half *padAh, *cath, *bufBh, *bufCh, *h1h, *prodh, *mvh;
    __half *wcatTh, *whTh, *wo2Th, *wcombTh, *wmTh, *wf1Th;
    float *h2p, *Up;
    cudaGetSymbolAddress((void**)&padAh,   g_padAh);
    cudaGetSymbolAddress((void**)&cath,    g_cath);
    cudaGetSymbolAddress((void**)&bufBh,   g_bufBh);
    cudaGetSymbolAddress((void**)&bufCh,   g_bufCh);
    cudaGetSymbolAddress((void**)&h1h,     g_h1h);
    cudaGetSymbolAddress((void**)&prodh,   g_prodh);
    cudaGetSymbolAddress((void**)&mvh,     g_mvh);
    cudaGetSymbolAddress((void**)&wcatTh,  g_WcatTh);
    cudaGetSymbolAddress((void**)&whTh,    g_WhTh);
    cudaGetSymbolAddress((void**)&wo2Th,   g_Wo2Th);
    cudaGetSymbolAddress((void**)&wcombTh, g_WcombTh);
    cudaGetSymbolAddress((void**)&wmTh,    g_WmTh);
    cudaGetSymbolAddress((void**)&wf1Th,   g_Wf1Th);
    cudaGetSymbolAddress((void**)&h2p,     g_h2);
    cudaGetSymbolAddress((void**)&Up,      g_U);

    cudaFuncSetAttribute(hgemm<MODE_N, false, false, false, false, true>,
                         cudaFuncAttributeMaxDynamicSharedMemorySize, SMEM_BYTES);
    cudaFuncSetAttribute(hgemm<MODE_N, true, true, true, false, true>,
                         cudaFuncAttributeMaxDynamicSharedMemorySize, SMEM_BYTES);
    cudaFuncSetAttribute(hgemm<MODE_N, true, true, true, true, true>,
                         cudaFuncAttributeMaxDynamicSharedMemorySize, SMEM_BYTES);
    cudaFuncSetAttribute(hgemm<MODE_N, false, false, false, false, false>,
                         cudaFuncAttributeMaxDynamicSharedMemorySize, SMEM_BYTES);
    cudaFuncSetAttribute(hgemm<MODE_PAIR, true, false, false, true, true>,
                         cudaFuncAttributeMaxDynamicSharedMemorySize, SMEM_BYTES);
    cudaFuncSetAttribute(hgemm<MODE_N, true, false, false, true, false>,
                         cudaFuncAttributeMaxDynamicSharedMemorySize, SMEM_BYTES);

    // prep
    pad_atoms_h_kernel<<<(N_ATOMS * KPAD_F + 255) / 256, 256>>>(f_atoms, padAh);
    build_wcatT_h_kernel<<<(1024 * KPAD_F + 255) / 256, 256>>>(W_i, W_o, wcatTh);
    build_wcombT_h_kernel<<<(4096 * HIDDEN + 255) / 256, 256>>>(W_fi, wcombTh);
    dim3 tb(32, 8);
    transpose_pad_h_kernel<<<dim3(HIDDEN / 32, HIDDEN / 32), tb>>>(W_h, whTh, HIDDEN, HIDDEN, HIDDEN);
    transpose_pad_h_kernel<<<dim3(HIDDEN / 32, HIDDEN / 32), tb>>>(W_o + ATOM_FDIM * HIDDEN, wo2Th, HIDDEN, HIDDEN, HIDDEN);
    transpose_pad_h_kernel<<<dim3(FFN1 / 32, HIDDEN / 32), tb>>>(W_fi + (size_t)512 * FFN1, wmTh, HIDDEN, FFN1, HIDDEN);
    transpose_pad_h_kernel<<<dim3(FFN2 / 32, FFN1 / 32), tb>>>(W_f1, wf1Th, FFN1, FFN2, FFN1);
    seg_bounds_kernel<<<(N_MOLS + 256) / 256, 256>>>(mol_ids);

    const int MT = (N_ATOMS + BM - 1) / BM;  // 782

    // 1+5. [inp | ah_partial] = padA @ Wcat              -> cath [N,1024] half
    hgemm<MODE_N, false, false, false, false, true><<<dim3(1024 / BN, MT), 256, SMEM_BYTES>>>(
        N_ATOMS, 1024, KPAD_F, KPAD_F, KPAD_F, 0, 1024, padAh, wcatTh,
        nullptr, nullptr, cath, nullptr, nullptr);
    // 2. bufBh = sum_j relu(inp[nei])
    gather_sum_h_kernel<<<N_ATOMS, 64>>>(cath, 1024, a_nei, bufBh, 1);
    // 3. msg2 = relu(inp + bufBh @ W_h)                  -> bufCh half
    hgemm<MODE_N, true, true, true, false, true><<<dim3(HIDDEN / BN, MT), 256, SMEM_BYTES>>>(
        N_ATOMS, HIDDEN, HIDDEN, HIDDEN, HIDDEN, 1024, HIDDEN, bufBh, whTh,
        cath, nullptr, bufCh, nullptr, nullptr);
    // 4. bufBh = sum_j msg2[nei]
    gather_sum_h_kernel<<<N_ATOMS, 64>>>(bufCh, HIDDEN, a_nei, bufBh, 0);
    // 6. atom_hiddens = relu(ah_partial + bufBh @ W_o_bot + b_o) -> bufCh half
    hgemm<MODE_N, true, true, true, true, true><<<dim3(HIDDEN / BN, MT), 256, SMEM_BYTES>>>(
        N_ATOMS, HIDDEN, HIDDEN, HIDDEN, HIDDEN, 1024, HIDDEN, bufBh, wo2Th,
        cath + HIDDEN, b_o, bufCh, nullptr, nullptr);
    // 7-8. sorted-segment mean (no atomics): sums, cnt, mvh
    seg_reduce_kernel<<<dim3(N_MOLS, HIDDEN / 128), 128>>>(bufCh);
    // 9a. U = mv @ [(Ws+W1) | (Ws+W2)]                    -> g_U [M,4096] fp32
    hgemm<MODE_N, false, false, false, false, false><<<dim3(4096 / BN, N_MOLS / BM), 256, SMEM_BYTES>>>(
        N_MOLS, 4096, HIDDEN, HIDDEN, HIDDEN, 0, 4096, mvh, wcombTh,
        nullptr, nullptr, Up, nullptr, nullptr);
    // 9b. prod[p] = mv[a]*mv[b]                           -> prodh half
    prod_kernel<<<N_PAIRS, 128>>>(edges);
    // 10. fused: h1 = relu(prod @ Wm + U1[a] + U2[b] + b_fi) -> h1h half
    hgemm<MODE_PAIR, true, false, false, true, true><<<dim3(FFN1 / BN, N_PAIRS / BM), 256, SMEM_BYTES>>>(
        N_PAIRS, FFN1, HIDDEN, HIDDEN, HIDDEN, FFN1, FFN1, prodh, wmTh,
        nullptr, b_fi, h1h, edges, Up);
    // 11. h2 = relu(h1 @ W_ffn_1 + b_ffn_1)               -> g_h2 fp32
    hgemm<MODE_N, true, false, false, true, false><<<dim3(FFN2 / BN, N_PAIRS / BM), 256, SMEM_BYTES>>>(
        N_PAIRS, FFN2, FFN1, FFN1, FFN1, 0, FFN2, h1h, wf1Th,
        nullptr, b_f1, h2p, nullptr, nullptr);
    // 12. out = sigmoid(h2 . W_ffn_2 + b_ffn_2)
    ffn_last_kernel<<<N_PAIRS, 128>>>(h2p, W_f2, b_f2, out);
}

// round 12
// speedup vs baseline: 6.8914x; 1.0487x over previous
#include <cuda_runtime.h>
#include <cuda_fp16.h>
#include <math.h>
#include <stdint.h>

#define N_ATOMS   100000
#define ATOM_FDIM 133
#define KPAD_F    160
#define HIDDEN    512
#define K_CAT     (KPAD_F + HIDDEN)   // 672 for split-K step 6
#define MAX_NEI   6
#define N_MOLS    4096
#define N_PAIRS   8192
#define FFN1      2048
#define FFN2      1024

#define MODE_N    0
#define MODE_PAIR 2
#define MODE_DOT  3

// ---------------- scratch (device globals: allocation-free) ----------------
__device__ alignas(16) __half g_padAh [N_ATOMS * KPAD_F];
__device__ alignas(16) __half g_inph  [N_ATOMS * HIDDEN];
__device__ alignas(16) __half g_bufBh [N_ATOMS * HIDDEN];
__device__ alignas(16) __half g_bufCh [N_ATOMS * HIDDEN];
__device__ alignas(16) __half g_h1h   [N_PAIRS * FFN1];
__device__ alignas(16) __half g_prodh [N_PAIRS * HIDDEN];
__device__ alignas(16) __half g_mvh   [N_MOLS * HIDDEN];
__device__ float g_dot [N_PAIRS];
__device__ float g_sums[N_MOLS * HIDDEN];
__device__ float g_cnt [N_MOLS];
__device__ float g_U   [N_MOLS * 4096];
__device__ int   g_segStart[N_MOLS + 1];
// transposed half weights [N][K] (K-contiguous)
__device__ alignas(16) __half g_WiTh   [HIDDEN * KPAD_F];
__device__ alignas(16) __half g_WoCatTh[HIDDEN * K_CAT];
__device__ alignas(16) __half g_WhTh   [HIDDEN * HIDDEN];
__device__ alignas(16) __half g_WcombTh[4096 * HIDDEN];
__device__ alignas(16) __half g_WmTh   [FFN1 * HIDDEN];
__device__ alignas(16) __half g_Wf1Th  [FFN2 * FFN1];

// ---------------- PTX helpers ----------------------------------------------
__device__ __forceinline__ uint32_t smem_u32(const void* p) {
    return (uint32_t)__cvta_generic_to_shared(p);
}
__device__ __forceinline__ void cp16(uint32_t s, const void* g, uint32_t bytes) {
    asm volatile("cp.async.cg.shared.global [%0], [%1], 16, %2;\n"
                 :: "r"(s), "l"(g), "r"(bytes));
}
__device__ __forceinline__ void cp_commit() {
    asm volatile("cp.async.commit_group;\n" ::: "memory");
}
template <int N>
__device__ __forceinline__ void cp_wait() {
    asm volatile("cp.async.wait_group %0;\n" :: "n"(N) : "memory");
}
__device__ __forceinline__ void ldsm4(uint32_t* r, uint32_t addr) {
    asm volatile("ldmatrix.sync.aligned.m8n8.x4.shared.b16 {%0,%1,%2,%3}, [%4];\n"
                 : "=r"(r[0]), "=r"(r[1]), "=r"(r[2]), "=r"(r[3]) : "r"(addr));
}
__device__ __forceinline__ void mma_f16(float* c, const uint32_t* a,
                                        uint32_t b0, uint32_t b1) {
    asm volatile(
        "mma.sync.aligned.m16n8k16.row.col.f32.f16.f16.f32 "
        "{%0,%1,%2,%3}, {%4,%5,%6,%7}, {%8,%9}, {%0,%1,%2,%3};\n"
        : "+f"(c[0]), "+f"(c[1]), "+f"(c[2]), "+f"(c[3])
        : "r"(a[0]), "r"(a[1]), "r"(a[2]), "r"(a[3]), "r"(b0), "r"(b1));
}

// ---------------- GEMM tile config ------------------------------------------
#define BM 128
#define BN 128
#define BK 32
#define STAGES 4
#define AT 40                                 // halves per smem row (pad 8)
#define A_H (BM * AT)                         // 5120 halves
#define STAGE_H (2 * A_H)
#define STAGE_BYTES (STAGE_H * 2)             // 20480
#define SMEM_BYTES (STAGES * STAGE_BYTES)     // 81920

// ---------------- fp16 mma GEMM: C = [A1|A2][MxK] @ BT[NxK]^T ---------------
// A chunks with k < K1 come from A1 (ld=lda1), k >= K1 from A2 (ld=lda2).
// MODE_DOT: instead of storing, accumulate sum(relu(v)*W2[col]) into dot[row].
template <int MODE, bool RELU, bool ADDC, bool CINH, bool BIAS, bool OUTH>
__global__ __launch_bounds__(256, 2)
void hgemm(int M, int N, int K, int K1, int lda1, int lda2, int ldb,
           int ldcin, int ldc,
           const __half* __restrict__ A1, const __half* __restrict__ A2,
           const __half* __restrict__ BT,
           const void* __restrict__ Cin, const float* __restrict__ bias,
           void* __restrict__ Cout,
           const int* __restrict__ idx, const float* __restrict__ U)
{
    extern __shared__ __half sm[];
    const uint32_t sbase = smem_u32(sm);
    const int tid = threadIdx.x;
    const int lane = tid & 31, wid = tid >> 5;
    const int wm = wid & 3, wn = wid >> 2;     // warp grid 4 x 2
    const int gid = lane >> 2, tig = lane & 3;
    const int rowBase = blockIdx.y * BM;
    const int colBase = blockIdx.x * BN;
    const int nk = K / BK;

    const __half* aPtr1[2]; const __half* aPtr2[2];
    uint32_t aSm[2]; uint32_t aBytes[2];
    const __half* bPtr[2]; uint32_t bSm[2];
#pragma unroll
    for (int j = 0; j < 2; j++) {
        int idx2 = tid + j * 256;
        int row = idx2 >> 2, c = idx2 & 3;
        int grow = rowBase + row;
        int crow = grow < M ? grow : 0;
        aPtr1[j]  = A1 + (size_t)crow * lda1 + c * 8;
        aPtr2[j]  = A2 + (size_t)crow * lda2 + c * 8;
        aSm[j]    = sbase + (uint32_t)(row * AT + c * 8) * 2;
        aBytes[j] = grow < M ? 16u : 0u;
        bPtr[j] = BT + (size_t)(colBase + row) * ldb + c * 8;
        bSm[j]  = sbase + (uint32_t)(A_H + row * AT + c * 8) * 2;
    }

    auto load_stage = [&](int stg, int kc0) {
        const uint32_t so = (uint32_t)stg * STAGE_BYTES;
#pragma unroll
        for (int j = 0; j < 2; j++) {
            const __half* src = (kc0 < K1) ? (aPtr1[j] + kc0)
                                           : (aPtr2[j] + (kc0 - K1));
            cp16(aSm[j] + so, src, aBytes[j]);
        }
#pragma unroll
        for (int j = 0; j < 2; j++)
            cp16(bSm[j] + so, bPtr[j] + kc0, 16u);
        cp_commit();
    };

    const int lr = lane & 15, lc = lane >> 4;
    uint32_t aLd[2], bLd[4];
#pragma unroll
    for (int mt = 0; mt < 2; mt++)
        aLd[mt] = sbase + (uint32_t)((wm * 32 + mt * 16 + lr) * AT + lc * 8) * 2;
#pragma unroll
    for (int j = 0; j < 4; j++)
        bLd[j] = sbase + (uint32_t)(A_H + (wn * 64 + j * 16 + lr) * AT + lc * 8) * 2;

    float acc[2][8][4];
#pragma unroll
    for (int mt = 0; mt < 2; mt++)
#pragma unroll
        for (int nt = 0; nt < 8; nt++)
#pragma unroll
            for (int i = 0; i < 4; i++) acc[mt][nt][i] = 0.f;

    load_stage(0, 0);
    if (nk > 1) load_stage(1, BK);
    if (nk > 2) load_stage(2, 2 * BK);

    int buf = 0;
    for (int kt = 0; kt < nk; kt++) {
        if (kt == nk - 1)      cp_wait<0>();
        else if (kt == nk - 2) cp_wait<1>();
        else                   cp_wait<2>();
        __syncthreads();
        if (kt + 3 < nk)
            load_stage((buf + 3) % STAGES, (kt + 3) * BK);

        const uint32_t so = (uint32_t)buf * STAGE_BYTES;
        uint32_t af[2][2][4], bf[2][4][4];
#pragma unroll
        for (int ks = 0; ks < 2; ks++) {
            const uint32_t ko = so + ks * 32;
            ldsm4(af[ks][0], aLd[0] + ko);
            ldsm4(af[ks][1], aLd[1] + ko);
#pragma unroll
            for (int j = 0; j < 4; j++)
                ldsm4(bf[ks][j], bLd[j] + ko);
        }
#pragma unroll
        for (int ks = 0; ks < 2; ks++)
#pragma unroll
            for (int mt = 0; mt < 2; mt++)
#pragma unroll
                for (int j = 0; j < 4; j++) {
                    mma_f16(acc[mt][2 * j],     af[ks][mt], bf[ks][j][0], bf[ks][j][2]);
                    mma_f16(acc[mt][2 * j + 1], af[ks][mt], bf[ks][j][1], bf[ks][j][3]);
                }
        buf = (buf + 1) % STAGES;
    }

    // ---- epilogue ----
#pragma unroll
    for (int mt = 0; mt < 2; mt++) {
#pragma unroll
        for (int h = 0; h < 2; h++) {
            const int row = rowBase + wm * 32 + mt * 16 + gid + h * 8;
            if (row >= M) continue;
            int e0 = 0, e1 = 0;
            if (MODE == MODE_PAIR) { e0 = __ldg(&idx[row]); e1 = __ldg(&idx[N_PAIRS + row]); }
            float dpart = 0.f;
#pragma unroll
            for (int nt = 0; nt < 8; nt++) {
                const int gc = colBase + wn * 64 + nt * 8 + tig * 2;
                float2 v = make_float2(acc[mt][nt][2 * h], acc[mt][nt][2 * h + 1]);
                if (BIAS) {
                    const float2 bb = *(const float2*)(bias + gc);
                    v.x += bb.x; v.y += bb.y;
                }
                if (ADDC) {
                    float2 ci;
                    if (CINH) {
                        __half2 c2 = *(const __half2*)((const __half*)Cin + (size_t)row * ldcin + gc);
                        ci = __half22float2(c2);
                    } else {
                        ci = *(const float2*)((const float*)Cin + (size_t)row * ldcin + gc);
                    }
                    v.x += ci.x; v.y += ci.y;
                }
                if (MODE == MODE_PAIR) {
                    const float2 u1 = *(const float2*)(U + (size_t)e0 * 4096 + gc);
                    const float2 u2 = *(const float2*)(U + (size_t)e1 * 4096 + FFN1 + gc);
                    v.x += u1.x + u2.x; v.y += u1.y + u2.y;
                }
                if (RELU) { v.x = fmaxf(v.x, 0.f); v.y = fmaxf(v.y, 0.f); }
                if (MODE == MODE_DOT) {
                    const float2 w2 = *(const float2*)(U + gc);
                    dpart += v.x * w2.x + v.y * w2.y;
                } else if (OUTH) {
                    *(__half2*)((__half*)Cout + (size_t)row * ldc + gc) = __floats2half2_rn(v.x, v.y);
                } else {
                    *(float2*)((float*)Cout + (size_t)row * ldc + gc) = v;
                }
            }
            if (MODE == MODE_DOT) {
                dpart += __shfl_xor_sync(0xffffffffu, dpart, 1);
                dpart += __shfl_xor_sync(0xffffffffu, dpart, 2);
                if (tig == 0) atomicAdd((float*)Cout + row, dpart);
            }
        }
    }
}

// ---------------- prep kernels ----------------------------------------------
__global__ void pad_atoms_h_kernel(const float* __restrict__ f, __half* __restrict__ out) {
    int idx = blockIdx.x * blockDim.x + threadIdx.x;
    if (idx >= N_ATOMS * KPAD_F) return;
    int a = idx / KPAD_F, k = idx - a * KPAD_F;
    out[idx] = __float2half((k < ATOM_FDIM) ? f[a * ATOM_FDIM + k] : 0.f);
}

__global__ void transpose_pad_h_kernel(const float* __restrict__ W, __half* __restrict__ WT,
                                       int K, int N, int Kpad) {
    __shared__ float t[32][33];
    int kb = blockIdx.y * 32, nb = blockIdx.x * 32;
    int tx = threadIdx.x, ty = threadIdx.y;
#pragma unroll
    for (int i = 0; i < 4; i++) {
        int kk = kb + ty + i * 8;
        t[ty + i * 8][tx] = (kk < K) ? W[(size_t)kk * N + nb + tx] : 0.f;
    }
    __syncthreads();
#pragma unroll
    for (int i = 0; i < 4; i++) {
        int n = nb + ty + i * 8;
        WT[(size_t)n * Kpad + kb + tx] = __float2half(t[tx][ty + i * 8]);
    }
}

// WoCatT[n][k], k<672: k<160 -> (k<133 ? Wo[k][n] : 0); k>=160 -> Wo[k-27][n]
__global__ void build_woCatT_h_kernel(const float* __restrict__ Wo,
                                      __half* __restrict__ out) {
    int idx = blockIdx.x * blockDim.x + threadIdx.x;
    if (idx >= HIDDEN * K_CAT) return;
    int n = idx / K_CAT, k = idx - n * K_CAT;
    float v = 0.f;
    if (k < KPAD_F) {
        if (k < ATOM_FDIM) v = Wo[(size_t)k * HIDDEN + n];
    } else {
        v = Wo[(size_t)(k - KPAD_F + ATOM_FDIM) * HIDDEN + n];
    }
    out[idx] = __float2half(v);
}

__global__ void build_wcombT_h_kernel(const float* __restrict__ Wfi,
                                      __half* __restrict__ out) {
    int idx = blockIdx.x * blockDim.x + threadIdx.x;
    if (idx >= 4096 * HIDDEN) return;
    int n = idx / HIDDEN, k = idx - n * HIDDEN;
    float v;
    if (n < FFN1)
        v = Wfi[(size_t)k * FFN1 + n] + Wfi[(size_t)(1024 + k) * FFN1 + n];
    else {
        int n2 = n - FFN1;
        v = Wfi[(size_t)k * FFN1 + n2] + Wfi[(size_t)(1536 + k) * FFN1 + n2];
    }
    out[idx] = __float2half(v);
}

// ---------------- neighbor gather-sum (half) --------------------------------
__global__ void gather_sum_h_kernel(const __half* __restrict__ src, int srcStride,
                                    const int* __restrict__ nei,
                                    __half* __restrict__ dst, int relu_src)
{
    int atom = blockIdx.x;
    int c = threadIdx.x;  // 0..63
    const int* nrow = nei + atom * MAX_NEI;
    float2 acc[4] = {{0.f,0.f},{0.f,0.f},{0.f,0.f},{0.f,0.f}};
#pragma unroll
    for (int j = 0; j < MAX_NEI; j++) {
        int n = __ldg(&nrow[j]);
        uint4 v = __ldg((const uint4*)(src + (size_t)n * srcStride) + c);
        uint32_t w[4] = {v.x, v.y, v.z, v.w};
#pragma unroll
        for (int i = 0; i < 4; i++) {
            float2 f = __half22float2(*(__half2*)&w[i]);
            if (relu_src) { f.x = fmaxf(f.x, 0.f); f.y = fmaxf(f.y, 0.f); }
            acc[i].x += f.x; acc[i].y += f.y;
        }
    }
    uint4 o;
    uint32_t* ow = (uint32_t*)&o;
#pragma unroll
    for (int i = 0; i < 4; i++) {
        __half2 h = __floats2half2_rn(acc[i].x, acc[i].y);
        ow[i] = *(uint32_t*)&h;
    }
    ((uint4*)(dst + (size_t)atom * HIDDEN))[c] = o;
}

// ---------------- sorted-segment mean ---------------------------------------
__global__ void seg_bounds_kernel(const int* __restrict__ mol_ids)
{
    int m = blockIdx.x * blockDim.x + threadIdx.x;
    if (m > N_MOLS) return;
    if (m == N_MOLS) { g_segStart[N_MOLS] = N_ATOMS; return; }
    int lo = 0, hi = N_ATOMS;
    while (lo < hi) {
        int mid = (lo + hi) >> 1;
        if (__ldg(&mol_ids[mid]) < m) lo = mid + 1; else hi = mid;
    }
    g_segStart[m] = lo;
}

__global__ void seg_reduce_kernel(const __half* __restrict__ ah)
{
    int m = blockIdx.x;
    int col = blockIdx.y * 128 + threadIdx.x;
    int s = __ldg(&g_segStart[m]);
    int e = __ldg(&g_segStart[m + 1]);
    float acc = 0.f;
    for (int r = s; r < e; r++)
        acc += __half2float(__ldg(&ah[(size_t)r * HIDDEN + col]));
    g_sums[(size_t)m * HIDDEN + col] = acc;
    float inv = 1.f / fmaxf((float)(e - s), 1.f);
    g_mvh[(size_t)m * HIDDEN + col] = __float2half(acc * inv);
    if (threadIdx.x == 0 && blockIdx.y == 0) g_cnt[m] = (float)(e - s);
}

// prod[p] = (sums[a]*inv_a)*(sums[b]*inv_b) (half out); also zero g_dot[p]
__global__ void prod_kernel(const int* __restrict__ edges)
{
    int p = blockIdx.x;
    int a = __ldg(&edges[p]);
    int b = __ldg(&edges[N_PAIRS + p]);
    float ia = 1.f / fmaxf(__ldg(&g_cnt[a]), 1.f);
    float ib = 1.f / fmaxf(__ldg(&g_cnt[b]), 1.f);
    int c = threadIdx.x;
    float4 va = __ldg((const float4*)(g_sums + (size_t)a * HIDDEN) + c);
    float4 vb = __ldg((const float4*)(g_sums + (size_t)b * HIDDEN) + c);
    va.x *= ia; va.y *= ia; va.z *= ia; va.w *= ia;
    vb.x *= ib; vb.y *= ib; vb.z *= ib; vb.w *= ib;
    __half2 h0 = __floats2half2_rn(va.x * vb.x, va.y * vb.y);
    __half2 h1 = __floats2half2_rn(va.z * vb.z, va.w * vb.w);
    uint2 o = make_uint2(*(uint32_t*)&h0, *(uint32_t*)&h1);
    ((uint2*)(g_prodh + (size_t)p * HIDDEN))[c] = o;
    if (c == 0) g_dot[p] = 0.f;
}

// out = sigmoid(dot + b_f2)
__global__ void sigmoid_kernel(const float* __restrict__ b2, float* __restrict__ out)
{
    int p = blockIdx.x * blockDim.x + threadIdx.x;
    if (p >= N_PAIRS) return;
    out[p] = 1.f / (1.f + expf(-(g_dot[p] + b2[0])));
}

// ---------------- launch ----------------------------------------------------
extern "C" void kernel_launch(void* const* d_in, const int* in_sizes, int n_in,
                              void* d_out, int out_size)
{
    const float* f_atoms = (const float*)d_in[0];
    const int*   a_nei   = (const int*)d_in[1];
    const int*   mol_ids = (const int*)d_in[2];
    const int*   edges   = (const int*)d_in[3];
    const float* W_i     = (const float*)d_in[4];
    const float* W_h     = (const float*)d_in[5];
    const float* W_o     = (const float*)d_in[6];
    const float* b_o     = (const float*)d_in[7];
    const float* W_fi    = (const float*)d_in[8];
    const float* b_fi    = (const float*)d_in[9];
    const float* W_f1    = (const float*)d_in[10];
    const float* b_f1    = (const float*)d_in[11];
    const float* W_f2    = (const float*)d_in[12];
    const float* b_f2    = (const float*)d_in[13];
    float* out = (float*)d_out;

    __half *padAh, *inph, *bufBh, *bufCh, *h1h, *prodh, *mvh;
    __half *wiT, *woCatT, *whT, *wcombT, *wmT, *wf1T;
    float *Up, *dotp;
    cudaGetSymbolAddress((void**)&padAh,  g_padAh);
    cudaGetSymbolAddress((void**)&inph,   g_inph);
    cudaGetSymbolAddress((void**)&bufBh,  g_bufBh);
    cudaGetSymbolAddress((void**)&bufCh,  g_bufCh);
    cudaGetSymbolAddress((void**)&h1h,    g_h1h);
    cudaGetSymbolAddress((void**)&prodh,  g_prodh);
    cudaGetSymbolAddress((void**)&mvh,    g_mvh);
    cudaGetSymbolAddress((void**)&wiT,    g_WiTh);
    cudaGetSymbolAddress((void**)&woCatT, g_WoCatTh);
    cudaGetSymbolAddress((void**)&whT,    g_WhTh);
    cudaGetSymbolAddress((void**)&wcombT, g_WcombTh);
    cudaGetSymbolAddress((void**)&wmT,    g_WmTh);
    cudaGetSymbolAddress((void**)&wf1T,   g_Wf1Th);
    cudaGetSymbolAddress((void**)&Up,     g_U);
    cudaGetSymbolAddress((void**)&dotp,   g_dot);

    cudaFuncSetAttribute(hgemm<MODE_N, false, false, false, false, true>,
                         cudaFuncAttributeMaxDynamicSharedMemorySize, SMEM_BYTES);
    cudaFuncSetAttribute(hgemm<MODE_N, true, true, true, false, true>,
                         cudaFuncAttributeMaxDynamicSharedMemorySize, SMEM_BYTES);
    cudaFuncSetAttribute(hgemm<MODE_N, true, false, false, true, true>,
                         cudaFuncAttributeMaxDynamicSharedMemorySize, SMEM_BYTES);
    cudaFuncSetAttribute(hgemm<MODE_N, false, false, false, false, false>,
                         cudaFuncAttributeMaxDynamicSharedMemorySize, SMEM_BYTES);
    cudaFuncSetAttribute(hgemm<MODE_PAIR, true, false, false, true, true>,
                         cudaFuncAttributeMaxDynamicSharedMemorySize, SMEM_BYTES);
    cudaFuncSetAttribute(hgemm<MODE_DOT, true, false, false, true, false>,
                         cudaFuncAttributeMaxDynamicSharedMemorySize, SMEM_BYTES);

    const int MT = (N_ATOMS + BM - 1) / BM;  // 782
    dim3 tb(32, 8);

    // launches 0-4: preps needed by GEMM1 (so GEMM1 is launch #5, ncu -s 5)
    pad_atoms_h_kernel<<<(N_ATOMS * KPAD_F + 255) / 256, 256>>>(f_atoms, padAh);
    transpose_pad_h_kernel<<<dim3(HIDDEN / 32, KPAD_F / 32), tb>>>(W_i, wiT, ATOM_FDIM, HIDDEN, KPAD_F);
    build_woCatT_h_kernel<<<(HIDDEN * K_CAT + 255) / 256, 256>>>(W_o, woCatT);
    transpose_pad_h_kernel<<<dim3(HIDDEN / 32, HIDDEN / 32), tb>>>(W_h, whT, HIDDEN, HIDDEN, HIDDEN);
    build_wcombT_h_kernel<<<(4096 * HIDDEN + 255) / 256, 256>>>(W_fi, wcombT);

    // launch 5 (ncu-captured): 1. inp = padA @ W_i        -> inph [N,512] half
    hgemm<MODE_N, false, false, false, false, true><<<dim3(HIDDEN / BN, MT), 256, SMEM_BYTES>>>(
        N_ATOMS, HIDDEN, KPAD_F, KPAD_F, KPAD_F, KPAD_F, KPAD_F, 0, HIDDEN,
        padAh, padAh, wiT, nullptr, nullptr, inph, nullptr, nullptr);

    // remaining preps
    transpose_pad_h_kernel<<<dim3(FFN1 / 32, HIDDEN / 32), tb>>>(W_fi + (size_t)512 * FFN1, wmT, HIDDEN, FFN1, HIDDEN);
    transpose_pad_h_kernel<<<dim3(FFN2 / 32, FFN1 / 32), tb>>>(W_f1, wf1T, FFN1, FFN2, FFN1);
    seg_bounds_kernel<<<(N_MOLS + 256) / 256, 256>>>(mol_ids);

    // 2. bufBh = sum_j relu(inp[nei])
    gather_sum_h_kernel<<<N_ATOMS, 64>>>(inph, HIDDEN, a_nei, bufBh, 1);
    // 3. msg2 = relu(inp + bufBh @ W_h)                  -> bufCh half
    hgemm<MODE_N, true, true, true, false, true><<<dim3(HIDDEN / BN, MT), 256, SMEM_BYTES>>>(
        N_ATOMS, HIDDEN, HIDDEN, HIDDEN, HIDDEN, HIDDEN, HIDDEN, HIDDEN, HIDDEN,
        bufBh, bufBh, whT, inph, nullptr, bufCh, nullptr, nullptr);
    // 4. bufBh = sum_j msg2[nei]
    gather_sum_h_kernel<<<N_ATOMS, 64>>>(bufCh, HIDDEN, a_nei, bufBh, 0);
    // 6. atom_hiddens = relu([padA | bufBh] @ WoCat + b_o) -> bufCh (split-K)
    hgemm<MODE_N, true, false, false, true, true><<<dim3(HIDDEN / BN, MT), 256, SMEM_BYTES>>>(
        N_ATOMS, HIDDEN, K_CAT, KPAD_F, KPAD_F, HIDDEN, K_CAT, 0, HIDDEN,
        padAh, bufBh, woCatT, nullptr, b_o, bufCh, nullptr, nullptr);
    // 7-8. sorted-segment mean (no atomics): sums, cnt, mvh
    seg_reduce_kernel<<<dim3(N_MOLS, HIDDEN / 128), 128>>>(bufCh);
    // 9a. U = mv @ [(Ws+W1) | (Ws+W2)]                    -> g_U [M,4096] fp32
    hgemm<MODE_N, false, false, false, false, false><<<dim3(4096 / BN, N_MOLS / BM), 256, SMEM_BYTES>>>(
        N_MOLS, 4096, HIDDEN, HIDDEN, HIDDEN, HIDDEN, HIDDEN, 0, 4096,
        mvh, mvh, wcombT, nullptr, nullptr, Up, nullptr, nullptr);
    // 9b. prod[p] = mv[a]*mv[b] (+ zero dot)              -> prodh half
    prod_kernel<<<N_PAIRS, 128>>>(edges);
    // 10. fused: h1 = relu(prod @ Wm + U1[a] + U2[b] + b_fi) -> h1h half
    hgemm<MODE_PAIR, true, false, false, true, true><<<dim3(FFN1 / BN, N_PAIRS / BM), 256, SMEM_BYTES>>>(
        N_PAIRS, FFN1, HIDDEN, HIDDEN, HIDDEN, HIDDEN, HIDDEN, FFN1, FFN1,
        prodh, prodh, wmT, nullptr, b_fi, h1h, edges, Up);
    // 11+12a. dot[p] += relu(h1 @ W_f1 + b_f1) . W_f2     (fused dot epilogue)
    hgemm<MODE_DOT, true, false, false, true, false><<<dim3(FFN2 / BN, N_PAIRS / BM), 256, SMEM_BYTES>>>(
        N_PAIRS, FFN2, FFN1, FFN1, FFN1, FFN1, FFN1, 0, FFN2,
        h1h, h1h, wf1T, nullptr, b_f1, dotp, nullptr, W_f2);
    // 12b. out = sigmoid(dot + b_f2)
    sigmoid_kernel<<<(N_PAIRS + 255) / 256, 256>>>(b_f2, out);
}

// round 13
// speedup vs baseline: 6.9615x; 1.0102x over previous
#include <cuda_runtime.h>
#include <cuda_fp16.h>
#include <math.h>
#include <stdint.h>

#define N_ATOMS   100000
#define ATOM_FDIM 133
#define KPAD_F    160
#define HIDDEN    512
#define K_CAT     (KPAD_F + HIDDEN)   // 672 for split-K step 6
#define MAX_NEI   6
#define N_MOLS    4096
#define N_PAIRS   8192
#define FFN1      2048
#define FFN2      1024

#define MODE_N    0
#define MODE_PAIR 2
#define MODE_DOT  3

// ---------------- scratch (device globals: allocation-free) ----------------
__device__ alignas(16) __half g_padAh [N_ATOMS * KPAD_F];
__device__ alignas(16) __half g_inph  [N_ATOMS * HIDDEN];
__device__ alignas(16) __half g_bufBh [N_ATOMS * HIDDEN];
__device__ alignas(16) __half g_bufCh [N_ATOMS * HIDDEN];
__device__ alignas(16) __half g_h1h   [N_PAIRS * FFN1];
__device__ alignas(16) __half g_prodh [N_PAIRS * HIDDEN];
__device__ alignas(16) __half g_mvh   [N_MOLS * HIDDEN];
__device__ alignas(16) __half g_Uh    [N_MOLS * 4096];
__device__ float g_dot [N_PAIRS];
__device__ float g_sums[N_MOLS * HIDDEN];
__device__ float g_cnt [N_MOLS];
__device__ int   g_segStart[N_MOLS + 1];
// transposed half weights [N][K] (K-contiguous)
__device__ alignas(16) __half g_WiTh   [HIDDEN * KPAD_F];
__device__ alignas(16) __half g_WoCatTh[HIDDEN * K_CAT];
__device__ alignas(16) __half g_WhTh   [HIDDEN * HIDDEN];
__device__ alignas(16) __half g_WcombTh[4096 * HIDDEN];
__device__ alignas(16) __half g_WmTh   [FFN1 * HIDDEN];
__device__ alignas(16) __half g_Wf1Th  [FFN2 * FFN1];

// ---------------- PTX helpers ----------------------------------------------
__device__ __forceinline__ uint32_t smem_u32(const void* p) {
    return (uint32_t)__cvta_generic_to_shared(p);
}
__device__ __forceinline__ void cp16(uint32_t s, const void* g, uint32_t bytes) {
    asm volatile("cp.async.cg.shared.global [%0], [%1], 16, %2;\n"
                 :: "r"(s), "l"(g), "r"(bytes));
}
__device__ __forceinline__ void cp_commit() {
    asm volatile("cp.async.commit_group;\n" ::: "memory");
}
template <int N>
__device__ __forceinline__ void cp_wait() {
    asm volatile("cp.async.wait_group %0;\n" :: "n"(N) : "memory");
}
__device__ __forceinline__ void ldsm4(uint32_t* r, uint32_t addr) {
    asm volatile("ldmatrix.sync.aligned.m8n8.x4.shared.b16 {%0,%1,%2,%3}, [%4];\n"
                 : "=r"(r[0]), "=r"(r[1]), "=r"(r[2]), "=r"(r[3]) : "r"(addr));
}
__device__ __forceinline__ void mma_f16(float* c, const uint32_t* a,
                                        uint32_t b0, uint32_t b1) {
    asm volatile(
        "mma.sync.aligned.m16n8k16.row.col.f32.f16.f16.f32 "
        "{%0,%1,%2,%3}, {%4,%5,%6,%7}, {%8,%9}, {%0,%1,%2,%3};\n"
        : "+f"(c[0]), "+f"(c[1]), "+f"(c[2]), "+f"(c[3])
        : "r"(a[0]), "r"(a[1]), "r"(a[2]), "r"(a[3]), "r"(b0), "r"(b1));
}

// ---------------- GEMM tile config ------------------------------------------
#define BM 128
#define BN 128
#define BK 32
#define STAGES 4
#define AT 40
#define A_H (BM * AT)
#define STAGE_H (2 * A_H)
#define STAGE_BYTES (STAGE_H * 2)             // 20480
#define SMEM_BYTES (STAGES * STAGE_BYTES)     // 81920

// ---------------- fp16 mma GEMM: C = [A1|A2][MxK] @ BT[NxK]^T ---------------
template <int MODE, bool RELU, bool ADDC, bool CINH, bool BIAS, bool OUTH>
__global__ __launch_bounds__(256, 2)
void hgemm(int M, int N, int K, int K1, int lda1, int lda2, int ldb,
           int ldcin, int ldc,
           const __half* __restrict__ A1, const __half* __restrict__ A2,
           const __half* __restrict__ BT,
           const void* __restrict__ Cin, const float* __restrict__ bias,
           void* __restrict__ Cout,
           const int* __restrict__ idx, const void* __restrict__ Uv)
{
    extern __shared__ __half sm[];
    const uint32_t sbase = smem_u32(sm);
    const int tid = threadIdx.x;
    const int lane = tid & 31, wid = tid >> 5;
    const int wm = wid & 3, wn = wid >> 2;
    const int gid = lane >> 2, tig = lane & 3;
    const int rowBase = blockIdx.y * BM;
    const int colBase = blockIdx.x * BN;
    const int nk = K / BK;

    const __half* aPtr1[2]; const __half* aPtr2[2];
    uint32_t aSm[2]; uint32_t aBytes[2];
    const __half* bPtr[2]; uint32_t bSm[2];
#pragma unroll
    for (int j = 0; j < 2; j++) {
        int idx2 = tid + j * 256;
        int row = idx2 >> 2, c = idx2 & 3;
        int grow = rowBase + row;
        int crow = grow < M ? grow : 0;
        aPtr1[j]  = A1 + (size_t)crow * lda1 + c * 8;
        aPtr2[j]  = A2 + (size_t)crow * lda2 + c * 8;
        aSm[j]    = sbase + (uint32_t)(row * AT + c * 8) * 2;
        aBytes[j] = grow < M ? 16u : 0u;
        bPtr[j] = BT + (size_t)(colBase + row) * ldb + c * 8;
        bSm[j]  = sbase + (uint32_t)(A_H + row * AT + c * 8) * 2;
    }

    auto load_stage = [&](int stg, int kc0) {
        const uint32_t so = (uint32_t)stg * STAGE_BYTES;
#pragma unroll
        for (int j = 0; j < 2; j++) {
            const __half* src = (kc0 < K1) ? (aPtr1[j] + kc0)
                                           : (aPtr2[j] + (kc0 - K1));
            cp16(aSm[j] + so, src, aBytes[j]);
        }
#pragma unroll
        for (int j = 0; j < 2; j++)
            cp16(bSm[j] + so, bPtr[j] + kc0, 16u);
        cp_commit();
    };

    const int lr = lane & 15, lc = lane >> 4;
    uint32_t aLd[2], bLd[4];
#pragma unroll
    for (int mt = 0; mt < 2; mt++)
        aLd[mt] = sbase + (uint32_t)((wm * 32 + mt * 16 + lr) * AT + lc * 8) * 2;
#pragma unroll
    for (int j = 0; j < 4; j++)
        bLd[j] = sbase + (uint32_t)(A_H + (wn * 64 + j * 16 + lr) * AT + lc * 8) * 2;

    float acc[2][8][4];
#pragma unroll
    for (int mt = 0; mt < 2; mt++)
#pragma unroll
        for (int nt = 0; nt < 8; nt++)
#pragma unroll
            for (int i = 0; i < 4; i++) acc[mt][nt][i] = 0.f;

    load_stage(0, 0);
    if (nk > 1) load_stage(1, BK);
    if (nk > 2) load_stage(2, 2 * BK);

    int buf = 0;
    for (int kt = 0; kt < nk; kt++) {
        if (kt == nk - 1)      cp_wait<0>();
        else if (kt == nk - 2) cp_wait<1>();
        else                   cp_wait<2>();
        __syncthreads();
        if (kt + 3 < nk)
            load_stage((buf + 3) % STAGES, (kt + 3) * BK);

        const uint32_t so = (uint32_t)buf * STAGE_BYTES;
        uint32_t af[2][2][4], bf[2][4][4];
#pragma unroll
        for (int ks = 0; ks < 2; ks++) {
            const uint32_t ko = so + ks * 32;
            ldsm4(af[ks][0], aLd[0] + ko);
            ldsm4(af[ks][1], aLd[1] + ko);
#pragma unroll
            for (int j = 0; j < 4; j++)
                ldsm4(bf[ks][j], bLd[j] + ko);
        }
#pragma unroll
        for (int ks = 0; ks < 2; ks++)
#pragma unroll
            for (int mt = 0; mt < 2; mt++)
#pragma unroll
                for (int j = 0; j < 4; j++) {
                    mma_f16(acc[mt][2 * j],     af[ks][mt], bf[ks][j][0], bf[ks][j][2]);
                    mma_f16(acc[mt][2 * j + 1], af[ks][mt], bf[ks][j][1], bf[ks][j][3]);
                }
        buf = (buf + 1) % STAGES;
    }

    // ---- epilogue ----
#pragma unroll
    for (int mt = 0; mt < 2; mt++) {
#pragma unroll
        for (int h = 0; h < 2; h++) {
            const int row = rowBase + wm * 32 + mt * 16 + gid + h * 8;
            if (row >= M) continue;
            int e0 = 0, e1 = 0;
            if (MODE == MODE_PAIR) { e0 = __ldg(&idx[row]); e1 = __ldg(&idx[N_PAIRS + row]); }
            float dpart = 0.f;
#pragma unroll
            for (int nt = 0; nt < 8; nt++) {
                const int gc = colBase + wn * 64 + nt * 8 + tig * 2;
                float2 v = make_float2(acc[mt][nt][2 * h], acc[mt][nt][2 * h + 1]);
                if (BIAS) {
                    const float2 bb = *(const float2*)(bias + gc);
                    v.x += bb.x; v.y += bb.y;
                }
                if (ADDC) {
                    float2 ci;
                    if (CINH) {
                        __half2 c2 = *(const __half2*)((const __half*)Cin + (size_t)row * ldcin + gc);
                        ci = __half22float2(c2);
                    } else {
                        ci = *(const float2*)((const float*)Cin + (size_t)row * ldcin + gc);
                    }
                    v.x += ci.x; v.y += ci.y;
                }
                if (MODE == MODE_PAIR) {
                    const __half* Uh = (const __half*)Uv;
                    float2 u1 = __half22float2(*(const __half2*)(Uh + (size_t)e0 * 4096 + gc));
                    float2 u2 = __half22float2(*(const __half2*)(Uh + (size_t)e1 * 4096 + FFN1 + gc));
                    v.x += u1.x + u2.x; v.y += u1.y + u2.y;
                }
                if (RELU) { v.x = fmaxf(v.x, 0.f); v.y = fmaxf(v.y, 0.f); }
                if (MODE == MODE_DOT) {
                    const float2 w2 = *(const float2*)((const float*)Uv + gc);
                    dpart += v.x * w2.x + v.y * w2.y;
                } else if (OUTH) {
                    *(__half2*)((__half*)Cout + (size_t)row * ldc + gc) = __floats2half2_rn(v.x, v.y);
                } else {
                    *(float2*)((float*)Cout + (size_t)row * ldc + gc) = v;
                }
            }
            if (MODE == MODE_DOT) {
                dpart += __shfl_xor_sync(0xffffffffu, dpart, 1);
                dpart += __shfl_xor_sync(0xffffffffu, dpart, 2);
                if (tig == 0) atomicAdd((float*)Cout + row, dpart);
            }
        }
    }
}

// ---------------- mega prep: all weight prep + pad + seg bounds, 1 launch ----
// block ranges (256 threads each)
#define PB_PAD    62500                                  // pad_atoms
#define PB_WIT    (PB_PAD + (HIDDEN / 32) * (KPAD_F / 32))        // +80
#define PB_WOCAT  (PB_WIT + (HIDDEN * K_CAT) / 256)               // +1344
#define PB_WH     (PB_WOCAT + (HIDDEN / 32) * (HIDDEN / 32))      // +256
#define PB_WCOMB  (PB_WH + (4096 * HIDDEN) / 256)                 // +8192
#define PB_WM     (PB_WCOMB + (FFN1 / 32) * (HIDDEN / 32))        // +1024
#define PB_WF1    (PB_WM + (FFN2 / 32) * (FFN1 / 32))             // +2048
#define PB_SEG    (PB_WF1 + 17)                                   // +17
#define PREP_BLOCKS PB_SEG

__device__ __forceinline__ void tile_transpose(const float* __restrict__ W,
                                               __half* __restrict__ WT,
                                               int K, int N, int Kpad,
                                               int bx, int by, int tid,
                                               float (*t)[33])
{
    int kb = by * 32, nb = bx * 32;
    int tx = tid & 31, ty = tid >> 5;
#pragma unroll
    for (int i = 0; i < 4; i++) {
        int kk = kb + ty + i * 8;
        t[ty + i * 8][tx] = (kk < K) ? W[(size_t)kk * N + nb + tx] : 0.f;
    }
    __syncthreads();
#pragma unroll
    for (int i = 0; i < 4; i++) {
        int n = nb + ty + i * 8;
        WT[(size_t)n * Kpad + kb + tx] = __float2half(t[tx][ty + i * 8]);
    }
}

__global__ __launch_bounds__(256)
void mega_prep_kernel(const float* __restrict__ f_atoms,
                      const int* __restrict__ mol_ids,
                      const float* __restrict__ W_i,
                      const float* __restrict__ W_h,
                      const float* __restrict__ W_o,
                      const float* __restrict__ W_fi,
                      const float* __restrict__ W_f1)
{
    __shared__ float t[32][33];
    const int b = blockIdx.x;
    const int tid = threadIdx.x;

    if (b < PB_PAD) {
        int idx = b * 256 + tid;
        if (idx < N_ATOMS * KPAD_F) {
            int a = idx / KPAD_F, k = idx - a * KPAD_F;
            g_padAh[idx] = __float2half((k < ATOM_FDIM) ? f_atoms[a * ATOM_FDIM + k] : 0.f);
        }
    } else if (b < PB_WIT) {
        int bi = b - PB_PAD;
        tile_transpose(W_i, g_WiTh, ATOM_FDIM, HIDDEN, KPAD_F,
                       bi % (HIDDEN / 32), bi / (HIDDEN / 32), tid, t);
    } else if (b < PB_WOCAT) {
        int idx = (b - PB_WIT) * 256 + tid;
        int n = idx / K_CAT, k = idx - n * K_CAT;
        float v = 0.f;
        if (k < KPAD_F) {
            if (k < ATOM_FDIM) v = W_o[(size_t)k * HIDDEN + n];
        } else {
            v = W_o[(size_t)(k - KPAD_F + ATOM_FDIM) * HIDDEN + n];
        }
        g_WoCatTh[idx] = __float2half(v);
    } else if (b < PB_WH) {
        int bi = b - PB_WOCAT;
        tile_transpose(W_h, g_WhTh, HIDDEN, HIDDEN, HIDDEN,
                       bi % (HIDDEN / 32), bi / (HIDDEN / 32), tid, t);
    } else if (b < PB_WCOMB) {
        int idx = (b - PB_WH) * 256 + tid;
        int n = idx / HIDDEN, k = idx - n * HIDDEN;
        float v;
        if (n < FFN1)
            v = W_fi[(size_t)k * FFN1 + n] + W_fi[(size_t)(1024 + k) * FFN1 + n];
        else {
            int n2 = n - FFN1;
            v = W_fi[(size_t)k * FFN1 + n2] + W_fi[(size_t)(1536 + k) * FFN1 + n2];
        }
        g_WcombTh[idx] = __float2half(v);
    } else if (b < PB_WM) {
        int bi = b - PB_WCOMB;
        tile_transpose(W_fi + (size_t)512 * FFN1, g_WmTh, HIDDEN, FFN1, HIDDEN,
                       bi % (FFN1 / 32), bi / (FFN1 / 32), tid, t);
    } else if (b < PB_WF1) {
        int bi = b - PB_WM;
        tile_transpose(W_f1, g_Wf1Th, FFN1, FFN2, FFN1,
                       bi % (FFN2 / 32), bi / (FFN2 / 32), tid, t);
    } else {
        int m = (b - PB_WF1) * 256 + tid;
        if (m <= N_MOLS) {
            if (m == N_MOLS) { g_segStart[N_MOLS] = N_ATOMS; return; }
            int lo = 0, hi = N_ATOMS;
            while (lo < hi) {
                int mid = (lo + hi) >> 1;
                if (__ldg(&mol_ids[mid]) < m) lo = mid + 1; else hi = mid;
            }
            g_segStart[m] = lo;
        }
    }
}

// ---------------- neighbor gather-sum (half) --------------------------------
__global__ void gather_sum_h_kernel(const __half* __restrict__ src, int srcStride,
                                    const int* __restrict__ nei,
                                    __half* __restrict__ dst, int relu_src)
{
    int atom = blockIdx.x;
    int c = threadIdx.x;  // 0..63
    const int* nrow = nei + atom * MAX_NEI;
    float2 acc[4] = {{0.f,0.f},{0.f,0.f},{0.f,0.f},{0.f,0.f}};
#pragma unroll
    for (int j = 0; j < MAX_NEI; j++) {
        int n = __ldg(&nrow[j]);
        uint4 v = __ldg((const uint4*)(src + (size_t)n * srcStride) + c);
        uint32_t w[4] = {v.x, v.y, v.z, v.w};
#pragma unroll
        for (int i = 0; i < 4; i++) {
            float2 f = __half22float2(*(__half2*)&w[i]);
            if (relu_src) { f.x = fmaxf(f.x, 0.f); f.y = fmaxf(f.y, 0.f); }
            acc[i].x += f.x; acc[i].y += f.y;
        }
    }
    uint4 o;
    uint32_t* ow = (uint32_t*)&o;
#pragma unroll
    for (int i = 0; i < 4; i++) {
        __half2 h = __floats2half2_rn(acc[i].x, acc[i].y);
        ow[i] = *(uint32_t*)&h;
    }
    ((uint4*)(dst + (size_t)atom * HIDDEN))[c] = o;
}

// ---------------- sorted-segment mean ---------------------------------------
__global__ void seg_reduce_kernel(const __half* __restrict__ ah)
{
    int m = blockIdx.x;
    int col = blockIdx.y * 128 + threadIdx.x;
    int s = __ldg(&g_segStart[m]);
    int e = __ldg(&g_segStart[m + 1]);
    float acc = 0.f;
    for (int r = s; r < e; r++)
        acc += __half2float(__ldg(&ah[(size_t)r * HIDDEN + col]));
    g_sums[(size_t)m * HIDDEN + col] = acc;
    float inv = 1.f / fmaxf((float)(e - s), 1.f);
    g_mvh[(size_t)m * HIDDEN + col] = __float2half(acc * inv);
    if (threadIdx.x == 0 && blockIdx.y == 0) g_cnt[m] = (float)(e - s);
}

// prod[p] = (sums[a]*inv_a)*(sums[b]*inv_b) (half out); also zero g_dot[p]
__global__ void prod_kernel(const int* __restrict__ edges)
{
    int p = blockIdx.x;
    int a = __ldg(&edges[p]);
    int b = __ldg(&edges[N_PAIRS + p]);
    float ia = 1.f / fmaxf(__ldg(&g_cnt[a]), 1.f);
    float ib = 1.f / fmaxf(__ldg(&g_cnt[b]), 1.f);
    int c = threadIdx.x;
    float4 va = __ldg((const float4*)(g_sums + (size_t)a * HIDDEN) + c);
    float4 vb = __ldg((const float4*)(g_sums + (size_t)b * HIDDEN) + c);
    va.x *= ia; va.y *= ia; va.z *= ia; va.w *= ia;
    vb.x *= ib; vb.y *= ib; vb.z *= ib; vb.w *= ib;
    __half2 h0 = __floats2half2_rn(va.x * vb.x, va.y * vb.y);
    __half2 h1 = __floats2half2_rn(va.z * vb.z, va.w * vb.w);
    uint2 o = make_uint2(*(uint32_t*)&h0, *(uint32_t*)&h1);
    ((uint2*)(g_prodh + (size_t)p * HIDDEN))[c] = o;
    if (c == 0) g_dot[p] = 0.f;
}

// out = sigmoid(dot + b_f2)
__global__ void sigmoid_kernel(const float* __restrict__ b2, float* __restrict__ out)
{
    int p = blockIdx.x * blockDim.x + threadIdx.x;
    if (p >= N_PAIRS) return;
    out[p] = 1.f / (1.f + expf(-(g_dot[p] + b2[0])));
}

// ---------------- launch ----------------------------------------------------
extern "C" void kernel_launch(void* const* d_in, const int* in_sizes, int n_in,
                              void* d_out, int out_size)
{
    const float* f_atoms = (const float*)d_in[0];
    const int*   a_nei   = (const int*)d_in[1];
    const int*   mol_ids = (const int*)d_in[2];
    const int*   edges   = (const int*)d_in[3];
    const float* W_i     = (const float*)d_in[4];
    const float* W_h     = (const float*)d_in[5];
    const float* W_o     = (const float*)d_in[6];
    const float* b_o     = (const float*)d_in[7];
    const float* W_fi    = (const float*)d_in[8];
    const float* b_fi    = (const float*)d_in[9];
    const float* W_f1    = (const float*)d_in[10];
    const float* b_f1    = (const float*)d_in[11];
    const float* W_f2    = (const float*)d_in[12];
    const float* b_f2    = (const float*)d_in[13];
    float* out = (float*)d_out;

    __half *padAh, *inph, *bufBh, *bufCh, *h1h, *prodh, *mvh, *Uh;
    __half *wiT, *woCatT, *whT, *wcombT, *wmT, *wf1T;
    float *dotp;
    cudaGetSymbolAddress((void**)&padAh,  g_padAh);
    cudaGetSymbolAddress((void**)&inph,   g_inph);
    cudaGetSymbolAddress((void**)&bufBh,  g_bufBh);
    cudaGetSymbolAddress((void**)&bufCh,  g_bufCh);
    cudaGetSymbolAddress((void**)&h1h,    g_h1h);
    cudaGetSymbolAddress((void**)&prodh,  g_prodh);
    cudaGetSymbolAddress((void**)&mvh,    g_mvh);
    cudaGetSymbolAddress((void**)&Uh,     g_Uh);
    cudaGetSymbolAddress((void**)&wiT,    g_WiTh);
    cudaGetSymbolAddress((void**)&woCatT, g_WoCatTh);
    cudaGetSymbolAddress((void**)&whT,    g_WhTh);
    cudaGetSymbolAddress((void**)&wcombT, g_WcombTh);
    cudaGetSymbolAddress((void**)&wmT,    g_WmTh);
    cudaGetSymbolAddress((void**)&wf1T,   g_Wf1Th);
    cudaGetSymbolAddress((void**)&dotp,   g_dot);

    cudaFuncSetAttribute(hgemm<MODE_N, false, false, false, false, true>,
                         cudaFuncAttributeMaxDynamicSharedMemorySize, SMEM_BYTES);
    cudaFuncSetAttribute(hgemm<MODE_N, true, true, true, false, true>,
                         cudaFuncAttributeMaxDynamicSharedMemorySize, SMEM_BYTES);
    cudaFuncSetAttribute(hgemm<MODE_N, true, false, false, true, true>,
                         cudaFuncAttributeMaxDynamicSharedMemorySize, SMEM_BYTES);
    cudaFuncSetAttribute(hgemm<MODE_PAIR, true, false, false, true, true>,
                         cudaFuncAttributeMaxDynamicSharedMemorySize, SMEM_BYTES);
    cudaFuncSetAttribute(hgemm<MODE_DOT, true, false, false, true, false>,
                         cudaFuncAttributeMaxDynamicSharedMemorySize, SMEM_BYTES);

    const int MT = (N_ATOMS + BM - 1) / BM;  // 782

    // 0. all prep in one launch
    mega_prep_kernel<<<PREP_BLOCKS, 256>>>(f_atoms, mol_ids, W_i, W_h, W_o, W_fi, W_f1);
    // 1. inp = padA @ W_i                                 -> inph [N,512] half
    hgemm<MODE_N, false, false, false, false, true><<<dim3(HIDDEN / BN, MT), 256, SMEM_BYTES>>>(
        N_ATOMS, HIDDEN, KPAD_F, KPAD_F, KPAD_F, KPAD_F, KPAD_F, 0, HIDDEN,
        padAh, padAh, wiT, nullptr, nullptr, inph, nullptr, nullptr);
    // 2. bufBh = sum_j relu(inp[nei])
    gather_sum_h_kernel<<<N_ATOMS, 64>>>(inph, HIDDEN, a_nei, bufBh, 1);
    // 3. msg2 = relu(inp + bufBh @ W_h)                   -> bufCh half
    hgemm<MODE_N, true, true, true, false, true><<<dim3(HIDDEN / BN, MT), 256, SMEM_BYTES>>>(
        N_ATOMS, HIDDEN, HIDDEN, HIDDEN, HIDDEN, HIDDEN, HIDDEN, HIDDEN, HIDDEN,
        bufBh, bufBh, whT, inph, nullptr, bufCh, nullptr, nullptr);
    // 4. bufBh = sum_j msg2[nei]
    gather_sum_h_kernel<<<N_ATOMS, 64>>>(bufCh, HIDDEN, a_nei, bufBh, 0);
    // 6. atom_hiddens = relu([padA | bufBh] @ WoCat + b_o) -> bufCh (split-K)
    hgemm<MODE_N, true, false, false, true, true><<<dim3(HIDDEN / BN, MT), 256, SMEM_BYTES>>>(
        N_ATOMS, HIDDEN, K_CAT, KPAD_F, KPAD_F, HIDDEN, K_CAT, 0, HIDDEN,
        padAh, bufBh, woCatT, nullptr, b_o, bufCh, nullptr, nullptr);
    // 7-8. sorted-segment mean (no atomics): sums, cnt, mvh
    seg_reduce_kernel<<<dim3(N_MOLS, HIDDEN / 128), 128>>>(bufCh);
    // 9a. U = mv @ [(Ws+W1) | (Ws+W2)]                    -> g_Uh [M,4096] half
    hgemm<MODE_N, false, false, false, false, true><<<dim3(4096 / BN, N_MOLS / BM), 256, SMEM_BYTES>>>(
        N_MOLS, 4096, HIDDEN, HIDDEN, HIDDEN, HIDDEN, HIDDEN, 0, 4096,
        mvh, mvh, wcombT, nullptr, nullptr, Uh, nullptr, nullptr);
    // 9b. prod[p] = mv[a]*mv[b] (+ zero dot)              -> prodh half
    prod_kernel<<<N_PAIRS, 128>>>(edges);
    // 10. fused: h1 = relu(prod @ Wm + U1[a] + U2[b] + b_fi) -> h1h half
    hgemm<MODE_PAIR, true, false, false, true, true><<<dim3(FFN1 / BN, N_PAIRS / BM), 256, SMEM_BYTES>>>(
        N_PAIRS, FFN1, HIDDEN, HIDDEN, HIDDEN, HIDDEN, HIDDEN, FFN1, FFN1,
        prodh, prodh, wmT, nullptr, b_fi, h1h, edges, Uh);
    // 11+12a. dot[p] += relu(h1 @ W_f1 + b_f1) . W_f2     (fused dot epilogue)
    hgemm<MODE_DOT, true, false, false, true, false><<<dim3(FFN2 / BN, N_PAIRS / BM), 256, SMEM_BYTES>>>(
        N_PAIRS, FFN2, FFN1, FFN1, FFN1, FFN1, FFN1, 0, FFN2,
        h1h, h1h, wf1T, nullptr, b_f1, dotp, nullptr, W_f2);
    // 12b. out = sigmoid(dot + b_f2)
    sigmoid_kernel<<<(N_PAIRS + 255) / 256, 256>>>(b_f2, out);
}